// round 1
// baseline (speedup 1.0000x reference)
#include <cuda_runtime.h>
#include <math.h>

// ---------------- problem constants ----------------
#define NHH   16
#define NOPE_ 128
#define ROPED 64
#define VD_   128
#define QLORA_ 1536
#define KVLORA_ 512
#define HDIM  2048
#define BB    2
#define SS    2048
#define QEXT  576              // KVLORA + ROPE
#define QHD   (NOPE_ + ROPED)  // 192

// ---------------- scratch (device globals; no allocation) ----------------
__device__ float g_ql   [(long)BB*SS*QLORA_];           // 4096x1536
__device__ float g_q    [(long)BB*SS*NHH*QHD];          // 4096x3072
__device__ float g_ckv  [(long)BB*SS*QEXT];             // 4096x576 (cols 512:576 roped in place)
__device__ float g_qext [(long)BB*NHH*SS*QEXT];         // per (b,h): [2048,576]
__device__ float g_scores[(long)BB*NHH*SS*SS];          // per (b,h): [2048,2048]
__device__ float g_out1 [(long)BB*NHH*SS*KVLORA_];      // per (b,h): [2048,512]
__device__ float g_out2 [(long)BB*SS*NHH*VD_];          // 4096x2048
__device__ float g_wabsT[(long)NHH*KVLORA_*NOPE_];      // per h: [512,128] = q_absorb^T

// ---------------- tiled GEMM: C = alpha * A @ op(B) ----------------
// A: [M,K] row-major (lda). bT=1: B is [N,K] (NT).  bT=0: B is [K,N] (NN).
// All of M,N multiples of 64; K (and causal K-limits) multiples of 16.
#define BM 64
#define BN 64
#define BKK 16

__global__ void gemm_kernel(const float* __restrict__ A, const float* __restrict__ B,
                            float* __restrict__ C,
                            int K, int lda, int ldb, int ldc,
                            long sAb, long sAh, long sBb, long sBh, long sCb, long sCh,
                            int zh, float alpha, int bT, int causalSkip, int causalK)
{
    int z = blockIdx.z;
    int bb = z / zh, hh = z % zh;
    A += bb * sAb + hh * sAh;
    B += bb * sBb + hh * sBh;
    C += bb * sCb + hh * sCh;

    int by = blockIdx.y, bx = blockIdx.x;
    if (causalSkip && bx * BN > by * BM + BM - 1) return;   // fully-masked tile
    int Klim = causalK ? min(K, by * BM + BM) : K;

    __shared__ float As[BKK][BM];
    __shared__ float Bs[BKK][BN];

    int tid = threadIdx.x;            // 256 threads
    int tx = tid & 15, ty = tid >> 4; // 16x16, each computes 4x4

    int lrow  = tid >> 2;             // 0..63
    int lcol4 = (tid & 3) << 2;       // 0,4,8,12
    const float* Aptr   = A + (long)(by * BM + lrow) * lda + lcol4;
    const float* BptrNT = B + (long)(bx * BN + lrow) * ldb + lcol4;
    int bk  = tid >> 4;               // 0..15 (NN path)
    int bn4 = (tid & 15) << 2;
    const float* BptrNN = B + (long)bk * ldb + bx * BN + bn4;

    float acc[4][4] = {};

    for (int k0 = 0; k0 < Klim; k0 += BKK) {
        float4 av = *(const float4*)(Aptr + k0);
        As[lcol4 + 0][lrow] = av.x;
        As[lcol4 + 1][lrow] = av.y;
        As[lcol4 + 2][lrow] = av.z;
        As[lcol4 + 3][lrow] = av.w;
        if (bT) {
            float4 bv = *(const float4*)(BptrNT + k0);
            Bs[lcol4 + 0][lrow] = bv.x;
            Bs[lcol4 + 1][lrow] = bv.y;
            Bs[lcol4 + 2][lrow] = bv.z;
            Bs[lcol4 + 3][lrow] = bv.w;
        } else {
            float4 bv = *(const float4*)(BptrNN + (long)k0 * ldb);
            *(float4*)&Bs[bk][bn4] = bv;
        }
        __syncthreads();
        #pragma unroll
        for (int kk = 0; kk < BKK; kk++) {
            float4 a4 = *(const float4*)&As[kk][ty << 2];
            float4 b4 = *(const float4*)&Bs[kk][tx << 2];
            float a[4] = {a4.x, a4.y, a4.z, a4.w};
            float b[4] = {b4.x, b4.y, b4.z, b4.w};
            #pragma unroll
            for (int i = 0; i < 4; i++)
                #pragma unroll
                for (int j = 0; j < 4; j++)
                    acc[i][j] = fmaf(a[i], b[j], acc[i][j]);
        }
        __syncthreads();
    }

    #pragma unroll
    for (int i = 0; i < 4; i++) {
        float* crow = C + (long)(by * BM + (ty << 2) + i) * ldc + bx * BN + (tx << 2);
        #pragma unroll
        for (int j = 0; j < 4; j++) crow[j] = alpha * acc[i][j];
    }
}

// ---------------- RMSNorm over last dim 1536 ----------------
__global__ void rmsnorm_kernel(float* __restrict__ ql, const float* __restrict__ w)
{
    float* row = ql + (long)blockIdx.x * QLORA_;
    int tid = threadIdx.x;
    float s = 0.f;
    for (int i = tid; i < QLORA_; i += 256) { float v = row[i]; s += v * v; }
    __shared__ float red[256];
    red[tid] = s; __syncthreads();
    for (int st = 128; st > 0; st >>= 1) { if (tid < st) red[tid] += red[tid + st]; __syncthreads(); }
    float scale = rsqrtf(red[0] / (float)QLORA_ + 1e-6f);
    for (int i = tid; i < QLORA_; i += 256) row[i] = w[i] * (row[i] * scale);
}

// ---------------- RoPE (stores the permuted-layout rope, matching reference) ----------------
__device__ __forceinline__ void rope_pair(float p, int i, float x0, float x1,
                                          float& o_lo, float& o_hi)
{
    double inv = exp(-((double)(2 * i) / 64.0) * 13.815510557964274); // ln(1e6)
    double ang = (double)p * inv;
    double sd, cd; sincos(ang, &sd, &cd);
    float c = (float)cd, s = (float)sd;
    o_lo = x0 * c - x1 * s;
    o_hi = x1 * c + x0 * s;
}

__global__ void rope_q_kernel(const float* __restrict__ q, const int* __restrict__ pos,
                              float* __restrict__ qext)
{
    int idx = blockIdx.x * blockDim.x + threadIdx.x;
    if (idx >= BB * SS * NHH) return;
    int h = idx % NHH;
    int bs = idx / NHH;
    int b = bs / SS, s_idx = bs % SS;
    float p = (float)pos[bs];
    const float* x = q + ((long)bs * NHH + h) * QHD + NOPE_;
    float* o = qext + ((long)(b * NHH + h) * SS + s_idx) * QEXT + KVLORA_;
    for (int i = 0; i < 32; i++) {
        float lo, hi;
        rope_pair(p, i, x[2 * i], x[2 * i + 1], lo, hi);
        o[i] = lo; o[32 + i] = hi;
    }
}

__global__ void rope_k_kernel(float* __restrict__ ckv, const int* __restrict__ pos)
{
    int bs = blockIdx.x * blockDim.x + threadIdx.x;
    if (bs >= BB * SS) return;
    float p = (float)pos[bs];
    float* x = ckv + (long)bs * QEXT + KVLORA_;
    float tmp[64];
    for (int i = 0; i < 32; i++)
        rope_pair(p, i, x[2 * i], x[2 * i + 1], tmp[i], tmp[32 + i]);
    for (int j = 0; j < 64; j++) x[j] = tmp[j];
}

// ---------------- transpose q_absorb: [h][n][c] -> [h][c][n] ----------------
__global__ void transpose_wabs_kernel(const float* __restrict__ Wkv_up, float* __restrict__ outT)
{
    int idx = blockIdx.x * blockDim.x + threadIdx.x;
    if (idx >= NHH * KVLORA_ * NOPE_) return;
    int n = idx % NOPE_;
    int r = idx / NOPE_;
    int c = r % KVLORA_;
    int h = r / KVLORA_;
    outT[idx] = Wkv_up[((long)h * 256 + n) * KVLORA_ + c];
}

// ---------------- causal row softmax (zeroes k>q so downstream GEMM is clean) ----------------
__global__ void softmax_kernel(float* __restrict__ scores)
{
    long row = blockIdx.x;           // (b*NH+h)*S + q
    int q = (int)(row % SS);
    float* r = scores + row * (long)SS;
    int tid = threadIdx.x;
    int n = q + 1;
    __shared__ float red[256];

    float mx = -1e30f;
    for (int k = tid; k < n; k += 256) mx = fmaxf(mx, r[k]);
    red[tid] = mx; __syncthreads();
    for (int st = 128; st > 0; st >>= 1) { if (tid < st) red[tid] = fmaxf(red[tid], red[tid + st]); __syncthreads(); }
    mx = red[0]; __syncthreads();

    float sum = 0.f;
    for (int k = tid; k < n; k += 256) { float e = __expf(r[k] - mx); r[k] = e; sum += e; }
    red[tid] = sum; __syncthreads();
    for (int st = 128; st > 0; st >>= 1) { if (tid < st) red[tid] += red[tid + st]; __syncthreads(); }
    float inv = 1.f / red[0];

    for (int k = tid; k < n; k += 256) r[k] *= inv;
    for (int k = n + tid; k < SS; k += 256) r[k] = 0.f;   // clean upper triangle
}

// ---------------- host side ----------------
static void launch_gemm(const float* A, const float* B, float* C,
                        int M, int N, int K, int lda, int ldb, int ldc,
                        long sAb, long sAh, long sBb, long sBh, long sCb, long sCh,
                        int zh, int zcount, float alpha, int bT, int cSkip, int cK)
{
    dim3 grid(N / BN, M / BM, zcount);
    gemm_kernel<<<grid, 256>>>(A, B, C, K, lda, ldb, ldc,
                               sAb, sAh, sBb, sBh, sCb, sCh, zh, alpha, bT, cSkip, cK);
}

extern "C" void kernel_launch(void* const* d_in, const int* in_sizes, int n_in,
                              void* d_out, int out_size)
{
    const float* hs      = (const float*)d_in[0];   // [2,2048,2048]
    const int*   pos     = (const int*)  d_in[1];   // [2,2048]
    /* d_in[2] = attention_mask (causal tril) — implied, unused */
    const float* Wq_down = (const float*)d_in[3];   // [1536,2048]
    const float* q_ln_w  = (const float*)d_in[4];   // [1536]
    const float* Wq_up   = (const float*)d_in[5];   // [3072,1536]
    const float* Wkv_down= (const float*)d_in[6];   // [576,2048]
    const float* Wkv_up  = (const float*)d_in[7];   // [4096,512]
    const float* Wo      = (const float*)d_in[8];   // [2048,2048]
    float* out = (float*)d_out;

    float *ql, *q, *ckv, *qext, *scores, *out1, *out2, *wabsT;
    cudaGetSymbolAddress((void**)&ql,     g_ql);
    cudaGetSymbolAddress((void**)&q,      g_q);
    cudaGetSymbolAddress((void**)&ckv,    g_ckv);
    cudaGetSymbolAddress((void**)&qext,   g_qext);
    cudaGetSymbolAddress((void**)&scores, g_scores);
    cudaGetSymbolAddress((void**)&out1,   g_out1);
    cudaGetSymbolAddress((void**)&out2,   g_out2);
    cudaGetSymbolAddress((void**)&wabsT,  g_wabsT);

    const int M = BB * SS;                 // 4096
    const float scale = 1.0f / sqrtf((float)QHD);

    // 1. ql = hs @ Wq_down^T                [4096,1536]
    launch_gemm(hs, Wq_down, ql, M, QLORA_, HDIM, HDIM, HDIM, QLORA_,
                0,0,0,0,0,0, 1, 1, 1.f, 1, 0, 0);
    // 2. RMSNorm(ql) * q_ln_w
    rmsnorm_kernel<<<M, 256>>>(ql, q_ln_w);
    // 3. q = ql @ Wq_up^T                   [4096,3072]
    launch_gemm(ql, Wq_up, q, M, NHH * QHD, QLORA_, QLORA_, QLORA_, NHH * QHD,
                0,0,0,0,0,0, 1, 1, 1.f, 1, 0, 0);
    // 4. ckv = hs @ Wkv_down^T              [4096,576]
    launch_gemm(hs, Wkv_down, ckv, M, QEXT, HDIM, HDIM, HDIM, QEXT,
                0,0,0,0,0,0, 1, 1, 1.f, 1, 0, 0);
    // 5. q_absorb^T per head
    transpose_wabs_kernel<<<(NHH * KVLORA_ * NOPE_ + 255) / 256, 256>>>(Wkv_up, wabsT);
    // 6. RoPE k (in place on ckv cols 512:576)
    rope_k_kernel<<<(BB * SS + 255) / 256, 256>>>(ckv, pos);
    // 7. RoPE q -> qext cols 512:576
    rope_q_kernel<<<(BB * SS * NHH + 255) / 256, 256>>>(q, pos, qext);
    // 8. qext[:,0:512] = q_nope @ q_absorb   (batched over b,h)
    launch_gemm(q, wabsT, qext, SS, KVLORA_, NOPE_,
                NHH * QHD, NOPE_, QEXT,
                (long)SS * NHH * QHD, (long)QHD,            // A offsets: b, h (h*192 into row)
                0, (long)KVLORA_ * NOPE_,                   // B offsets
                (long)NHH * SS * QEXT, (long)SS * QEXT,     // C offsets
                NHH, BB * NHH, 1.f, 1, 0, 0);
    // 9. scores = scale * qext @ ckv^T       (batched, causal block-skip)
    launch_gemm(qext, ckv, scores, SS, SS, QEXT,
                QEXT, QEXT, SS,
                (long)NHH * SS * QEXT, (long)SS * QEXT,
                (long)SS * QEXT, 0,
                (long)NHH * SS * SS, (long)SS * SS,
                NHH, BB * NHH, scale, 1, 1, 0);
    // 10. softmax (causal, zero upper triangle)
    softmax_kernel<<<BB * NHH * SS, 256>>>(scores);
    // 11. out1 = attn @ compressed_kv        (batched, causal K-limit, NN)
    launch_gemm(scores, ckv, out1, SS, KVLORA_, SS,
                SS, QEXT, KVLORA_,
                (long)NHH * SS * SS, (long)SS * SS,
                (long)SS * QEXT, 0,
                (long)NHH * SS * KVLORA_, (long)SS * KVLORA_,
                NHH, BB * NHH, 1.f, 0, 0, 1);
    // 12. out2 = out1 @ out_absorb^T         (batched)
    launch_gemm(out1, Wkv_up + (long)NOPE_ * KVLORA_, out2, SS, VD_, KVLORA_,
                KVLORA_, KVLORA_, NHH * VD_,
                (long)NHH * SS * KVLORA_, (long)SS * KVLORA_,
                0, (long)256 * KVLORA_,
                (long)SS * NHH * VD_, (long)VD_,
                NHH, BB * NHH, 1.f, 1, 0, 0);
    // 13. final = out2 @ Wo^T                [4096,2048]
    launch_gemm(out2, Wo, out, M, HDIM, NHH * VD_, NHH * VD_, NHH * VD_, HDIM,
                0,0,0,0,0,0, 1, 1, 1.f, 1, 0, 0);
}

// round 2
// speedup vs baseline: 1.4523x; 1.4523x over previous
#include <cuda_runtime.h>
#include <math.h>

// ---------------- problem constants ----------------
#define NHH   16
#define NOPE_ 128
#define ROPED 64
#define VD_   128
#define QLORA_ 1536
#define KVLORA_ 512
#define HDIM  2048
#define BB    2
#define SS    2048
#define QEXT  576              // KVLORA + ROPE
#define QHD   (NOPE_ + ROPED)  // 192

// ---------------- scratch (device globals; no allocation) ----------------
__device__ float g_ql   [(long)BB*SS*QLORA_];
__device__ float g_q    [(long)BB*SS*NHH*QHD];
__device__ float g_ckv  [(long)BB*SS*QEXT];
__device__ float g_qext [(long)BB*NHH*SS*QEXT];
__device__ float g_scores[(long)BB*NHH*SS*SS];
__device__ float g_out1 [(long)BB*NHH*SS*KVLORA_];
__device__ float g_out2 [(long)BB*SS*NHH*VD_];
__device__ float g_wabsT[(long)NHH*KVLORA_*NOPE_];

// ---------------- 128xBN SIMT GEMM, double-buffered, 8xTN per thread -------
// C = alpha * A @ op(B).  A:[M,K] row-major.  bT=1: B [N,K] (NT); bT=0: B [K,N].
// BM=128, BK=8 fixed. 256 threads. M % 128 == 0, N % BN == 0, K % 8 == 0.
template<int BN, int TN>
__global__ void __launch_bounds__(256, 2)
gemm_kernel(const float* __restrict__ A, const float* __restrict__ B,
            float* __restrict__ C,
            int K, int lda, int ldb, int ldc,
            long sAb, long sAh, long sBb, long sBh, long sCb, long sCh,
            int zh, float alpha, int bT, int causalSkip, int causalK)
{
    constexpr int BM = 128, BK = 8;
    int z = blockIdx.z;
    A += (long)(z / zh) * sAb + (long)(z % zh) * sAh;
    B += (long)(z / zh) * sBb + (long)(z % zh) * sBh;
    C += (long)(z / zh) * sCb + (long)(z % zh) * sCh;

    int by = blockIdx.y, bx = blockIdx.x;
    if (causalSkip && bx * BN > by * BM + (BM - 1)) return;   // fully masked
    int Klim = causalK ? min(K, by * BM + BM) : K;

    __shared__ float As[2][BK][BM + 4];
    __shared__ float Bs[2][BK][BN + 4];

    int tid = threadIdx.x;
    int tx = tid & 15, ty = tid >> 4;

    // A tile loader: 128x8 floats = 256 float4, 1 per thread
    int arow = tid >> 1;
    int acol = (tid & 1) << 2;
    const float* Aptr = A + (long)(by * BM + arow) * lda + acol;

    // B tile loader: BN*8 floats = BN*2 float4
    constexpr int NB4 = BN * 2;
    int brow = tid >> 1;
    int bcol = (tid & 1) << 2;
    const float* BptrNT = B + (long)(bx * BN + brow) * ldb + bcol;
    int bkr = tid / (BN / 4);
    int bn4 = (tid % (BN / 4)) << 2;
    const float* BptrNN = B + (long)bkr * ldb + bx * BN + bn4;

    float acc[8][TN];
    #pragma unroll
    for (int i = 0; i < 8; i++)
        #pragma unroll
        for (int j = 0; j < TN; j++) acc[i][j] = 0.f;

    // prologue: load k0 = 0 into buffer 0
    float4 aReg = *(const float4*)Aptr;
    float4 bReg = make_float4(0.f, 0.f, 0.f, 0.f);
    if (tid < NB4)
        bReg = bT ? *(const float4*)BptrNT : *(const float4*)BptrNN;

    As[0][acol + 0][arow] = aReg.x;
    As[0][acol + 1][arow] = aReg.y;
    As[0][acol + 2][arow] = aReg.z;
    As[0][acol + 3][arow] = aReg.w;
    if (tid < NB4) {
        if (bT) {
            Bs[0][bcol + 0][brow] = bReg.x;
            Bs[0][bcol + 1][brow] = bReg.y;
            Bs[0][bcol + 2][brow] = bReg.z;
            Bs[0][bcol + 3][brow] = bReg.w;
        } else {
            *(float4*)&Bs[0][bkr][bn4] = bReg;
        }
    }
    __syncthreads();

    int p = 0;
    for (int k0 = BK; k0 < Klim; k0 += BK) {
        // prefetch next K-tile into registers
        aReg = *(const float4*)(Aptr + k0);
        if (tid < NB4)
            bReg = bT ? *(const float4*)(BptrNT + k0)
                      : *(const float4*)(BptrNN + (long)k0 * ldb);

        // compute on buffer p
        #pragma unroll
        for (int kk = 0; kk < BK; kk++) {
            float a[8], b[TN];
            *(float4*)&a[0] = *(const float4*)&As[p][kk][(ty << 2)];
            *(float4*)&a[4] = *(const float4*)&As[p][kk][64 + (ty << 2)];
            *(float4*)&b[0] = *(const float4*)&Bs[p][kk][(tx << 2)];
            if (TN == 8)
                *(float4*)&b[4] = *(const float4*)&Bs[p][kk][BN / 2 + (tx << 2)];
            #pragma unroll
            for (int i = 0; i < 8; i++)
                #pragma unroll
                for (int j = 0; j < TN; j++)
                    acc[i][j] = fmaf(a[i], b[j], acc[i][j]);
        }

        // stage prefetched data into the other buffer
        int q = p ^ 1;
        As[q][acol + 0][arow] = aReg.x;
        As[q][acol + 1][arow] = aReg.y;
        As[q][acol + 2][arow] = aReg.z;
        As[q][acol + 3][arow] = aReg.w;
        if (tid < NB4) {
            if (bT) {
                Bs[q][bcol + 0][brow] = bReg.x;
                Bs[q][bcol + 1][brow] = bReg.y;
                Bs[q][bcol + 2][brow] = bReg.z;
                Bs[q][bcol + 3][brow] = bReg.w;
            } else {
                *(float4*)&Bs[q][bkr][bn4] = bReg;
            }
        }
        __syncthreads();
        p = q;
    }

    // final K-tile compute
    #pragma unroll
    for (int kk = 0; kk < BK; kk++) {
        float a[8], b[TN];
        *(float4*)&a[0] = *(const float4*)&As[p][kk][(ty << 2)];
        *(float4*)&a[4] = *(const float4*)&As[p][kk][64 + (ty << 2)];
        *(float4*)&b[0] = *(const float4*)&Bs[p][kk][(tx << 2)];
        if (TN == 8)
            *(float4*)&b[4] = *(const float4*)&Bs[p][kk][BN / 2 + (tx << 2)];
        #pragma unroll
        for (int i = 0; i < 8; i++)
            #pragma unroll
            for (int j = 0; j < TN; j++)
                acc[i][j] = fmaf(a[i], b[j], acc[i][j]);
    }

    // epilogue: float4 stores
    #pragma unroll
    for (int half = 0; half < 2; half++) {
        #pragma unroll
        for (int i = 0; i < 4; i++) {
            int row = by * BM + half * 64 + (ty << 2) + i;
            float* cp = C + (long)row * ldc + bx * BN + (tx << 2);
            float4 v;
            v.x = alpha * acc[half * 4 + i][0];
            v.y = alpha * acc[half * 4 + i][1];
            v.z = alpha * acc[half * 4 + i][2];
            v.w = alpha * acc[half * 4 + i][3];
            *(float4*)cp = v;
            if (TN == 8) {
                float4 w;
                w.x = alpha * acc[half * 4 + i][4];
                w.y = alpha * acc[half * 4 + i][5];
                w.z = alpha * acc[half * 4 + i][6];
                w.w = alpha * acc[half * 4 + i][7];
                *(float4*)(cp + BN / 2) = w;
            }
        }
    }
}

// ---------------- RMSNorm over last dim 1536 ----------------
__global__ void rmsnorm_kernel(float* __restrict__ ql, const float* __restrict__ w)
{
    float* row = ql + (long)blockIdx.x * QLORA_;
    int tid = threadIdx.x;
    float s = 0.f;
    for (int i = tid; i < QLORA_; i += 256) { float v = row[i]; s += v * v; }
    __shared__ float red[256];
    red[tid] = s; __syncthreads();
    for (int st = 128; st > 0; st >>= 1) { if (tid < st) red[tid] += red[tid + st]; __syncthreads(); }
    float scale = rsqrtf(red[0] / (float)QLORA_ + 1e-6f);
    for (int i = tid; i < QLORA_; i += 256) row[i] = w[i] * (row[i] * scale);
}

// ---------------- RoPE ----------------
__device__ __forceinline__ void rope_pair(float p, int i, float x0, float x1,
                                          float& o_lo, float& o_hi)
{
    double inv = exp(-((double)(2 * i) / 64.0) * 13.815510557964274); // ln(1e6)
    double ang = (double)p * inv;
    double sd, cd; sincos(ang, &sd, &cd);
    float c = (float)cd, s = (float)sd;
    o_lo = x0 * c - x1 * s;
    o_hi = x1 * c + x0 * s;
}

__global__ void rope_q_kernel(const float* __restrict__ q, const int* __restrict__ pos,
                              float* __restrict__ qext)
{
    int idx = blockIdx.x * blockDim.x + threadIdx.x;
    if (idx >= BB * SS * NHH) return;
    int h = idx % NHH;
    int bs = idx / NHH;
    int b = bs / SS, s_idx = bs % SS;
    float p = (float)pos[bs];
    const float* x = q + ((long)bs * NHH + h) * QHD + NOPE_;
    float* o = qext + ((long)(b * NHH + h) * SS + s_idx) * QEXT + KVLORA_;
    for (int i = 0; i < 32; i++) {
        float lo, hi;
        rope_pair(p, i, x[2 * i], x[2 * i + 1], lo, hi);
        o[i] = lo; o[32 + i] = hi;
    }
}

__global__ void rope_k_kernel(float* __restrict__ ckv, const int* __restrict__ pos)
{
    int bs = blockIdx.x * blockDim.x + threadIdx.x;
    if (bs >= BB * SS) return;
    float p = (float)pos[bs];
    float* x = ckv + (long)bs * QEXT + KVLORA_;
    float tmp[64];
    for (int i = 0; i < 32; i++)
        rope_pair(p, i, x[2 * i], x[2 * i + 1], tmp[i], tmp[32 + i]);
    for (int j = 0; j < 64; j++) x[j] = tmp[j];
}

// ---------------- transpose q_absorb: [h][n][c] -> [h][c][n] ----------------
__global__ void transpose_wabs_kernel(const float* __restrict__ Wkv_up, float* __restrict__ outT)
{
    int idx = blockIdx.x * blockDim.x + threadIdx.x;
    if (idx >= NHH * KVLORA_ * NOPE_) return;
    int n = idx % NOPE_;
    int r = idx / NOPE_;
    int c = r % KVLORA_;
    int h = r / KVLORA_;
    outT[idx] = Wkv_up[((long)h * 256 + n) * KVLORA_ + c];
}

// ---------------- causal row softmax ----------------
__global__ void softmax_kernel(float* __restrict__ scores)
{
    long row = blockIdx.x;
    int q = (int)(row % SS);
    float* r = scores + row * (long)SS;
    int tid = threadIdx.x;
    int n = q + 1;
    __shared__ float red[256];

    float mx = -1e30f;
    for (int k = tid; k < n; k += 256) mx = fmaxf(mx, r[k]);
    red[tid] = mx; __syncthreads();
    for (int st = 128; st > 0; st >>= 1) { if (tid < st) red[tid] = fmaxf(red[tid], red[tid + st]); __syncthreads(); }
    mx = red[0]; __syncthreads();

    float sum = 0.f;
    for (int k = tid; k < n; k += 256) { float e = __expf(r[k] - mx); r[k] = e; sum += e; }
    red[tid] = sum; __syncthreads();
    for (int st = 128; st > 0; st >>= 1) { if (tid < st) red[tid] += red[tid + st]; __syncthreads(); }
    float inv = 1.f / red[0];

    for (int k = tid; k < n; k += 256) r[k] *= inv;
    for (int k = n + tid; k < SS; k += 256) r[k] = 0.f;
}

// ---------------- host side ----------------
static void launch_gemm128(const float* A, const float* B, float* C,
                           int M, int N, int K, int lda, int ldb, int ldc,
                           long sAb, long sAh, long sBb, long sBh, long sCb, long sCh,
                           int zh, int zcount, float alpha, int bT, int cSkip, int cK)
{
    dim3 grid(N / 128, M / 128, zcount);
    gemm_kernel<128, 8><<<grid, 256>>>(A, B, C, K, lda, ldb, ldc,
                                       sAb, sAh, sBb, sBh, sCb, sCh,
                                       zh, alpha, bT, cSkip, cK);
}

static void launch_gemm64(const float* A, const float* B, float* C,
                          int M, int N, int K, int lda, int ldb, int ldc,
                          float alpha, int bT)
{
    dim3 grid(N / 64, M / 128, 1);
    gemm_kernel<64, 4><<<grid, 256>>>(A, B, C, K, lda, ldb, ldc,
                                      0, 0, 0, 0, 0, 0, 1, alpha, bT, 0, 0);
}

extern "C" void kernel_launch(void* const* d_in, const int* in_sizes, int n_in,
                              void* d_out, int out_size)
{
    const float* hs      = (const float*)d_in[0];
    const int*   pos     = (const int*)  d_in[1];
    const float* Wq_down = (const float*)d_in[3];
    const float* q_ln_w  = (const float*)d_in[4];
    const float* Wq_up   = (const float*)d_in[5];
    const float* Wkv_down= (const float*)d_in[6];
    const float* Wkv_up  = (const float*)d_in[7];
    const float* Wo      = (const float*)d_in[8];
    float* out = (float*)d_out;

    float *ql, *q, *ckv, *qext, *scores, *out1, *out2, *wabsT;
    cudaGetSymbolAddress((void**)&ql,     g_ql);
    cudaGetSymbolAddress((void**)&q,      g_q);
    cudaGetSymbolAddress((void**)&ckv,    g_ckv);
    cudaGetSymbolAddress((void**)&qext,   g_qext);
    cudaGetSymbolAddress((void**)&scores, g_scores);
    cudaGetSymbolAddress((void**)&out1,   g_out1);
    cudaGetSymbolAddress((void**)&out2,   g_out2);
    cudaGetSymbolAddress((void**)&wabsT,  g_wabsT);

    const int M = BB * SS;
    const float scale = 1.0f / sqrtf((float)QHD);

    // 1. ql = hs @ Wq_down^T                [4096,1536]
    launch_gemm128(hs, Wq_down, ql, M, QLORA_, HDIM, HDIM, HDIM, QLORA_,
                   0,0,0,0,0,0, 1, 1, 1.f, 1, 0, 0);
    // 2. RMSNorm(ql) * q_ln_w
    rmsnorm_kernel<<<M, 256>>>(ql, q_ln_w);
    // 3. q = ql @ Wq_up^T                   [4096,3072]
    launch_gemm128(ql, Wq_up, q, M, NHH * QHD, QLORA_, QLORA_, QLORA_, NHH * QHD,
                   0,0,0,0,0,0, 1, 1, 1.f, 1, 0, 0);
    // 4. ckv = hs @ Wkv_down^T              [4096,576]  (N=576 -> BN=64 path)
    launch_gemm64(hs, Wkv_down, ckv, M, QEXT, HDIM, HDIM, HDIM, QEXT, 1.f, 1);
    // 5. q_absorb^T per head
    transpose_wabs_kernel<<<(NHH * KVLORA_ * NOPE_ + 255) / 256, 256>>>(Wkv_up, wabsT);
    // 6. RoPE k (in place on ckv cols 512:576)
    rope_k_kernel<<<(BB * SS + 255) / 256, 256>>>(ckv, pos);
    // 7. RoPE q -> qext cols 512:576
    rope_q_kernel<<<(BB * SS * NHH + 255) / 256, 256>>>(q, pos, qext);
    // 8. qext[:,0:512] = q_nope @ q_absorb   (batched over b,h)
    launch_gemm128(q, wabsT, qext, SS, KVLORA_, NOPE_,
                   NHH * QHD, NOPE_, QEXT,
                   (long)SS * NHH * QHD, (long)QHD,
                   0, (long)KVLORA_ * NOPE_,
                   (long)NHH * SS * QEXT, (long)SS * QEXT,
                   NHH, BB * NHH, 1.f, 1, 0, 0);
    // 9. scores = scale * qext @ ckv^T       (batched, causal block-skip)
    launch_gemm128(qext, ckv, scores, SS, SS, QEXT,
                   QEXT, QEXT, SS,
                   (long)NHH * SS * QEXT, (long)SS * QEXT,
                   (long)SS * QEXT, 0,
                   (long)NHH * SS * SS, (long)SS * SS,
                   NHH, BB * NHH, scale, 1, 1, 0);
    // 10. softmax (causal, zero upper triangle)
    softmax_kernel<<<BB * NHH * SS, 256>>>(scores);
    // 11. out1 = attn @ compressed_kv        (batched, causal K-limit, NN)
    launch_gemm128(scores, ckv, out1, SS, KVLORA_, SS,
                   SS, QEXT, KVLORA_,
                   (long)NHH * SS * SS, (long)SS * SS,
                   (long)SS * QEXT, 0,
                   (long)NHH * SS * KVLORA_, (long)SS * KVLORA_,
                   NHH, BB * NHH, 1.f, 0, 0, 1);
    // 12. out2 = out1 @ out_absorb^T         (batched)
    launch_gemm128(out1, Wkv_up + (long)NOPE_ * KVLORA_, out2, SS, VD_, KVLORA_,
                   KVLORA_, KVLORA_, NHH * VD_,
                   (long)NHH * SS * KVLORA_, (long)SS * KVLORA_,
                   0, (long)256 * KVLORA_,
                   (long)SS * NHH * VD_, (long)VD_,
                   NHH, BB * NHH, 1.f, 1, 0, 0);
    // 13. final = out2 @ Wo^T                [4096,2048]
    launch_gemm128(out2, Wo, out, M, HDIM, NHH * VD_, NHH * VD_, NHH * VD_, HDIM,
                   0,0,0,0,0,0, 1, 1, 1.f, 1, 0, 0);
}

// round 4
// speedup vs baseline: 1.9895x; 1.3700x over previous
#include <cuda_runtime.h>
#include <cuda_bf16.h>
#include <math.h>
#include <stdint.h>

// ---------------- problem constants ----------------
#define NHH   16
#define NOPE_ 128
#define ROPED 64
#define VD_   128
#define QLORA_ 1536
#define KVLORA_ 512
#define HDIM  2048
#define BB    2
#define SS    2048
#define QEXT  576
#define QHD   (NOPE_ + ROPED)  // 192

// ---------------- scratch ----------------
__device__ float g_ql   [(long)BB*SS*QLORA_];
__device__ float g_q    [(long)BB*SS*NHH*QHD];
__device__ float g_ckv  [(long)BB*SS*QEXT];
__device__ float g_ckvT [(long)BB*KVLORA_*SS];
__device__ float g_qext [(long)BB*NHH*SS*QEXT];
__device__ float g_scores[(long)BB*NHH*SS*SS];
__device__ float g_out1 [(long)BB*NHH*SS*KVLORA_];
__device__ float g_out2 [(long)BB*SS*NHH*VD_];
__device__ float g_wabsT[(long)NHH*KVLORA_*NOPE_];

// ================= warp-MMA (bf16 HMMA) GEMM =================
// C = alpha * A @ B^T   (A:[M,K], B:[N,K], row-major fp32)
// 3-term bf16 split: C ~= Ah Bh + Ah Bl + Al Bh  (fp32 accum)
// Block 128x128, BK=32. 256 threads = 8 warps (2 M x 4 N), warp tile 64x32.
// M%128==0, N%128==0, K%32==0 (causal Klim stays %32).

#define ROWB 80            // bytes per smem row: 32 bf16 data + 8 pad
#define TILEB (128 * ROWB) // 10240 bytes per tile
#define BUFB  (4 * TILEB)  // Ah, Al, Bh, Bl
#define MSMEM (2 * BUFB)   // 81920

extern __shared__ char dsmem[];

__device__ __forceinline__ uint32_t smem_u32(const void* p) {
    uint32_t a;
    asm("{ .reg .u64 t; cvta.to.shared.u64 t, %1; cvt.u32.u64 %0, t; }" : "=r"(a) : "l"(p));
    return a;
}
__device__ __forceinline__ void ldmx4(uint32_t* r, uint32_t addr) {
    asm volatile("ldmatrix.sync.aligned.m8n8.x4.shared.b16 {%0,%1,%2,%3}, [%4];"
                 : "=r"(r[0]), "=r"(r[1]), "=r"(r[2]), "=r"(r[3]) : "r"(addr));
}
__device__ __forceinline__ void mma16816(float* d, const uint32_t* a, const uint32_t* b) {
    asm volatile("mma.sync.aligned.m16n8k16.row.col.f32.bf16.bf16.f32 "
                 "{%0,%1,%2,%3}, {%4,%5,%6,%7}, {%8,%9}, {%0,%1,%2,%3};"
                 : "+f"(d[0]), "+f"(d[1]), "+f"(d[2]), "+f"(d[3])
                 : "r"(a[0]), "r"(a[1]), "r"(a[2]), "r"(a[3]), "r"(b[0]), "r"(b[1]));
}

__device__ __forceinline__ void conv_store(char* bufHi, char* bufLo, const float4* rv, int tid)
{
    #pragma unroll
    for (int i = 0; i < 4; i++) {
        int idx = (i << 8) + tid;        // 0..1023
        int r = idx >> 3;                // row 0..127
        int c4 = (idx & 7) << 2;         // col 0,4,..,28
        float4 v = rv[i];
        __nv_bfloat16 h0 = __float2bfloat16(v.x);
        __nv_bfloat16 h1 = __float2bfloat16(v.y);
        __nv_bfloat16 h2 = __float2bfloat16(v.z);
        __nv_bfloat16 h3 = __float2bfloat16(v.w);
        __nv_bfloat16 l0 = __float2bfloat16(v.x - __bfloat162float(h0));
        __nv_bfloat16 l1 = __float2bfloat16(v.y - __bfloat162float(h1));
        __nv_bfloat16 l2 = __float2bfloat16(v.z - __bfloat162float(h2));
        __nv_bfloat16 l3 = __float2bfloat16(v.w - __bfloat162float(h3));
        int off = r * ROWB + (c4 << 1);
        uint2 hv, lv;
        hv.x = (uint32_t)__bfloat16_as_ushort(h0) | ((uint32_t)__bfloat16_as_ushort(h1) << 16);
        hv.y = (uint32_t)__bfloat16_as_ushort(h2) | ((uint32_t)__bfloat16_as_ushort(h3) << 16);
        lv.x = (uint32_t)__bfloat16_as_ushort(l0) | ((uint32_t)__bfloat16_as_ushort(l1) << 16);
        lv.y = (uint32_t)__bfloat16_as_ushort(l2) | ((uint32_t)__bfloat16_as_ushort(l3) << 16);
        *(uint2*)(bufHi + off) = hv;
        *(uint2*)(bufLo + off) = lv;
    }
}

__global__ void __launch_bounds__(256)
mma_gemm(const float* __restrict__ A, const float* __restrict__ B, float* __restrict__ C,
         int K, int lda, int ldb, int ldc,
         long sAb, long sAh, long sBb, long sBh, long sCb, long sCh,
         int zh, float alpha, int causalSkip, int causalK)
{
    int z = blockIdx.z;
    A += (long)(z / zh) * sAb + (long)(z % zh) * sAh;
    B += (long)(z / zh) * sBb + (long)(z % zh) * sBh;
    C += (long)(z / zh) * sCb + (long)(z % zh) * sCh;
    int by = blockIdx.y, bx = blockIdx.x;
    if (causalSkip && bx * 128 > by * 128 + 127) return;
    int Klim = causalK ? min(K, by * 128 + 128) : K;
    int nCh = Klim >> 5;                 // 32-K chunks

    int tid = threadIdx.x;
    int lane = tid & 31, wid = tid >> 5;
    int wm = wid & 1, wn = wid >> 1;     // warp grid 2 x 4

    uint32_t sb = smem_u32(dsmem);

    // ldmatrix lane offsets (relative to tile base)
    uint32_t aoff[4][2], boff[2][2];
    {
        int ar = wm * 64 + (lane & 15);
        int ak = (lane >> 4) << 3;
        #pragma unroll
        for (int mt = 0; mt < 4; mt++)
            #pragma unroll
            for (int kh = 0; kh < 2; kh++)
                aoff[mt][kh] = (uint32_t)((ar + mt * 16) * ROWB + ((ak + kh * 16) << 1));
        int br = wn * 32 + (lane & 7) + ((lane & 16) ? 8 : 0);
        int bk = (lane & 8) ? 8 : 0;
        #pragma unroll
        for (int np = 0; np < 2; np++)
            #pragma unroll
            for (int kh = 0; kh < 2; kh++)
                boff[np][kh] = (uint32_t)((br + np * 16) * ROWB + ((bk + kh * 16) << 1));
    }

    // global pointers for this thread's loader lanes
    int lrow = tid >> 3;                 // 0..31 -> but 1024 chunks: idx>>3 gives 0..127 w/ i
    int lc4  = (tid & 7) << 2;
    const float* Abase = A + (long)(by * 128) * lda;
    const float* Bbase = B + (long)(bx * 128) * ldb;

    float acc[4][4][4];
    #pragma unroll
    for (int mt = 0; mt < 4; mt++)
        #pragma unroll
        for (int nt = 0; nt < 4; nt++)
            #pragma unroll
            for (int r = 0; r < 4; r++) acc[mt][nt][r] = 0.f;

    float4 ra[4], rb[4];
    // load chunk 0
    #pragma unroll
    for (int i = 0; i < 4; i++) {
        int r = ((i << 8) + tid) >> 3;
        ra[i] = *(const float4*)(Abase + (long)r * lda + lc4);
        rb[i] = *(const float4*)(Bbase + (long)r * ldb + lc4);
    }
    conv_store(dsmem,             dsmem + TILEB,     ra, tid);
    conv_store(dsmem + 2 * TILEB, dsmem + 3 * TILEB, rb, tid);
    __syncthreads();

    for (int c = 0; c < nCh; c++) {
        int koff = (c + 1) << 5;
        if (c + 1 < nCh) {
            #pragma unroll
            for (int i = 0; i < 4; i++) {
                int r = ((i << 8) + tid) >> 3;
                ra[i] = *(const float4*)(Abase + (long)r * lda + koff + lc4);
                rb[i] = *(const float4*)(Bbase + (long)r * ldb + koff + lc4);
            }
        }

        uint32_t bufb = sb + (uint32_t)((c & 1) * BUFB);
        uint32_t sAh_ = bufb, sAl_ = bufb + TILEB, sBh_ = bufb + 2 * TILEB, sBl_ = bufb + 3 * TILEB;

        #pragma unroll
        for (int kh = 0; kh < 2; kh++) {
            uint32_t ah[4][4], al[4][4], bh[2][4], bl[2][4];
            #pragma unroll
            for (int mt = 0; mt < 4; mt++) {
                ldmx4(ah[mt], sAh_ + aoff[mt][kh]);
                ldmx4(al[mt], sAl_ + aoff[mt][kh]);
            }
            #pragma unroll
            for (int np = 0; np < 2; np++) {
                ldmx4(bh[np], sBh_ + boff[np][kh]);
                ldmx4(bl[np], sBl_ + boff[np][kh]);
            }
            #pragma unroll
            for (int mt = 0; mt < 4; mt++) {
                #pragma unroll
                for (int nt = 0; nt < 4; nt++) {
                    const uint32_t* bhp = &bh[nt >> 1][(nt & 1) << 1];
                    const uint32_t* blp = &bl[nt >> 1][(nt & 1) << 1];
                    mma16816(acc[mt][nt], ah[mt], bhp);
                    mma16816(acc[mt][nt], ah[mt], blp);
                    mma16816(acc[mt][nt], al[mt], bhp);
                }
            }
        }

        if (c + 1 < nCh) {
            char* nb = dsmem + ((c + 1) & 1) * BUFB;
            conv_store(nb,             nb + TILEB,     ra, tid);
            conv_store(nb + 2 * TILEB, nb + 3 * TILEB, rb, tid);
        }
        __syncthreads();
    }

    // epilogue
    #pragma unroll
    for (int mt = 0; mt < 4; mt++) {
        int r0 = by * 128 + wm * 64 + mt * 16 + (lane >> 2);
        #pragma unroll
        for (int nt = 0; nt < 4; nt++) {
            int c0 = bx * 128 + wn * 32 + nt * 8 + ((lane & 3) << 1);
            float2 v0, v1;
            v0.x = alpha * acc[mt][nt][0];
            v0.y = alpha * acc[mt][nt][1];
            v1.x = alpha * acc[mt][nt][2];
            v1.y = alpha * acc[mt][nt][3];
            *(float2*)(C + (long)r0 * ldc + c0) = v0;
            *(float2*)(C + (long)(r0 + 8) * ldc + c0) = v1;
        }
    }
}

// ---------------- SIMT GEMM (N=576 ckv-down) ----------------
template<int BN, int TN>
__global__ void __launch_bounds__(256, 2)
gemm_kernel(const float* __restrict__ A, const float* __restrict__ B,
            float* __restrict__ C, int K, int lda, int ldb, int ldc, float alpha)
{
    constexpr int BM = 128, BK = 8;
    int by = blockIdx.y, bx = blockIdx.x;

    __shared__ float As[2][BK][BM + 4];
    __shared__ float Bs[2][BK][BN + 4];

    int tid = threadIdx.x;
    int tx = tid & 15, ty = tid >> 4;
    int arow = tid >> 1, acol = (tid & 1) << 2;
    const float* Aptr = A + (long)(by * BM + arow) * lda + acol;
    constexpr int NB4 = BN * 2;
    int brow = tid >> 1, bcol = (tid & 1) << 2;
    const float* BptrNT = B + (long)(bx * BN + brow) * ldb + bcol;

    float acc[8][TN];
    #pragma unroll
    for (int i = 0; i < 8; i++)
        #pragma unroll
        for (int j = 0; j < TN; j++) acc[i][j] = 0.f;

    float4 aReg = *(const float4*)Aptr;
    float4 bReg = make_float4(0.f, 0.f, 0.f, 0.f);
    if (tid < NB4) bReg = *(const float4*)BptrNT;
    As[0][acol + 0][arow] = aReg.x; As[0][acol + 1][arow] = aReg.y;
    As[0][acol + 2][arow] = aReg.z; As[0][acol + 3][arow] = aReg.w;
    if (tid < NB4) {
        Bs[0][bcol + 0][brow] = bReg.x; Bs[0][bcol + 1][brow] = bReg.y;
        Bs[0][bcol + 2][brow] = bReg.z; Bs[0][bcol + 3][brow] = bReg.w;
    }
    __syncthreads();

    int p = 0;
    for (int k0 = BK; k0 < K; k0 += BK) {
        aReg = *(const float4*)(Aptr + k0);
        if (tid < NB4) bReg = *(const float4*)(BptrNT + k0);
        #pragma unroll
        for (int kk = 0; kk < BK; kk++) {
            float a[8], b[TN];
            *(float4*)&a[0] = *(const float4*)&As[p][kk][(ty << 2)];
            *(float4*)&a[4] = *(const float4*)&As[p][kk][64 + (ty << 2)];
            *(float4*)&b[0] = *(const float4*)&Bs[p][kk][(tx << 2)];
            if (TN == 8) *(float4*)&b[4] = *(const float4*)&Bs[p][kk][BN / 2 + (tx << 2)];
            #pragma unroll
            for (int i = 0; i < 8; i++)
                #pragma unroll
                for (int j = 0; j < TN; j++)
                    acc[i][j] = fmaf(a[i], b[j], acc[i][j]);
        }
        int q = p ^ 1;
        As[q][acol + 0][arow] = aReg.x; As[q][acol + 1][arow] = aReg.y;
        As[q][acol + 2][arow] = aReg.z; As[q][acol + 3][arow] = aReg.w;
        if (tid < NB4) {
            Bs[q][bcol + 0][brow] = bReg.x; Bs[q][bcol + 1][brow] = bReg.y;
            Bs[q][bcol + 2][brow] = bReg.z; Bs[q][bcol + 3][brow] = bReg.w;
        }
        __syncthreads();
        p = q;
    }
    #pragma unroll
    for (int kk = 0; kk < BK; kk++) {
        float a[8], b[TN];
        *(float4*)&a[0] = *(const float4*)&As[p][kk][(ty << 2)];
        *(float4*)&a[4] = *(const float4*)&As[p][kk][64 + (ty << 2)];
        *(float4*)&b[0] = *(const float4*)&Bs[p][kk][(tx << 2)];
        if (TN == 8) *(float4*)&b[4] = *(const float4*)&Bs[p][kk][BN / 2 + (tx << 2)];
        #pragma unroll
        for (int i = 0; i < 8; i++)
            #pragma unroll
            for (int j = 0; j < TN; j++)
                acc[i][j] = fmaf(a[i], b[j], acc[i][j]);
    }
    #pragma unroll
    for (int half = 0; half < 2; half++) {
        #pragma unroll
        for (int i = 0; i < 4; i++) {
            int row = by * BM + half * 64 + (ty << 2) + i;
            float* cp = C + (long)row * ldc + bx * BN + (tx << 2);
            float4 v;
            v.x = alpha * acc[half * 4 + i][0]; v.y = alpha * acc[half * 4 + i][1];
            v.z = alpha * acc[half * 4 + i][2]; v.w = alpha * acc[half * 4 + i][3];
            *(float4*)cp = v;
            if (TN == 8) {
                float4 w;
                w.x = alpha * acc[half * 4 + i][4]; w.y = alpha * acc[half * 4 + i][5];
                w.z = alpha * acc[half * 4 + i][6]; w.w = alpha * acc[half * 4 + i][7];
                *(float4*)(cp + BN / 2) = w;
            }
        }
    }
}

// ---------------- RMSNorm ----------------
__global__ void rmsnorm_kernel(float* __restrict__ ql, const float* __restrict__ w)
{
    float* row = ql + (long)blockIdx.x * QLORA_;
    int tid = threadIdx.x;
    float s = 0.f;
    for (int i = tid; i < QLORA_; i += 256) { float v = row[i]; s += v * v; }
    __shared__ float red[256];
    red[tid] = s; __syncthreads();
    for (int st = 128; st > 0; st >>= 1) { if (tid < st) red[tid] += red[tid + st]; __syncthreads(); }
    float scale = rsqrtf(red[0] / (float)QLORA_ + 1e-6f);
    for (int i = tid; i < QLORA_; i += 256) row[i] = w[i] * (row[i] * scale);
}

// ---------------- RoPE ----------------
__device__ __forceinline__ void rope_pair(float p, int i, float x0, float x1,
                                          float& o_lo, float& o_hi)
{
    double inv = exp(-((double)(2 * i) / 64.0) * 13.815510557964274);
    double ang = (double)p * inv;
    double sd, cd; sincos(ang, &sd, &cd);
    float cc = (float)cd, ss = (float)sd;
    o_lo = x0 * cc - x1 * ss;
    o_hi = x1 * cc + x0 * ss;
}

__global__ void rope_q_kernel(const float* __restrict__ q, const int* __restrict__ pos,
                              float* __restrict__ qext)
{
    int idx = blockIdx.x * blockDim.x + threadIdx.x;
    if (idx >= BB * SS * NHH) return;
    int h = idx % NHH;
    int bs = idx / NHH;
    int b = bs / SS, s_idx = bs % SS;
    float p = (float)pos[bs];
    const float* x = q + ((long)bs * NHH + h) * QHD + NOPE_;
    float* o = qext + ((long)(b * NHH + h) * SS + s_idx) * QEXT + KVLORA_;
    for (int i = 0; i < 32; i++) {
        float lo, hi;
        rope_pair(p, i, x[2 * i], x[2 * i + 1], lo, hi);
        o[i] = lo; o[32 + i] = hi;
    }
}

__global__ void rope_k_kernel(float* __restrict__ ckv, const int* __restrict__ pos)
{
    int bs = blockIdx.x * blockDim.x + threadIdx.x;
    if (bs >= BB * SS) return;
    float p = (float)pos[bs];
    float* x = ckv + (long)bs * QEXT + KVLORA_;
    float tmp[64];
    for (int i = 0; i < 32; i++)
        rope_pair(p, i, x[2 * i], x[2 * i + 1], tmp[i], tmp[32 + i]);
    for (int j = 0; j < 64; j++) x[j] = tmp[j];
}

// ---------------- transposes ----------------
__global__ void transpose_wabs_kernel(const float* __restrict__ Wkv_up, float* __restrict__ outT)
{
    int idx = blockIdx.x * blockDim.x + threadIdx.x;
    if (idx >= NHH * KVLORA_ * NOPE_) return;
    int n = idx % NOPE_;
    int r = idx / NOPE_;
    int c = r % KVLORA_;
    int h = r / KVLORA_;
    outT[idx] = Wkv_up[((long)h * 256 + n) * KVLORA_ + c];
}

__global__ void transpose_ckv_kernel(const float* __restrict__ ckv, float* __restrict__ ckvT)
{
    __shared__ float t[32][33];
    int b = blockIdx.z;
    int s0 = blockIdx.x * 32, c0 = blockIdx.y * 32;
    int x = threadIdx.x, y = threadIdx.y;
    for (int i = y; i < 32; i += 8)
        t[i][x] = ckv[((long)b * SS + s0 + i) * QEXT + c0 + x];
    __syncthreads();
    for (int i = y; i < 32; i += 8)
        ckvT[((long)b * KVLORA_ + c0 + i) * SS + s0 + x] = t[x][i];
}

// ---------------- causal softmax ----------------
__global__ void softmax_kernel(float* __restrict__ scores)
{
    long row = blockIdx.x;
    int q = (int)(row % SS);
    float* r = scores + row * (long)SS;
    int tid = threadIdx.x;
    int n = q + 1;
    __shared__ float red[256];

    float mx = -1e30f;
    for (int k = tid; k < n; k += 256) mx = fmaxf(mx, r[k]);
    red[tid] = mx; __syncthreads();
    for (int st = 128; st > 0; st >>= 1) { if (tid < st) red[tid] = fmaxf(red[tid], red[tid + st]); __syncthreads(); }
    mx = red[0]; __syncthreads();

    float sum = 0.f;
    for (int k = tid; k < n; k += 256) { float e = __expf(r[k] - mx); r[k] = e; sum += e; }
    red[tid] = sum; __syncthreads();
    for (int st = 128; st > 0; st >>= 1) { if (tid < st) red[tid] += red[tid + st]; __syncthreads(); }
    float inv = 1.f / red[0];

    for (int k = tid; k < n; k += 256) r[k] *= inv;
    for (int k = n + tid; k < SS; k += 256) r[k] = 0.f;
}

// ---------------- host ----------------
static void launch_mma(const float* A, const float* B, float* C,
                       int M, int N, int K, int lda, int ldb, int ldc,
                       long sAb, long sAh, long sBb, long sBh, long sCb, long sCh,
                       int zh, int zcount, float alpha, int cSkip, int cK)
{
    cudaFuncSetAttribute(mma_gemm, cudaFuncAttributeMaxDynamicSharedMemorySize, MSMEM);
    dim3 grid(N / 128, M / 128, zcount);
    mma_gemm<<<grid, 256, MSMEM>>>(A, B, C, K, lda, ldb, ldc,
                                   sAb, sAh, sBb, sBh, sCb, sCh, zh, alpha, cSkip, cK);
}

extern "C" void kernel_launch(void* const* d_in, const int* in_sizes, int n_in,
                              void* d_out, int out_size)
{
    const float* hs      = (const float*)d_in[0];
    const int*   pos     = (const int*)  d_in[1];
    const float* Wq_down = (const float*)d_in[3];
    const float* q_ln_w  = (const float*)d_in[4];
    const float* Wq_up   = (const float*)d_in[5];
    const float* Wkv_down= (const float*)d_in[6];
    const float* Wkv_up  = (const float*)d_in[7];
    const float* Wo      = (const float*)d_in[8];
    float* out = (float*)d_out;

    float *ql, *q, *ckv, *ckvT, *qext, *scores, *out1, *out2, *wabsT;
    cudaGetSymbolAddress((void**)&ql,     g_ql);
    cudaGetSymbolAddress((void**)&q,      g_q);
    cudaGetSymbolAddress((void**)&ckv,    g_ckv);
    cudaGetSymbolAddress((void**)&ckvT,   g_ckvT);
    cudaGetSymbolAddress((void**)&qext,   g_qext);
    cudaGetSymbolAddress((void**)&scores, g_scores);
    cudaGetSymbolAddress((void**)&out1,   g_out1);
    cudaGetSymbolAddress((void**)&out2,   g_out2);
    cudaGetSymbolAddress((void**)&wabsT,  g_wabsT);

    const int M = BB * SS;
    const float scale = 1.0f / sqrtf((float)QHD);

    // 1. ql = hs @ Wq_down^T [4096,1536]
    launch_mma(hs, Wq_down, ql, M, QLORA_, HDIM, HDIM, HDIM, QLORA_,
               0,0,0,0,0,0, 1, 1, 1.f, 0, 0);
    // 2. RMSNorm
    rmsnorm_kernel<<<M, 256>>>(ql, q_ln_w);
    // 3. q = ql @ Wq_up^T [4096,3072]
    launch_mma(ql, Wq_up, q, M, NHH * QHD, QLORA_, QLORA_, QLORA_, NHH * QHD,
               0,0,0,0,0,0, 1, 1, 1.f, 0, 0);
    // 4. ckv = hs @ Wkv_down^T [4096,576] (SIMT, N not /128)
    {
        dim3 grid(QEXT / 64, M / 128, 1);
        gemm_kernel<64, 4><<<grid, 256>>>(hs, Wkv_down, ckv, HDIM, HDIM, HDIM, QEXT, 1.f);
    }
    // 5. q_absorb^T per head
    transpose_wabs_kernel<<<(NHH * KVLORA_ * NOPE_ + 255) / 256, 256>>>(Wkv_up, wabsT);
    // 6. RoPE k
    rope_k_kernel<<<(BB * SS + 255) / 256, 256>>>(ckv, pos);
    // 7. RoPE q -> qext cols 512:576
    rope_q_kernel<<<(BB * SS * NHH + 255) / 256, 256>>>(q, pos, qext);
    // 8. qext[:,0:512] = q_nope @ q_absorb (batched)
    launch_mma(q, wabsT, qext, SS, KVLORA_, NOPE_,
               NHH * QHD, NOPE_, QEXT,
               (long)SS * NHH * QHD, (long)QHD,
               0, (long)KVLORA_ * NOPE_,
               (long)NHH * SS * QEXT, (long)SS * QEXT,
               NHH, BB * NHH, 1.f, 0, 0);
    // 9. scores = scale * qext @ ckv^T (batched, causal skip)
    launch_mma(qext, ckv, scores, SS, SS, QEXT,
               QEXT, QEXT, SS,
               (long)NHH * SS * QEXT, (long)SS * QEXT,
               (long)SS * QEXT, 0,
               (long)NHH * SS * SS, (long)SS * SS,
               NHH, BB * NHH, scale, 1, 0);
    // 10. softmax
    softmax_kernel<<<BB * NHH * SS, 256>>>(scores);
    // 11a. ckvT
    {
        dim3 grid(SS / 32, KVLORA_ / 32, BB);
        transpose_ckv_kernel<<<grid, dim3(32, 8)>>>(ckv, ckvT);
    }
    // 11b. out1 = attn @ ckv (via ckvT, causal K-limit)
    launch_mma(scores, ckvT, out1, SS, KVLORA_, SS,
               SS, SS, KVLORA_,
               (long)NHH * SS * SS, (long)SS * SS,
               (long)KVLORA_ * SS, 0,
               (long)NHH * SS * KVLORA_, (long)SS * KVLORA_,
               NHH, BB * NHH, 1.f, 0, 1);
    // 12. out2 = out1 @ out_absorb^T (batched)
    launch_mma(out1, Wkv_up + (long)NOPE_ * KVLORA_, out2, SS, VD_, KVLORA_,
               KVLORA_, KVLORA_, NHH * VD_,
               (long)NHH * SS * KVLORA_, (long)SS * KVLORA_,
               0, (long)256 * KVLORA_,
               (long)SS * NHH * VD_, (long)VD_,
               NHH, BB * NHH, 1.f, 0, 0);
    // 13. final = out2 @ Wo^T [4096,2048]
    launch_mma(out2, Wo, out, M, HDIM, NHH * VD_, NHH * VD_, NHH * VD_, HDIM,
               0,0,0,0,0,0, 1, 1, 1.f, 0, 0);
}

// round 5
// speedup vs baseline: 2.5025x; 1.2578x over previous
#include <cuda_runtime.h>
#include <cuda_bf16.h>
#include <math.h>
#include <stdint.h>

typedef unsigned short U16;

// ---------------- problem constants ----------------
#define NHH   16
#define NOPE_ 128
#define ROPED 64
#define VD_   128
#define QLORA_ 1536
#define KVLORA_ 512
#define HDIM  2048
#define BB    2
#define SS    2048
#define QEXT  576
#define QHD   (NOPE_ + ROPED)  // 192

// ---------------- scratch ----------------
__device__ float g_ql    [(long)BB*SS*QLORA_];
__device__ float g_ckv   [(long)BB*SS*QEXT];
__device__ float g_scores[(long)BB*NHH*SS*SS];

__device__ U16 g_hs_h [(long)BB*SS*HDIM],      g_hs_l [(long)BB*SS*HDIM];
__device__ U16 g_wqd_h[(long)QLORA_*HDIM],     g_wqd_l[(long)QLORA_*HDIM];
__device__ U16 g_wqu_h[(long)NHH*QHD*QLORA_],  g_wqu_l[(long)NHH*QHD*QLORA_];
__device__ U16 g_wo_h [(long)HDIM*HDIM],       g_wo_l [(long)HDIM*HDIM];
__device__ U16 g_wkvup_h[(long)NHH*256*KVLORA_], g_wkvup_l[(long)NHH*256*KVLORA_];
__device__ U16 g_wabsT_h[(long)NHH*KVLORA_*NOPE_], g_wabsT_l[(long)NHH*KVLORA_*NOPE_];
__device__ U16 g_ql_h [(long)BB*SS*QLORA_],    g_ql_l [(long)BB*SS*QLORA_];
__device__ U16 g_q_h  [(long)BB*SS*NHH*QHD],   g_q_l  [(long)BB*SS*NHH*QHD];
__device__ U16 g_ckv_h[(long)BB*SS*QEXT],      g_ckv_l[(long)BB*SS*QEXT];
__device__ U16 g_ckvT_h[(long)BB*KVLORA_*SS],  g_ckvT_l[(long)BB*KVLORA_*SS];
__device__ U16 g_qext_h[(long)BB*NHH*SS*QEXT], g_qext_l[(long)BB*NHH*SS*QEXT];
__device__ U16 g_sc_h [(long)BB*NHH*SS*SS],    g_sc_l [(long)BB*NHH*SS*SS];
__device__ U16 g_out1_h[(long)BB*NHH*SS*KVLORA_], g_out1_l[(long)BB*NHH*SS*KVLORA_];
__device__ U16 g_out2_h[(long)BB*SS*NHH*VD_],  g_out2_l[(long)BB*SS*NHH*VD_];

// ================= helpers =================
__device__ __forceinline__ uint32_t smem_u32(const void* p) {
    uint32_t a;
    asm("{ .reg .u64 t; cvta.to.shared.u64 t, %1; cvt.u32.u64 %0, t; }" : "=r"(a) : "l"(p));
    return a;
}
__device__ __forceinline__ void cp16(uint32_t dst, const void* src) {
    asm volatile("cp.async.cg.shared.global [%0], [%1], 16;" :: "r"(dst), "l"(src));
}
#define CP_COMMIT() asm volatile("cp.async.commit_group;" ::: "memory")
#define CP_WAIT1()  asm volatile("cp.async.wait_group 1;" ::: "memory")

__device__ __forceinline__ void ldmx4(uint32_t* r, uint32_t addr) {
    asm volatile("ldmatrix.sync.aligned.m8n8.x4.shared.b16 {%0,%1,%2,%3}, [%4];"
                 : "=r"(r[0]), "=r"(r[1]), "=r"(r[2]), "=r"(r[3]) : "r"(addr));
}
__device__ __forceinline__ void mma16816(float* d, const uint32_t* a, const uint32_t* b) {
    asm volatile("mma.sync.aligned.m16n8k16.row.col.f32.bf16.bf16.f32 "
                 "{%0,%1,%2,%3}, {%4,%5,%6,%7}, {%8,%9}, {%0,%1,%2,%3};"
                 : "+f"(d[0]), "+f"(d[1]), "+f"(d[2]), "+f"(d[3])
                 : "r"(a[0]), "r"(a[1]), "r"(a[2]), "r"(a[3]), "r"(b[0]), "r"(b[1]));
}
__device__ __forceinline__ void split1(float v, U16& h, U16& l) {
    __nv_bfloat16 hb = __float2bfloat16(v);
    __nv_bfloat16 lb = __float2bfloat16(v - __bfloat162float(hb));
    h = __bfloat16_as_ushort(hb);
    l = __bfloat16_as_ushort(lb);
}

// ================= bf16-pair warp-MMA GEMM =================
// C = alpha * A @ B^T.  A,B pre-split hi/lo bf16 (row-major, elem ld).
// Block 128x128, BK=32, 3-stage cp.async pipeline, 8 warps (2x4), warp 64x32.
#define ROWB 80
#define TILEB (128 * ROWB)     // 10240
#define SGB   (4 * TILEB)      // 40960 per stage
#define MSMEM (3 * SGB)        // 122880

extern __shared__ char dsmem[];

__device__ __forceinline__ void issue_stage(uint32_t sbase,
    const U16* gAh, const U16* gAl, const U16* gBh, const U16* gBl,
    int lda, int ldb, int k0, int tid)
{
    #pragma unroll
    for (int half = 0; half < 2; half++) {
        int idx = (half << 8) + tid;          // 0..511
        int row = idx >> 2;
        int e0  = (idx & 3) << 3;             // element offset in chunk row
        long ao = (long)row * lda + k0 + e0;
        long bo = (long)row * ldb + k0 + e0;
        uint32_t d = sbase + (uint32_t)(row * ROWB + (e0 << 1));
        cp16(d,             gAh + ao);
        cp16(d + TILEB,     gAl + ao);
        cp16(d + 2 * TILEB, gBh + bo);
        cp16(d + 3 * TILEB, gBl + bo);
    }
}

__global__ void __launch_bounds__(256)
mma_gemm(const U16* __restrict__ Ah, const U16* __restrict__ Al,
         const U16* __restrict__ Bh, const U16* __restrict__ Bl,
         float* __restrict__ C, U16* __restrict__ Chi, U16* __restrict__ Clo,
         int K, int lda, int ldb, int ldc,
         long sAb, long sAhh, long sBb, long sBhh, long sCb, long sChh,
         int zh, float alpha, int causalSkip, int causalK, int pairOut)
{
    int z = blockIdx.z;
    long ao = (long)(z / zh) * sAb + (long)(z % zh) * sAhh;
    long bo = (long)(z / zh) * sBb + (long)(z % zh) * sBhh;
    long co = (long)(z / zh) * sCb + (long)(z % zh) * sChh;
    int by = blockIdx.y, bx = blockIdx.x;
    if (causalSkip && bx * 128 > by * 128 + 127) return;
    int Klim = causalK ? min(K, by * 128 + 128) : K;
    int nCh = Klim >> 5;

    int tid = threadIdx.x;
    int lane = tid & 31, wid = tid >> 5;
    int wm = wid & 1, wn = wid >> 1;

    uint32_t sb = smem_u32(dsmem);

    const U16* gAh = Ah + ao + (long)(by * 128) * lda;
    const U16* gAl = Al + ao + (long)(by * 128) * lda;
    const U16* gBh = Bh + bo + (long)(bx * 128) * ldb;
    const U16* gBl = Bl + bo + (long)(bx * 128) * ldb;

    // ldmatrix lane offsets
    uint32_t aoff[4][2], boff[2][2];
    {
        int ar = wm * 64 + (lane & 15);
        int ak = (lane >> 4) << 3;
        #pragma unroll
        for (int mt = 0; mt < 4; mt++)
            #pragma unroll
            for (int kh = 0; kh < 2; kh++)
                aoff[mt][kh] = (uint32_t)((ar + mt * 16) * ROWB + ((ak + kh * 16) << 1));
        int br = wn * 32 + (lane & 7) + ((lane & 16) ? 8 : 0);
        int bk = (lane & 8) ? 8 : 0;
        #pragma unroll
        for (int np = 0; np < 2; np++)
            #pragma unroll
            for (int kh = 0; kh < 2; kh++)
                boff[np][kh] = (uint32_t)((br + np * 16) * ROWB + ((bk + kh * 16) << 1));
    }

    float acc[4][4][4];
    #pragma unroll
    for (int mt = 0; mt < 4; mt++)
        #pragma unroll
        for (int nt = 0; nt < 4; nt++)
            #pragma unroll
            for (int r = 0; r < 4; r++) acc[mt][nt][r] = 0.f;

    // prologue: stages 0,1
    issue_stage(sb, gAh, gAl, gBh, gBl, lda, ldb, 0, tid);
    CP_COMMIT();
    if (nCh > 1)
        issue_stage(sb + SGB, gAh, gAl, gBh, gBl, lda, ldb, 32, tid);
    CP_COMMIT();

    int sc = 0;  // stage of chunk c
    for (int c = 0; c < nCh; c++) {
        CP_WAIT1();
        __syncthreads();
        if (c + 2 < nCh) {
            int sn = sc + 2; if (sn >= 3) sn -= 3;
            issue_stage(sb + sn * SGB, gAh, gAl, gBh, gBl, lda, ldb, (c + 2) << 5, tid);
        }
        CP_COMMIT();

        uint32_t bufb = sb + sc * SGB;
        uint32_t sAh_ = bufb, sAl_ = bufb + TILEB, sBh_ = bufb + 2 * TILEB, sBl_ = bufb + 3 * TILEB;
        #pragma unroll
        for (int kh = 0; kh < 2; kh++) {
            uint32_t ah[4][4], al[4][4], bh[2][4], bl[2][4];
            #pragma unroll
            for (int mt = 0; mt < 4; mt++) {
                ldmx4(ah[mt], sAh_ + aoff[mt][kh]);
                ldmx4(al[mt], sAl_ + aoff[mt][kh]);
            }
            #pragma unroll
            for (int np = 0; np < 2; np++) {
                ldmx4(bh[np], sBh_ + boff[np][kh]);
                ldmx4(bl[np], sBl_ + boff[np][kh]);
            }
            #pragma unroll
            for (int mt = 0; mt < 4; mt++) {
                #pragma unroll
                for (int nt = 0; nt < 4; nt++) {
                    const uint32_t* bhp = &bh[nt >> 1][(nt & 1) << 1];
                    const uint32_t* blp = &bl[nt >> 1][(nt & 1) << 1];
                    mma16816(acc[mt][nt], ah[mt], bhp);
                    mma16816(acc[mt][nt], ah[mt], blp);
                    mma16816(acc[mt][nt], al[mt], bhp);
                }
            }
        }
        __syncthreads();
        if (++sc == 3) sc = 0;
    }

    // epilogue
    #pragma unroll
    for (int mt = 0; mt < 4; mt++) {
        int r0 = by * 128 + wm * 64 + mt * 16 + (lane >> 2);
        #pragma unroll
        for (int nt = 0; nt < 4; nt++) {
            int c0 = bx * 128 + wn * 32 + nt * 8 + ((lane & 3) << 1);
            float v00 = alpha * acc[mt][nt][0], v01 = alpha * acc[mt][nt][1];
            float v10 = alpha * acc[mt][nt][2], v11 = alpha * acc[mt][nt][3];
            if (!pairOut) {
                *(float2*)(C + co + (long)r0 * ldc + c0) = make_float2(v00, v01);
                *(float2*)(C + co + (long)(r0 + 8) * ldc + c0) = make_float2(v10, v11);
            } else {
                U16 h0, l0, h1, l1;
                split1(v00, h0, l0); split1(v01, h1, l1);
                *(uint32_t*)(Chi + co + (long)r0 * ldc + c0) = (uint32_t)h0 | ((uint32_t)h1 << 16);
                *(uint32_t*)(Clo + co + (long)r0 * ldc + c0) = (uint32_t)l0 | ((uint32_t)l1 << 16);
                split1(v10, h0, l0); split1(v11, h1, l1);
                *(uint32_t*)(Chi + co + (long)(r0 + 8) * ldc + c0) = (uint32_t)h0 | ((uint32_t)h1 << 16);
                *(uint32_t*)(Clo + co + (long)(r0 + 8) * ldc + c0) = (uint32_t)l0 | ((uint32_t)l1 << 16);
            }
        }
    }
}

// ---------------- SIMT GEMM (N=576 ckv-down, fp32) ----------------
template<int BN, int TN>
__global__ void __launch_bounds__(256, 2)
gemm_kernel(const float* __restrict__ A, const float* __restrict__ B,
            float* __restrict__ C, int K, int lda, int ldb, int ldc, float alpha)
{
    constexpr int BM = 128, BK = 8;
    int by = blockIdx.y, bx = blockIdx.x;

    __shared__ float As[2][BK][BM + 4];
    __shared__ float Bs[2][BK][BN + 4];

    int tid = threadIdx.x;
    int tx = tid & 15, ty = tid >> 4;
    int arow = tid >> 1, acol = (tid & 1) << 2;
    const float* Aptr = A + (long)(by * BM + arow) * lda + acol;
    constexpr int NB4 = BN * 2;
    int brow = tid >> 1, bcol = (tid & 1) << 2;
    const float* BptrNT = B + (long)(bx * BN + brow) * ldb + bcol;

    float acc[8][TN];
    #pragma unroll
    for (int i = 0; i < 8; i++)
        #pragma unroll
        for (int j = 0; j < TN; j++) acc[i][j] = 0.f;

    float4 aReg = *(const float4*)Aptr;
    float4 bReg = make_float4(0.f, 0.f, 0.f, 0.f);
    if (tid < NB4) bReg = *(const float4*)BptrNT;
    As[0][acol + 0][arow] = aReg.x; As[0][acol + 1][arow] = aReg.y;
    As[0][acol + 2][arow] = aReg.z; As[0][acol + 3][arow] = aReg.w;
    if (tid < NB4) {
        Bs[0][bcol + 0][brow] = bReg.x; Bs[0][bcol + 1][brow] = bReg.y;
        Bs[0][bcol + 2][brow] = bReg.z; Bs[0][bcol + 3][brow] = bReg.w;
    }
    __syncthreads();

    int p = 0;
    for (int k0 = BK; k0 < K; k0 += BK) {
        aReg = *(const float4*)(Aptr + k0);
        if (tid < NB4) bReg = *(const float4*)(BptrNT + k0);
        #pragma unroll
        for (int kk = 0; kk < BK; kk++) {
            float a[8], b[TN];
            *(float4*)&a[0] = *(const float4*)&As[p][kk][(ty << 2)];
            *(float4*)&a[4] = *(const float4*)&As[p][kk][64 + (ty << 2)];
            *(float4*)&b[0] = *(const float4*)&Bs[p][kk][(tx << 2)];
            if (TN == 8) *(float4*)&b[4] = *(const float4*)&Bs[p][kk][BN / 2 + (tx << 2)];
            #pragma unroll
            for (int i = 0; i < 8; i++)
                #pragma unroll
                for (int j = 0; j < TN; j++)
                    acc[i][j] = fmaf(a[i], b[j], acc[i][j]);
        }
        int q = p ^ 1;
        As[q][acol + 0][arow] = aReg.x; As[q][acol + 1][arow] = aReg.y;
        As[q][acol + 2][arow] = aReg.z; As[q][acol + 3][arow] = aReg.w;
        if (tid < NB4) {
            Bs[q][bcol + 0][brow] = bReg.x; Bs[q][bcol + 1][brow] = bReg.y;
            Bs[q][bcol + 2][brow] = bReg.z; Bs[q][bcol + 3][brow] = bReg.w;
        }
        __syncthreads();
        p = q;
    }
    #pragma unroll
    for (int kk = 0; kk < BK; kk++) {
        float a[8], b[TN];
        *(float4*)&a[0] = *(const float4*)&As[p][kk][(ty << 2)];
        *(float4*)&a[4] = *(const float4*)&As[p][kk][64 + (ty << 2)];
        *(float4*)&b[0] = *(const float4*)&Bs[p][kk][(tx << 2)];
        if (TN == 8) *(float4*)&b[4] = *(const float4*)&Bs[p][kk][BN / 2 + (tx << 2)];
        #pragma unroll
        for (int i = 0; i < 8; i++)
            #pragma unroll
            for (int j = 0; j < TN; j++)
                acc[i][j] = fmaf(a[i], b[j], acc[i][j]);
    }
    #pragma unroll
    for (int half = 0; half < 2; half++) {
        #pragma unroll
        for (int i = 0; i < 4; i++) {
            int row = by * BM + half * 64 + (ty << 2) + i;
            float* cp = C + (long)row * ldc + bx * BN + (tx << 2);
            float4 v;
            v.x = alpha * acc[half * 4 + i][0]; v.y = alpha * acc[half * 4 + i][1];
            v.z = alpha * acc[half * 4 + i][2]; v.w = alpha * acc[half * 4 + i][3];
            *(float4*)cp = v;
            if (TN == 8) {
                float4 w;
                w.x = alpha * acc[half * 4 + i][4]; w.y = alpha * acc[half * 4 + i][5];
                w.z = alpha * acc[half * 4 + i][6]; w.w = alpha * acc[half * 4 + i][7];
                *(float4*)(cp + BN / 2) = w;
            }
        }
    }
}

// ---------------- split fp32 -> bf16 hi/lo ----------------
__global__ void split_kernel(const float* __restrict__ src,
                             U16* __restrict__ hi, U16* __restrict__ lo, long n)
{
    long i = ((long)blockIdx.x * 256 + threadIdx.x) * 4;
    if (i >= n) return;
    float4 v = *(const float4*)(src + i);
    U16 h[4], l[4];
    split1(v.x, h[0], l[0]); split1(v.y, h[1], l[1]);
    split1(v.z, h[2], l[2]); split1(v.w, h[3], l[3]);
    uint2 hv, lv;
    hv.x = (uint32_t)h[0] | ((uint32_t)h[1] << 16); hv.y = (uint32_t)h[2] | ((uint32_t)h[3] << 16);
    lv.x = (uint32_t)l[0] | ((uint32_t)l[1] << 16); lv.y = (uint32_t)l[2] | ((uint32_t)l[3] << 16);
    *(uint2*)(hi + i) = hv;
    *(uint2*)(lo + i) = lv;
}

// ---------------- RMSNorm (fp32 in, pair out) ----------------
__global__ void rmsnorm_kernel(const float* __restrict__ ql, const float* __restrict__ w,
                               U16* __restrict__ oh, U16* __restrict__ ol)
{
    const float* row = ql + (long)blockIdx.x * QLORA_;
    long ob = (long)blockIdx.x * QLORA_;
    int tid = threadIdx.x;
    float s = 0.f;
    for (int i = tid; i < QLORA_; i += 256) { float v = row[i]; s += v * v; }
    __shared__ float red[256];
    red[tid] = s; __syncthreads();
    for (int st = 128; st > 0; st >>= 1) { if (tid < st) red[tid] += red[tid + st]; __syncthreads(); }
    float scale = rsqrtf(red[0] / (float)QLORA_ + 1e-6f);
    for (int i = tid; i < QLORA_; i += 256) {
        float v = w[i] * (row[i] * scale);
        U16 h, l; split1(v, h, l);
        oh[ob + i] = h; ol[ob + i] = l;
    }
}

// ---------------- RoPE ----------------
__device__ __forceinline__ void rope_pair(float p, int i, float x0, float x1,
                                          float& o_lo, float& o_hi)
{
    double inv = exp(-((double)(2 * i) / 64.0) * 13.815510557964274);
    double ang = (double)p * inv;
    double sd, cd; sincos(ang, &sd, &cd);
    float cc = (float)cd, ss = (float)sd;
    o_lo = x0 * cc - x1 * ss;
    o_hi = x1 * cc + x0 * ss;
}

__global__ void rope_q_kernel(const U16* __restrict__ qh, const U16* __restrict__ qlo,
                              const int* __restrict__ pos,
                              U16* __restrict__ eh, U16* __restrict__ el)
{
    int idx = blockIdx.x * blockDim.x + threadIdx.x;
    if (idx >= BB * SS * NHH) return;
    int h = idx % NHH;
    int bs = idx / NHH;
    int b = bs / SS, s_idx = bs % SS;
    float p = (float)pos[bs];
    long xb = ((long)bs * NHH + h) * QHD + NOPE_;
    long ob = ((long)(b * NHH + h) * SS + s_idx) * QEXT + KVLORA_;
    for (int i = 0; i < 32; i++) {
        float x0 = __bfloat162float(__ushort_as_bfloat16(qh[xb + 2 * i]))
                 + __bfloat162float(__ushort_as_bfloat16(qlo[xb + 2 * i]));
        float x1 = __bfloat162float(__ushort_as_bfloat16(qh[xb + 2 * i + 1]))
                 + __bfloat162float(__ushort_as_bfloat16(qlo[xb + 2 * i + 1]));
        float lo, hi;
        rope_pair(p, i, x0, x1, lo, hi);
        U16 a, c;
        split1(lo, a, c); eh[ob + i] = a; el[ob + i] = c;
        split1(hi, a, c); eh[ob + 32 + i] = a; el[ob + 32 + i] = c;
    }
}

__global__ void rope_k_kernel(float* __restrict__ ckv, const int* __restrict__ pos)
{
    int bs = blockIdx.x * blockDim.x + threadIdx.x;
    if (bs >= BB * SS) return;
    float p = (float)pos[bs];
    float* x = ckv + (long)bs * QEXT + KVLORA_;
    float tmp[64];
    for (int i = 0; i < 32; i++)
        rope_pair(p, i, x[2 * i], x[2 * i + 1], tmp[i], tmp[32 + i]);
    for (int j = 0; j < 64; j++) x[j] = tmp[j];
}

// ---------------- transposes (pair out) ----------------
__global__ void transpose_wabs_kernel(const float* __restrict__ Wkv_up,
                                      U16* __restrict__ oh, U16* __restrict__ ol)
{
    int idx = blockIdx.x * blockDim.x + threadIdx.x;
    if (idx >= NHH * KVLORA_ * NOPE_) return;
    int n = idx % NOPE_;
    int r = idx / NOPE_;
    int c = r % KVLORA_;
    int h = r / KVLORA_;
    float v = Wkv_up[((long)h * 256 + n) * KVLORA_ + c];
    U16 a, b; split1(v, a, b);
    oh[idx] = a; ol[idx] = b;
}

__global__ void transpose_ckv_kernel(const float* __restrict__ ckv,
                                     U16* __restrict__ oh, U16* __restrict__ ol)
{
    __shared__ float t[32][33];
    int b = blockIdx.z;
    int s0 = blockIdx.x * 32, c0 = blockIdx.y * 32;
    int x = threadIdx.x, y = threadIdx.y;
    for (int i = y; i < 32; i += 8)
        t[i][x] = ckv[((long)b * SS + s0 + i) * QEXT + c0 + x];
    __syncthreads();
    for (int i = y; i < 32; i += 8) {
        long o = ((long)b * KVLORA_ + c0 + i) * SS + s0 + x;
        U16 hh, ll; split1(t[x][i], hh, ll);
        oh[o] = hh; ol[o] = ll;
    }
}

// ---------------- causal softmax (fp32 in, pair out) ----------------
__global__ void softmax_kernel(const float* __restrict__ scores,
                               U16* __restrict__ oh, U16* __restrict__ ol)
{
    long row = blockIdx.x;
    int q = (int)(row % SS);
    const float* r = scores + row * (long)SS;
    long ob = row * (long)SS;
    int tid = threadIdx.x;
    int n = q + 1;
    __shared__ float red[256];

    float mx = -1e30f;
    for (int k = tid; k < n; k += 256) mx = fmaxf(mx, r[k]);
    red[tid] = mx; __syncthreads();
    for (int st = 128; st > 0; st >>= 1) { if (tid < st) red[tid] = fmaxf(red[tid], red[tid + st]); __syncthreads(); }
    mx = red[0]; __syncthreads();

    float sum = 0.f;
    __shared__ float es[2048];
    for (int k = tid; k < n; k += 256) { float e = __expf(r[k] - mx); es[k] = e; sum += e; }
    red[tid] = sum; __syncthreads();
    for (int st = 128; st > 0; st >>= 1) { if (tid < st) red[tid] += red[tid + st]; __syncthreads(); }
    float inv = 1.f / red[0];

    for (int k = tid; k < n; k += 256) {
        U16 h, l; split1(es[k] * inv, h, l);
        oh[ob + k] = h; ol[ob + k] = l;
    }
    for (int k = n + tid; k < SS; k += 256) { oh[ob + k] = 0; ol[ob + k] = 0; }
}

// ---------------- host ----------------
static void launch_mma(const U16* Ah, const U16* Al, const U16* Bh, const U16* Bl,
                       float* C, U16* Chi, U16* Clo,
                       int M, int N, int K, int lda, int ldb, int ldc,
                       long sAb, long sAh, long sBb, long sBh, long sCb, long sCh,
                       int zh, int zcount, float alpha, int cSkip, int cK, int pairOut)
{
    cudaFuncSetAttribute(mma_gemm, cudaFuncAttributeMaxDynamicSharedMemorySize, MSMEM);
    dim3 grid(N / 128, M / 128, zcount);
    mma_gemm<<<grid, 256, MSMEM>>>(Ah, Al, Bh, Bl, C, Chi, Clo, K, lda, ldb, ldc,
                                   sAb, sAh, sBb, sBh, sCb, sCh, zh, alpha, cSkip, cK, pairOut);
}

static void launch_split(const float* s, U16* h, U16* l, long n)
{
    split_kernel<<<(unsigned)((n / 4 + 255) / 256), 256>>>(s, h, l, n);
}

extern "C" void kernel_launch(void* const* d_in, const int* in_sizes, int n_in,
                              void* d_out, int out_size)
{
    const float* hs      = (const float*)d_in[0];
    const int*   pos     = (const int*)  d_in[1];
    const float* Wq_down = (const float*)d_in[3];
    const float* q_ln_w  = (const float*)d_in[4];
    const float* Wq_up   = (const float*)d_in[5];
    const float* Wkv_down= (const float*)d_in[6];
    const float* Wkv_up  = (const float*)d_in[7];
    const float* Wo      = (const float*)d_in[8];
    float* out = (float*)d_out;

    float *ql, *ckv, *scores;
    cudaGetSymbolAddress((void**)&ql, g_ql);
    cudaGetSymbolAddress((void**)&ckv, g_ckv);
    cudaGetSymbolAddress((void**)&scores, g_scores);
    U16 *hs_h, *hs_l, *wqd_h, *wqd_l, *wqu_h, *wqu_l, *wo_h, *wo_l;
    U16 *wkvup_h, *wkvup_l, *wabsT_h, *wabsT_l, *ql_h, *ql_l, *q_h, *q_l;
    U16 *ckv_h, *ckv_l, *ckvT_h, *ckvT_l, *qext_h, *qext_l;
    U16 *sc_h, *sc_l, *out1_h, *out1_l, *out2_h, *out2_l;
    cudaGetSymbolAddress((void**)&hs_h, g_hs_h);     cudaGetSymbolAddress((void**)&hs_l, g_hs_l);
    cudaGetSymbolAddress((void**)&wqd_h, g_wqd_h);   cudaGetSymbolAddress((void**)&wqd_l, g_wqd_l);
    cudaGetSymbolAddress((void**)&wqu_h, g_wqu_h);   cudaGetSymbolAddress((void**)&wqu_l, g_wqu_l);
    cudaGetSymbolAddress((void**)&wo_h, g_wo_h);     cudaGetSymbolAddress((void**)&wo_l, g_wo_l);
    cudaGetSymbolAddress((void**)&wkvup_h, g_wkvup_h); cudaGetSymbolAddress((void**)&wkvup_l, g_wkvup_l);
    cudaGetSymbolAddress((void**)&wabsT_h, g_wabsT_h); cudaGetSymbolAddress((void**)&wabsT_l, g_wabsT_l);
    cudaGetSymbolAddress((void**)&ql_h, g_ql_h);     cudaGetSymbolAddress((void**)&ql_l, g_ql_l);
    cudaGetSymbolAddress((void**)&q_h, g_q_h);       cudaGetSymbolAddress((void**)&q_l, g_q_l);
    cudaGetSymbolAddress((void**)&ckv_h, g_ckv_h);   cudaGetSymbolAddress((void**)&ckv_l, g_ckv_l);
    cudaGetSymbolAddress((void**)&ckvT_h, g_ckvT_h); cudaGetSymbolAddress((void**)&ckvT_l, g_ckvT_l);
    cudaGetSymbolAddress((void**)&qext_h, g_qext_h); cudaGetSymbolAddress((void**)&qext_l, g_qext_l);
    cudaGetSymbolAddress((void**)&sc_h, g_sc_h);     cudaGetSymbolAddress((void**)&sc_l, g_sc_l);
    cudaGetSymbolAddress((void**)&out1_h, g_out1_h); cudaGetSymbolAddress((void**)&out1_l, g_out1_l);
    cudaGetSymbolAddress((void**)&out2_h, g_out2_h); cudaGetSymbolAddress((void**)&out2_l, g_out2_l);

    const int M = BB * SS;
    const float scale = 1.0f / sqrtf((float)QHD);

    // input/weight splits
    launch_split(hs, hs_h, hs_l, (long)BB * SS * HDIM);
    launch_split(Wq_down, wqd_h, wqd_l, (long)QLORA_ * HDIM);
    launch_split(Wq_up, wqu_h, wqu_l, (long)NHH * QHD * QLORA_);
    launch_split(Wo, wo_h, wo_l, (long)HDIM * HDIM);
    launch_split(Wkv_up, wkvup_h, wkvup_l, (long)NHH * 256 * KVLORA_);
    transpose_wabs_kernel<<<(NHH * KVLORA_ * NOPE_ + 255) / 256, 256>>>(Wkv_up, wabsT_h, wabsT_l);

    // 1. ql = hs @ Wq_down^T [4096,1536] fp32 out
    launch_mma(hs_h, hs_l, wqd_h, wqd_l, ql, 0, 0,
               M, QLORA_, HDIM, HDIM, HDIM, QLORA_,
               0,0,0,0,0,0, 1, 1, 1.f, 0, 0, 0);
    // 2. RMSNorm -> ql pair
    rmsnorm_kernel<<<M, 256>>>(ql, q_ln_w, ql_h, ql_l);
    // 3. q = ql @ Wq_up^T [4096,3072] pair out
    launch_mma(ql_h, ql_l, wqu_h, wqu_l, 0, q_h, q_l,
               M, NHH * QHD, QLORA_, QLORA_, QLORA_, NHH * QHD,
               0,0,0,0,0,0, 1, 1, 1.f, 0, 0, 1);
    // 4. ckv = hs @ Wkv_down^T [4096,576] SIMT fp32
    {
        dim3 grid(QEXT / 64, M / 128, 1);
        gemm_kernel<64, 4><<<grid, 256>>>(hs, Wkv_down, ckv, HDIM, HDIM, HDIM, QEXT, 1.f);
    }
    // 5. RoPE k (fp32 in place) then split + transpose
    rope_k_kernel<<<(BB * SS + 255) / 256, 256>>>(ckv, pos);
    launch_split(ckv, ckv_h, ckv_l, (long)BB * SS * QEXT);
    {
        dim3 grid(SS / 32, KVLORA_ / 32, BB);
        transpose_ckv_kernel<<<grid, dim3(32, 8)>>>(ckv, ckvT_h, ckvT_l);
    }
    // 6. RoPE q -> qext pair cols 512:576
    rope_q_kernel<<<(BB * SS * NHH + 255) / 256, 256>>>(q_h, q_l, pos, qext_h, qext_l);
    // 7. qext[:,0:512] = q_nope @ q_absorb (pair out)
    launch_mma(q_h, q_l, wabsT_h, wabsT_l, 0, qext_h, qext_l,
               SS, KVLORA_, NOPE_, NHH * QHD, NOPE_, QEXT,
               (long)SS * NHH * QHD, (long)QHD,
               0, (long)KVLORA_ * NOPE_,
               (long)NHH * SS * QEXT, (long)SS * QEXT,
               NHH, BB * NHH, 1.f, 0, 0, 1);
    // 8. scores = scale * qext @ ckv^T (fp32 out, causal skip)
    launch_mma(qext_h, qext_l, ckv_h, ckv_l, scores, 0, 0,
               SS, SS, QEXT, QEXT, QEXT, SS,
               (long)NHH * SS * QEXT, (long)SS * QEXT,
               (long)SS * QEXT, 0,
               (long)NHH * SS * SS, (long)SS * SS,
               NHH, BB * NHH, scale, 1, 0, 0);
    // 9. softmax -> scores pair
    softmax_kernel<<<BB * NHH * SS, 256>>>(scores, sc_h, sc_l);
    // 10. out1 = attn @ ckv (via ckvT pair, causal K-limit, pair out)
    launch_mma(sc_h, sc_l, ckvT_h, ckvT_l, 0, out1_h, out1_l,
               SS, KVLORA_, SS, SS, SS, KVLORA_,
               (long)NHH * SS * SS, (long)SS * SS,
               (long)KVLORA_ * SS, 0,
               (long)NHH * SS * KVLORA_, (long)SS * KVLORA_,
               NHH, BB * NHH, 1.f, 0, 1, 1);
    // 11. out2 = out1 @ out_absorb^T (pair out)
    launch_mma(out1_h, out1_l, wkvup_h + (long)NOPE_ * KVLORA_, wkvup_l + (long)NOPE_ * KVLORA_,
               0, out2_h, out2_l,
               SS, VD_, KVLORA_, KVLORA_, KVLORA_, NHH * VD_,
               (long)NHH * SS * KVLORA_, (long)SS * KVLORA_,
               0, (long)256 * KVLORA_,
               (long)SS * NHH * VD_, (long)VD_,
               NHH, BB * NHH, 1.f, 0, 0, 1);
    // 12. final = out2 @ Wo^T [4096,2048] fp32 out
    launch_mma(out2_h, out2_l, wo_h, wo_l, out, 0, 0,
               M, HDIM, NHH * VD_, NHH * VD_, NHH * VD_, HDIM,
               0,0,0,0,0,0, 1, 1, 1.f, 0, 0, 0);
}

// round 6
// speedup vs baseline: 3.0689x; 1.2264x over previous
#include <cuda_runtime.h>
#include <cuda_fp16.h>
#include <math.h>
#include <stdint.h>

typedef unsigned short U16;

// ---------------- problem constants ----------------
#define NHH   16
#define NOPE_ 128
#define ROPED 64
#define VD_   128
#define QLORA_ 1536
#define KVLORA_ 512
#define HDIM  2048
#define BB    2
#define SS    2048
#define QEXT  576
#define QHD   (NOPE_ + ROPED)  // 192

// ---------------- scratch ----------------
__device__ float g_ql    [(long)BB*SS*QLORA_];
__device__ float g_ckv   [(long)BB*SS*QEXT];
__device__ float g_scores[(long)BB*NHH*SS*SS];

__device__ U16 g_hs_h [(long)BB*SS*HDIM],      g_hs_l [(long)BB*SS*HDIM];
__device__ U16 g_wqd_h[(long)QLORA_*HDIM],     g_wqd_l[(long)QLORA_*HDIM];
__device__ U16 g_wqu_h[(long)NHH*QHD*QLORA_],  g_wqu_l[(long)NHH*QHD*QLORA_];
__device__ U16 g_wo_h [(long)HDIM*HDIM],       g_wo_l [(long)HDIM*HDIM];
__device__ U16 g_wkvd_h[(long)640*HDIM],       g_wkvd_l[(long)640*HDIM];   // padded 576->640
__device__ U16 g_wkvup_h[(long)NHH*256*KVLORA_], g_wkvup_l[(long)NHH*256*KVLORA_];
__device__ U16 g_wabsT_h[(long)NHH*KVLORA_*NOPE_], g_wabsT_l[(long)NHH*KVLORA_*NOPE_];
__device__ U16 g_ql_h [(long)BB*SS*QLORA_],    g_ql_l [(long)BB*SS*QLORA_];
__device__ U16 g_q_h  [(long)BB*SS*NHH*QHD],   g_q_l  [(long)BB*SS*NHH*QHD];
__device__ U16 g_ckv_h[(long)BB*SS*QEXT],      g_ckv_l[(long)BB*SS*QEXT];
__device__ U16 g_ckvT_h[(long)BB*KVLORA_*SS],  g_ckvT_l[(long)BB*KVLORA_*SS];
__device__ U16 g_qext_s[(long)BB*NHH*SS*QEXT];            // single fp16
__device__ U16 g_sc_s  [(long)BB*NHH*SS*SS];              // probs single fp16
__device__ U16 g_out1_h[(long)BB*NHH*SS*KVLORA_], g_out1_l[(long)BB*NHH*SS*KVLORA_];
__device__ U16 g_out2_h[(long)BB*SS*NHH*VD_],  g_out2_l[(long)BB*SS*NHH*VD_];

// ================= helpers =================
__device__ __forceinline__ uint32_t smem_u32(const void* p) {
    uint32_t a;
    asm("{ .reg .u64 t; cvta.to.shared.u64 t, %1; cvt.u32.u64 %0, t; }" : "=r"(a) : "l"(p));
    return a;
}
__device__ __forceinline__ void cp16(uint32_t dst, const void* src) {
    asm volatile("cp.async.cg.shared.global [%0], [%1], 16;" :: "r"(dst), "l"(src));
}
#define CP_COMMIT() asm volatile("cp.async.commit_group;" ::: "memory")
#define CP_WAIT1()  asm volatile("cp.async.wait_group 1;" ::: "memory")

__device__ __forceinline__ void ldmx4(uint32_t* r, uint32_t addr) {
    asm volatile("ldmatrix.sync.aligned.m8n8.x4.shared.b16 {%0,%1,%2,%3}, [%4];"
                 : "=r"(r[0]), "=r"(r[1]), "=r"(r[2]), "=r"(r[3]) : "r"(addr));
}
__device__ __forceinline__ void mma16816(float* d, const uint32_t* a, const uint32_t* b) {
    asm volatile("mma.sync.aligned.m16n8k16.row.col.f32.f16.f16.f32 "
                 "{%0,%1,%2,%3}, {%4,%5,%6,%7}, {%8,%9}, {%0,%1,%2,%3};"
                 : "+f"(d[0]), "+f"(d[1]), "+f"(d[2]), "+f"(d[3])
                 : "r"(a[0]), "r"(a[1]), "r"(a[2]), "r"(a[3]), "r"(b[0]), "r"(b[1]));
}
__device__ __forceinline__ void split1h(float v, U16& h, U16& l) {
    __half hb = __float2half_rn(v);
    __half lb = __float2half_rn(v - __half2float(hb));
    h = __half_as_ushort(hb);
    l = __half_as_ushort(lb);
}
__device__ __forceinline__ U16 tohalf(float v) {
    return __half_as_ushort(__float2half_rn(v));
}

// ================= fp16-pair warp-MMA GEMM =================
// C = alpha * A @ B^T.  Row-major, elem ld.
// ASINGLE=0: A pair + B pair, 3 mma/k16.  ASINGLE=1: A single + B pair, 2 mma/k16.
// Block 128x128, BK=32, 3-stage cp.async pipeline, 8 warps (2x4).
// outMode: 0 = fp32 C; 1 = pair (Co,Clo); 2 = single fp16 (Co).
#define ROWB 80
#define TILEB (128 * ROWB)     // 10240

extern __shared__ char dsmem[];

template<int ASINGLE>
__global__ void __launch_bounds__(256)
mma_gemm(const U16* __restrict__ Ah, const U16* __restrict__ Al,
         const U16* __restrict__ Bh, const U16* __restrict__ Bl,
         float* __restrict__ C, U16* __restrict__ Co, U16* __restrict__ Clo,
         int K, int lda, int ldb, int ldc, int ncols,
         long sAb, long sAhh, long sBb, long sBhh, long sCb, long sChh,
         int zh, float alpha, int causalSkip, int causalK, int outMode)
{
    constexpr int NTILES = ASINGLE ? 3 : 4;
    constexpr int SGB = NTILES * TILEB;

    int z = blockIdx.z;
    long ao = (long)(z / zh) * sAb + (long)(z % zh) * sAhh;
    long bo = (long)(z / zh) * sBb + (long)(z % zh) * sBhh;
    long co = (long)(z / zh) * sCb + (long)(z % zh) * sChh;
    int by = blockIdx.y, bx = blockIdx.x;
    if (causalSkip && bx * 128 > by * 128 + 127) return;
    int Klim = causalK ? min(K, by * 128 + 128) : K;
    int nCh = Klim >> 5;

    int tid = threadIdx.x;
    int lane = tid & 31, wid = tid >> 5;
    int wm = wid & 1, wn = wid >> 1;

    uint32_t sb = smem_u32(dsmem);

    const U16* gAh = Ah + ao + (long)(by * 128) * lda;
    const U16* gAl = ASINGLE ? gAh : (Al + ao + (long)(by * 128) * lda);
    const U16* gBh = Bh + bo + (long)(bx * 128) * ldb;
    const U16* gBl = Bl + bo + (long)(bx * 128) * ldb;

    uint32_t aoff[4][2], boff[2][2];
    {
        int ar = wm * 64 + (lane & 15);
        int ak = (lane >> 4) << 3;
        #pragma unroll
        for (int mt = 0; mt < 4; mt++)
            #pragma unroll
            for (int kh = 0; kh < 2; kh++)
                aoff[mt][kh] = (uint32_t)((ar + mt * 16) * ROWB + ((ak + kh * 16) << 1));
        int br = wn * 32 + (lane & 7) + ((lane & 16) ? 8 : 0);
        int bk = (lane & 8) ? 8 : 0;
        #pragma unroll
        for (int np = 0; np < 2; np++)
            #pragma unroll
            for (int kh = 0; kh < 2; kh++)
                boff[np][kh] = (uint32_t)((br + np * 16) * ROWB + ((bk + kh * 16) << 1));
    }

    float acc[4][4][4];
    #pragma unroll
    for (int mt = 0; mt < 4; mt++)
        #pragma unroll
        for (int nt = 0; nt < 4; nt++)
            #pragma unroll
            for (int r = 0; r < 4; r++) acc[mt][nt][r] = 0.f;

    auto issue = [&](uint32_t sbase, int k0) {
        #pragma unroll
        for (int half = 0; half < 2; half++) {
            int idx = (half << 8) + tid;
            int row = idx >> 2;
            int e0  = (idx & 3) << 3;
            long aof = (long)row * lda + k0 + e0;
            long bof = (long)row * ldb + k0 + e0;
            uint32_t d = sbase + (uint32_t)(row * ROWB + (e0 << 1));
            cp16(d, gAh + aof);
            if (!ASINGLE) cp16(d + TILEB, gAl + aof);
            cp16(d + (ASINGLE ? 1 : 2) * TILEB, gBh + bof);
            cp16(d + (ASINGLE ? 2 : 3) * TILEB, gBl + bof);
        }
    };

    issue(sb, 0);
    CP_COMMIT();
    if (nCh > 1) issue(sb + SGB, 32);
    CP_COMMIT();

    int sc = 0;
    for (int c = 0; c < nCh; c++) {
        CP_WAIT1();
        __syncthreads();
        if (c + 2 < nCh) {
            int sn = sc + 2; if (sn >= 3) sn -= 3;
            issue(sb + sn * SGB, (c + 2) << 5);
        }
        CP_COMMIT();

        uint32_t bufb = sb + sc * SGB;
        uint32_t sA_  = bufb;
        uint32_t sAl_ = bufb + TILEB;
        uint32_t sBh_ = bufb + (ASINGLE ? 1 : 2) * TILEB;
        uint32_t sBl_ = bufb + (ASINGLE ? 2 : 3) * TILEB;

        #pragma unroll
        for (int kh = 0; kh < 2; kh++) {
            uint32_t ah[4][4], al[4][4], bh[2][4], bl[2][4];
            #pragma unroll
            for (int mt = 0; mt < 4; mt++) {
                ldmx4(ah[mt], sA_ + aoff[mt][kh]);
                if (!ASINGLE) ldmx4(al[mt], sAl_ + aoff[mt][kh]);
            }
            #pragma unroll
            for (int np = 0; np < 2; np++) {
                ldmx4(bh[np], sBh_ + boff[np][kh]);
                ldmx4(bl[np], sBl_ + boff[np][kh]);
            }
            #pragma unroll
            for (int mt = 0; mt < 4; mt++) {
                #pragma unroll
                for (int nt = 0; nt < 4; nt++) {
                    const uint32_t* bhp = &bh[nt >> 1][(nt & 1) << 1];
                    const uint32_t* blp = &bl[nt >> 1][(nt & 1) << 1];
                    mma16816(acc[mt][nt], ah[mt], bhp);
                    mma16816(acc[mt][nt], ah[mt], blp);
                    if (!ASINGLE) mma16816(acc[mt][nt], al[mt], bhp);
                }
            }
        }
        __syncthreads();
        if (++sc == 3) sc = 0;
    }

    // epilogue
    #pragma unroll
    for (int mt = 0; mt < 4; mt++) {
        int r0 = by * 128 + wm * 64 + mt * 16 + (lane >> 2);
        #pragma unroll
        for (int nt = 0; nt < 4; nt++) {
            int c0 = bx * 128 + wn * 32 + nt * 8 + ((lane & 3) << 1);
            if (c0 >= ncols) continue;
            float v00 = alpha * acc[mt][nt][0], v01 = alpha * acc[mt][nt][1];
            float v10 = alpha * acc[mt][nt][2], v11 = alpha * acc[mt][nt][3];
            if (outMode == 0) {
                *(float2*)(C + co + (long)r0 * ldc + c0) = make_float2(v00, v01);
                *(float2*)(C + co + (long)(r0 + 8) * ldc + c0) = make_float2(v10, v11);
            } else if (outMode == 1) {
                U16 h0, l0, h1, l1;
                split1h(v00, h0, l0); split1h(v01, h1, l1);
                *(uint32_t*)(Co  + co + (long)r0 * ldc + c0) = (uint32_t)h0 | ((uint32_t)h1 << 16);
                *(uint32_t*)(Clo + co + (long)r0 * ldc + c0) = (uint32_t)l0 | ((uint32_t)l1 << 16);
                split1h(v10, h0, l0); split1h(v11, h1, l1);
                *(uint32_t*)(Co  + co + (long)(r0 + 8) * ldc + c0) = (uint32_t)h0 | ((uint32_t)h1 << 16);
                *(uint32_t*)(Clo + co + (long)(r0 + 8) * ldc + c0) = (uint32_t)l0 | ((uint32_t)l1 << 16);
            } else {
                *(uint32_t*)(Co + co + (long)r0 * ldc + c0) =
                    (uint32_t)tohalf(v00) | ((uint32_t)tohalf(v01) << 16);
                *(uint32_t*)(Co + co + (long)(r0 + 8) * ldc + c0) =
                    (uint32_t)tohalf(v10) | ((uint32_t)tohalf(v11) << 16);
            }
        }
    }
}

// ---------------- split fp32 -> fp16 hi/lo ----------------
__global__ void split_kernel(const float* __restrict__ src,
                             U16* __restrict__ hi, U16* __restrict__ lo, long n)
{
    long i = ((long)blockIdx.x * 256 + threadIdx.x) * 4;
    if (i >= n) return;
    float4 v = *(const float4*)(src + i);
    U16 h[4], l[4];
    split1h(v.x, h[0], l[0]); split1h(v.y, h[1], l[1]);
    split1h(v.z, h[2], l[2]); split1h(v.w, h[3], l[3]);
    uint2 hv, lv;
    hv.x = (uint32_t)h[0] | ((uint32_t)h[1] << 16); hv.y = (uint32_t)h[2] | ((uint32_t)h[3] << 16);
    lv.x = (uint32_t)l[0] | ((uint32_t)l[1] << 16); lv.y = (uint32_t)l[2] | ((uint32_t)l[3] << 16);
    *(uint2*)(hi + i) = hv;
    *(uint2*)(lo + i) = lv;
}

// ---------------- RMSNorm (fp32 in, pair out) ----------------
__global__ void rmsnorm_kernel(const float* __restrict__ ql, const float* __restrict__ w,
                               U16* __restrict__ oh, U16* __restrict__ ol)
{
    const float* row = ql + (long)blockIdx.x * QLORA_;
    long ob = (long)blockIdx.x * QLORA_;
    int tid = threadIdx.x;
    float s = 0.f;
    for (int i = tid; i < QLORA_; i += 256) { float v = row[i]; s += v * v; }
    __shared__ float red[256];
    red[tid] = s; __syncthreads();
    for (int st = 128; st > 0; st >>= 1) { if (tid < st) red[tid] += red[tid + st]; __syncthreads(); }
    float scale = rsqrtf(red[0] / (float)QLORA_ + 1e-6f);
    for (int i = tid; i < QLORA_; i += 256) {
        float v = w[i] * (row[i] * scale);
        U16 h, l; split1h(v, h, l);
        oh[ob + i] = h; ol[ob + i] = l;
    }
}

// ---------------- RoPE ----------------
__device__ __forceinline__ void rope_pair(float p, int i, float x0, float x1,
                                          float& o_lo, float& o_hi)
{
    double inv = exp(-((double)(2 * i) / 64.0) * 13.815510557964274);
    double ang = (double)p * inv;
    double sd, cd; sincos(ang, &sd, &cd);
    float cc = (float)cd, ss = (float)sd;
    o_lo = x0 * cc - x1 * ss;
    o_hi = x1 * cc + x0 * ss;
}

__global__ void rope_q_kernel(const U16* __restrict__ qh, const U16* __restrict__ qlo,
                              const int* __restrict__ pos, U16* __restrict__ es)
{
    int idx = blockIdx.x * blockDim.x + threadIdx.x;
    if (idx >= BB * SS * NHH) return;
    int h = idx % NHH;
    int bs = idx / NHH;
    int b = bs / SS, s_idx = bs % SS;
    float p = (float)pos[bs];
    long xb = ((long)bs * NHH + h) * QHD + NOPE_;
    long ob = ((long)(b * NHH + h) * SS + s_idx) * QEXT + KVLORA_;
    for (int i = 0; i < 32; i++) {
        float x0 = __half2float(__ushort_as_half(qh[xb + 2 * i]))
                 + __half2float(__ushort_as_half(qlo[xb + 2 * i]));
        float x1 = __half2float(__ushort_as_half(qh[xb + 2 * i + 1]))
                 + __half2float(__ushort_as_half(qlo[xb + 2 * i + 1]));
        float lo, hi;
        rope_pair(p, i, x0, x1, lo, hi);
        es[ob + i] = tohalf(lo);
        es[ob + 32 + i] = tohalf(hi);
    }
}

__global__ void rope_k_kernel(float* __restrict__ ckv, const int* __restrict__ pos)
{
    int bs = blockIdx.x * blockDim.x + threadIdx.x;
    if (bs >= BB * SS) return;
    float p = (float)pos[bs];
    float* x = ckv + (long)bs * QEXT + KVLORA_;
    float tmp[64];
    for (int i = 0; i < 32; i++)
        rope_pair(p, i, x[2 * i], x[2 * i + 1], tmp[i], tmp[32 + i]);
    for (int j = 0; j < 64; j++) x[j] = tmp[j];
}

// ---------------- transposes (pair out) ----------------
__global__ void transpose_wabs_kernel(const float* __restrict__ Wkv_up,
                                      U16* __restrict__ oh, U16* __restrict__ ol)
{
    int idx = blockIdx.x * blockDim.x + threadIdx.x;
    if (idx >= NHH * KVLORA_ * NOPE_) return;
    int n = idx % NOPE_;
    int r = idx / NOPE_;
    int c = r % KVLORA_;
    int h = r / KVLORA_;
    float v = Wkv_up[((long)h * 256 + n) * KVLORA_ + c];
    U16 a, b; split1h(v, a, b);
    oh[idx] = a; ol[idx] = b;
}

__global__ void transpose_ckv_kernel(const float* __restrict__ ckv,
                                     U16* __restrict__ oh, U16* __restrict__ ol)
{
    __shared__ float t[32][33];
    int b = blockIdx.z;
    int s0 = blockIdx.x * 32, c0 = blockIdx.y * 32;
    int x = threadIdx.x, y = threadIdx.y;
    for (int i = y; i < 32; i += 8)
        t[i][x] = ckv[((long)b * SS + s0 + i) * QEXT + c0 + x];
    __syncthreads();
    for (int i = y; i < 32; i += 8) {
        long o = ((long)b * KVLORA_ + c0 + i) * SS + s0 + x;
        U16 hh, ll; split1h(t[x][i], hh, ll);
        oh[o] = hh; ol[o] = ll;
    }
}

// ---------------- causal softmax (fp32 in, single fp16 out) ----------------
__global__ void softmax_kernel(const float* __restrict__ scores, U16* __restrict__ os)
{
    long row = blockIdx.x;
    int q = (int)(row % SS);
    const float* r = scores + row * (long)SS;
    long ob = row * (long)SS;
    int tid = threadIdx.x;
    int n = q + 1;
    __shared__ float red[256];

    float mx = -1e30f;
    for (int k = tid; k < n; k += 256) mx = fmaxf(mx, r[k]);
    red[tid] = mx; __syncthreads();
    for (int st = 128; st > 0; st >>= 1) { if (tid < st) red[tid] = fmaxf(red[tid], red[tid + st]); __syncthreads(); }
    mx = red[0]; __syncthreads();

    float sum = 0.f;
    __shared__ float es[2048];
    for (int k = tid; k < n; k += 256) { float e = __expf(r[k] - mx); es[k] = e; sum += e; }
    red[tid] = sum; __syncthreads();
    for (int st = 128; st > 0; st >>= 1) { if (tid < st) red[tid] += red[tid + st]; __syncthreads(); }
    float inv = 1.f / red[0];

    for (int k = tid; k < n; k += 256) os[ob + k] = tohalf(es[k] * inv);
    for (int k = n + tid; k < SS; k += 256) os[ob + k] = 0;
}

// ---------------- host ----------------
static void launch_mma_p(const U16* Ah, const U16* Al, const U16* Bh, const U16* Bl,
                         float* C, U16* Co, U16* Clo,
                         int M, int Npad, int K, int lda, int ldb, int ldc, int ncols,
                         long sAb, long sAh, long sBb, long sBh, long sCb, long sCh,
                         int zh, int zcount, float alpha, int cSkip, int cK, int outMode)
{
    cudaFuncSetAttribute(mma_gemm<0>, cudaFuncAttributeMaxDynamicSharedMemorySize, 3 * 4 * TILEB);
    dim3 grid(Npad / 128, M / 128, zcount);
    mma_gemm<0><<<grid, 256, 3 * 4 * TILEB>>>(Ah, Al, Bh, Bl, C, Co, Clo,
        K, lda, ldb, ldc, ncols, sAb, sAh, sBb, sBh, sCb, sCh, zh, alpha, cSkip, cK, outMode);
}

static void launch_mma_s(const U16* As, const U16* Bh, const U16* Bl,
                         float* C, U16* Co, U16* Clo,
                         int M, int N, int K, int lda, int ldb, int ldc,
                         long sAb, long sAh, long sBb, long sBh, long sCb, long sCh,
                         int zh, int zcount, float alpha, int cSkip, int cK, int outMode)
{
    cudaFuncSetAttribute(mma_gemm<1>, cudaFuncAttributeMaxDynamicSharedMemorySize, 3 * 3 * TILEB);
    dim3 grid(N / 128, M / 128, zcount);
    mma_gemm<1><<<grid, 256, 3 * 3 * TILEB>>>(As, As, Bh, Bl, C, Co, Clo,
        K, lda, ldb, ldc, N, sAb, sAh, sBb, sBh, sCb, sCh, zh, alpha, cSkip, cK, outMode);
}

static void launch_split(const float* s, U16* h, U16* l, long n)
{
    split_kernel<<<(unsigned)((n / 4 + 255) / 256), 256>>>(s, h, l, n);
}

extern "C" void kernel_launch(void* const* d_in, const int* in_sizes, int n_in,
                              void* d_out, int out_size)
{
    const float* hs      = (const float*)d_in[0];
    const int*   pos     = (const int*)  d_in[1];
    const float* Wq_down = (const float*)d_in[3];
    const float* q_ln_w  = (const float*)d_in[4];
    const float* Wq_up   = (const float*)d_in[5];
    const float* Wkv_down= (const float*)d_in[6];
    const float* Wkv_up  = (const float*)d_in[7];
    const float* Wo      = (const float*)d_in[8];
    float* out = (float*)d_out;

    float *ql, *ckv, *scores;
    cudaGetSymbolAddress((void**)&ql, g_ql);
    cudaGetSymbolAddress((void**)&ckv, g_ckv);
    cudaGetSymbolAddress((void**)&scores, g_scores);
    U16 *hs_h, *hs_l, *wqd_h, *wqd_l, *wqu_h, *wqu_l, *wo_h, *wo_l, *wkvd_h, *wkvd_l;
    U16 *wkvup_h, *wkvup_l, *wabsT_h, *wabsT_l, *ql_h, *ql_l, *q_h, *q_l;
    U16 *ckv_h, *ckv_l, *ckvT_h, *ckvT_l, *qext_s, *sc_s;
    U16 *out1_h, *out1_l, *out2_h, *out2_l;
    cudaGetSymbolAddress((void**)&hs_h, g_hs_h);     cudaGetSymbolAddress((void**)&hs_l, g_hs_l);
    cudaGetSymbolAddress((void**)&wqd_h, g_wqd_h);   cudaGetSymbolAddress((void**)&wqd_l, g_wqd_l);
    cudaGetSymbolAddress((void**)&wqu_h, g_wqu_h);   cudaGetSymbolAddress((void**)&wqu_l, g_wqu_l);
    cudaGetSymbolAddress((void**)&wo_h, g_wo_h);     cudaGetSymbolAddress((void**)&wo_l, g_wo_l);
    cudaGetSymbolAddress((void**)&wkvd_h, g_wkvd_h); cudaGetSymbolAddress((void**)&wkvd_l, g_wkvd_l);
    cudaGetSymbolAddress((void**)&wkvup_h, g_wkvup_h); cudaGetSymbolAddress((void**)&wkvup_l, g_wkvup_l);
    cudaGetSymbolAddress((void**)&wabsT_h, g_wabsT_h); cudaGetSymbolAddress((void**)&wabsT_l, g_wabsT_l);
    cudaGetSymbolAddress((void**)&ql_h, g_ql_h);     cudaGetSymbolAddress((void**)&ql_l, g_ql_l);
    cudaGetSymbolAddress((void**)&q_h, g_q_h);       cudaGetSymbolAddress((void**)&q_l, g_q_l);
    cudaGetSymbolAddress((void**)&ckv_h, g_ckv_h);   cudaGetSymbolAddress((void**)&ckv_l, g_ckv_l);
    cudaGetSymbolAddress((void**)&ckvT_h, g_ckvT_h); cudaGetSymbolAddress((void**)&ckvT_l, g_ckvT_l);
    cudaGetSymbolAddress((void**)&qext_s, g_qext_s);
    cudaGetSymbolAddress((void**)&sc_s, g_sc_s);
    cudaGetSymbolAddress((void**)&out1_h, g_out1_h); cudaGetSymbolAddress((void**)&out1_l, g_out1_l);
    cudaGetSymbolAddress((void**)&out2_h, g_out2_h); cudaGetSymbolAddress((void**)&out2_l, g_out2_l);

    const int M = BB * SS;
    const float scale = 1.0f / sqrtf((float)QHD);

    // input/weight splits (pad rows of wkvd beyond 576 are never read usefully:
    // they only feed output cols >= 576 which are predicated off; globals are zero anyway)
    launch_split(hs, hs_h, hs_l, (long)BB * SS * HDIM);
    launch_split(Wq_down, wqd_h, wqd_l, (long)QLORA_ * HDIM);
    launch_split(Wq_up, wqu_h, wqu_l, (long)NHH * QHD * QLORA_);
    launch_split(Wo, wo_h, wo_l, (long)HDIM * HDIM);
    launch_split(Wkv_down, wkvd_h, wkvd_l, (long)QEXT * HDIM);
    launch_split(Wkv_up, wkvup_h, wkvup_l, (long)NHH * 256 * KVLORA_);
    transpose_wabs_kernel<<<(NHH * KVLORA_ * NOPE_ + 255) / 256, 256>>>(Wkv_up, wabsT_h, wabsT_l);

    // 1. ql = hs @ Wq_down^T [4096,1536] fp32
    launch_mma_p(hs_h, hs_l, wqd_h, wqd_l, ql, 0, 0,
                 M, QLORA_, HDIM, HDIM, HDIM, QLORA_, QLORA_,
                 0,0,0,0,0,0, 1, 1, 1.f, 0, 0, 0);
    // 2. RMSNorm -> ql pair
    rmsnorm_kernel<<<M, 256>>>(ql, q_ln_w, ql_h, ql_l);
    // 3. q = ql @ Wq_up^T [4096,3072] pair out
    launch_mma_p(ql_h, ql_l, wqu_h, wqu_l, 0, q_h, q_l,
                 M, NHH * QHD, QLORA_, QLORA_, QLORA_, NHH * QHD, NHH * QHD,
                 0,0,0,0,0,0, 1, 1, 1.f, 0, 0, 1);
    // 4. ckv = hs @ Wkv_down^T [4096,576] via Npad=640, fp32 out
    launch_mma_p(hs_h, hs_l, wkvd_h, wkvd_l, ckv, 0, 0,
                 M, 640, HDIM, HDIM, HDIM, QEXT, QEXT,
                 0,0,0,0,0,0, 1, 1, 1.f, 0, 0, 0);
    // 5. RoPE k (fp32 in place), split + transpose
    rope_k_kernel<<<(BB * SS + 255) / 256, 256>>>(ckv, pos);
    launch_split(ckv, ckv_h, ckv_l, (long)BB * SS * QEXT);
    {
        dim3 grid(SS / 32, KVLORA_ / 32, BB);
        transpose_ckv_kernel<<<grid, dim3(32, 8)>>>(ckv, ckvT_h, ckvT_l);
    }
    // 6. RoPE q -> qext single cols 512:576
    rope_q_kernel<<<(BB * SS * NHH + 255) / 256, 256>>>(q_h, q_l, pos, qext_s);
    // 7. qext[:,0:512] = q_nope @ q_absorb (single fp16 out)
    launch_mma_p(q_h, q_l, wabsT_h, wabsT_l, 0, qext_s, 0,
                 SS, KVLORA_, NOPE_, NHH * QHD, NOPE_, QEXT, KVLORA_,
                 (long)SS * NHH * QHD, (long)QHD,
                 0, (long)KVLORA_ * NOPE_,
                 (long)NHH * SS * QEXT, (long)SS * QEXT,
                 NHH, BB * NHH, 1.f, 0, 0, 2);
    // 8. scores = scale * qext(single) @ ckv(pair)^T, fp32 out, causal skip
    launch_mma_s(qext_s, ckv_h, ckv_l, scores, 0, 0,
                 SS, SS, QEXT, QEXT, QEXT, SS,
                 (long)NHH * SS * QEXT, (long)SS * QEXT,
                 (long)SS * QEXT, 0,
                 (long)NHH * SS * SS, (long)SS * SS,
                 NHH, BB * NHH, scale, 1, 0, 0);
    // 9. softmax -> probs single fp16
    softmax_kernel<<<BB * NHH * SS, 256>>>(scores, sc_s);
    // 10. out1 = probs(single) @ ckvT(pair), causal K-limit, pair out
    launch_mma_s(sc_s, ckvT_h, ckvT_l, 0, out1_h, out1_l,
                 SS, KVLORA_, SS, SS, SS, KVLORA_,
                 (long)NHH * SS * SS, (long)SS * SS,
                 (long)KVLORA_ * SS, 0,
                 (long)NHH * SS * KVLORA_, (long)SS * KVLORA_,
                 NHH, BB * NHH, 1.f, 0, 1, 1);
    // 11. out2 = out1 @ out_absorb^T (pair out)
    launch_mma_p(out1_h, out1_l, wkvup_h + (long)NOPE_ * KVLORA_, wkvup_l + (long)NOPE_ * KVLORA_,
                 0, out2_h, out2_l,
                 SS, VD_, KVLORA_, KVLORA_, KVLORA_, NHH * VD_, NHH * VD_,
                 (long)NHH * SS * KVLORA_, (long)SS * KVLORA_,
                 0, (long)256 * KVLORA_,
                 (long)SS * NHH * VD_, (long)VD_,
                 NHH, BB * NHH, 1.f, 0, 0, 1);
    // 12. final = out2 @ Wo^T [4096,2048] fp32 out
    launch_mma_p(out2_h, out2_l, wo_h, wo_l, out, 0, 0,
                 M, HDIM, NHH * VD_, NHH * VD_, NHH * VD_, HDIM, HDIM,
                 0,0,0,0,0,0, 1, 1, 1.f, 0, 0, 0);
}

// round 7
// speedup vs baseline: 3.5260x; 1.1489x over previous
#include <cuda_runtime.h>
#include <cuda_fp16.h>
#include <math.h>
#include <stdint.h>

typedef unsigned short U16;

// ---------------- problem constants ----------------
#define NHH   16
#define NOPE_ 128
#define ROPED 64
#define VD_   128
#define QLORA_ 1536
#define KVLORA_ 512
#define HDIM  2048
#define BB    2
#define SS    2048
#define QEXT  576
#define QHD   (NOPE_ + ROPED)  // 192

// ---------------- scratch ----------------
__device__ float g_ql    [(long)BB*SS*QLORA_];
__device__ float g_ckv   [(long)BB*SS*QEXT];
__device__ float g_scores[(long)BB*NHH*SS*SS];

__device__ U16 g_hs_h [(long)BB*SS*HDIM],      g_hs_l [(long)BB*SS*HDIM];
__device__ U16 g_wqd_h[(long)QLORA_*HDIM],     g_wqd_l[(long)QLORA_*HDIM];
__device__ U16 g_wqu_h[(long)NHH*QHD*QLORA_],  g_wqu_l[(long)NHH*QHD*QLORA_];
__device__ U16 g_wo_h [(long)HDIM*HDIM],       g_wo_l [(long)HDIM*HDIM];
__device__ U16 g_wkvd_h[(long)640*HDIM],       g_wkvd_l[(long)640*HDIM];   // padded 576->640
__device__ U16 g_wkvup_h[(long)NHH*256*KVLORA_], g_wkvup_l[(long)NHH*256*KVLORA_];
__device__ U16 g_wabsT_h[(long)NHH*KVLORA_*NOPE_], g_wabsT_l[(long)NHH*KVLORA_*NOPE_];
__device__ U16 g_ql_h [(long)BB*SS*QLORA_],    g_ql_l [(long)BB*SS*QLORA_];
__device__ U16 g_q_h  [(long)BB*SS*NHH*QHD],   g_q_l  [(long)BB*SS*NHH*QHD];
__device__ U16 g_ckv_s[(long)BB*SS*QEXT];                 // single fp16
__device__ U16 g_ckvT_s[(long)BB*KVLORA_*SS];             // single fp16
__device__ U16 g_qext_s[(long)BB*NHH*SS*QEXT];            // single fp16
__device__ U16 g_sc_s  [(long)BB*NHH*SS*SS];              // probs single fp16
__device__ U16 g_out1_h[(long)BB*NHH*SS*KVLORA_], g_out1_l[(long)BB*NHH*SS*KVLORA_];
__device__ U16 g_out2_h[(long)BB*SS*NHH*VD_],  g_out2_l[(long)BB*SS*NHH*VD_];

// ================= helpers =================
__device__ __forceinline__ uint32_t smem_u32(const void* p) {
    uint32_t a;
    asm("{ .reg .u64 t; cvta.to.shared.u64 t, %1; cvt.u32.u64 %0, t; }" : "=r"(a) : "l"(p));
    return a;
}
__device__ __forceinline__ void cp16(uint32_t dst, const void* src) {
    asm volatile("cp.async.cg.shared.global [%0], [%1], 16;" :: "r"(dst), "l"(src));
}
#define CP_COMMIT() asm volatile("cp.async.commit_group;" ::: "memory")
#define CP_WAIT1()  asm volatile("cp.async.wait_group 1;" ::: "memory")

__device__ __forceinline__ void ldmx4(uint32_t* r, uint32_t addr) {
    asm volatile("ldmatrix.sync.aligned.m8n8.x4.shared.b16 {%0,%1,%2,%3}, [%4];"
                 : "=r"(r[0]), "=r"(r[1]), "=r"(r[2]), "=r"(r[3]) : "r"(addr));
}
__device__ __forceinline__ void mma16816(float* d, const uint32_t* a, const uint32_t* b) {
    asm volatile("mma.sync.aligned.m16n8k16.row.col.f32.f16.f16.f32 "
                 "{%0,%1,%2,%3}, {%4,%5,%6,%7}, {%8,%9}, {%0,%1,%2,%3};"
                 : "+f"(d[0]), "+f"(d[1]), "+f"(d[2]), "+f"(d[3])
                 : "r"(a[0]), "r"(a[1]), "r"(a[2]), "r"(a[3]), "r"(b[0]), "r"(b[1]));
}
__device__ __forceinline__ void split1h(float v, U16& h, U16& l) {
    __half hb = __float2half_rn(v);
    __half lb = __float2half_rn(v - __half2float(hb));
    h = __half_as_ushort(hb);
    l = __half_as_ushort(lb);
}
__device__ __forceinline__ U16 tohalf(float v) {
    return __half_as_ushort(__float2half_rn(v));
}

// ================= fp16 warp-MMA GEMM =================
// C = alpha * A @ B^T.  Row-major, elem ld.
// AS: A is single fp16 (else hi/lo pair). BS: same for B.
// mma per k16: 3 (pair,pair) / 2 (single,pair) / 1 (single,single)
// Block 128x128, BK=32, 3-stage cp.async pipeline, 8 warps (2x4).
// outMode: 0 = fp32 C; 1 = pair (Co,Clo); 2 = single fp16 (Co).
#define ROWB 80
#define TILEB (128 * ROWB)     // 10240

extern __shared__ char dsmem[];

template<int AS, int BS>
__global__ void __launch_bounds__(256)
mma_gemm(const U16* __restrict__ Ah, const U16* __restrict__ Al,
         const U16* __restrict__ Bh, const U16* __restrict__ Bl,
         float* __restrict__ C, U16* __restrict__ Co, U16* __restrict__ Clo,
         int K, int lda, int ldb, int ldc, int ncols,
         long sAb, long sAhh, long sBb, long sBhh, long sCb, long sChh,
         int zh, float alpha, int causalSkip, int causalK, int outMode)
{
    constexpr int ATILES = AS ? 1 : 2;
    constexpr int BTILES = BS ? 1 : 2;
    constexpr int SGB = (ATILES + BTILES) * TILEB;

    int z = blockIdx.z;
    long ao = (long)(z / zh) * sAb + (long)(z % zh) * sAhh;
    long bo = (long)(z / zh) * sBb + (long)(z % zh) * sBhh;
    long co = (long)(z / zh) * sCb + (long)(z % zh) * sChh;
    int by = blockIdx.y, bx = blockIdx.x;
    if (causalSkip && bx * 128 > by * 128 + 127) return;
    int Klim = causalK ? min(K, by * 128 + 128) : K;
    int nCh = Klim >> 5;

    int tid = threadIdx.x;
    int lane = tid & 31, wid = tid >> 5;
    int wm = wid & 1, wn = wid >> 1;

    uint32_t sb = smem_u32(dsmem);

    const U16* gAh = Ah + ao + (long)(by * 128) * lda;
    const U16* gAl = AS ? gAh : (Al + ao + (long)(by * 128) * lda);
    const U16* gBh = Bh + bo + (long)(bx * 128) * ldb;
    const U16* gBl = BS ? gBh : (Bl + bo + (long)(bx * 128) * ldb);

    uint32_t aoff[4][2], boff[2][2];
    {
        int ar = wm * 64 + (lane & 15);
        int ak = (lane >> 4) << 3;
        #pragma unroll
        for (int mt = 0; mt < 4; mt++)
            #pragma unroll
            for (int kh = 0; kh < 2; kh++)
                aoff[mt][kh] = (uint32_t)((ar + mt * 16) * ROWB + ((ak + kh * 16) << 1));
        int br = wn * 32 + (lane & 7) + ((lane & 16) ? 8 : 0);
        int bk = (lane & 8) ? 8 : 0;
        #pragma unroll
        for (int np = 0; np < 2; np++)
            #pragma unroll
            for (int kh = 0; kh < 2; kh++)
                boff[np][kh] = (uint32_t)((br + np * 16) * ROWB + ((bk + kh * 16) << 1));
    }

    float acc[4][4][4];
    #pragma unroll
    for (int mt = 0; mt < 4; mt++)
        #pragma unroll
        for (int nt = 0; nt < 4; nt++)
            #pragma unroll
            for (int r = 0; r < 4; r++) acc[mt][nt][r] = 0.f;

    auto issue = [&](uint32_t sbase, int k0) {
        #pragma unroll
        for (int half = 0; half < 2; half++) {
            int idx = (half << 8) + tid;
            int row = idx >> 2;
            int e0  = (idx & 3) << 3;
            long aof = (long)row * lda + k0 + e0;
            long bof = (long)row * ldb + k0 + e0;
            uint32_t d = sbase + (uint32_t)(row * ROWB + (e0 << 1));
            cp16(d, gAh + aof);
            if (!AS) cp16(d + TILEB, gAl + aof);
            cp16(d + ATILES * TILEB, gBh + bof);
            if (!BS) cp16(d + (ATILES + 1) * TILEB, gBl + bof);
        }
    };

    issue(sb, 0);
    CP_COMMIT();
    if (nCh > 1) issue(sb + SGB, 32);
    CP_COMMIT();

    int sc = 0;
    for (int c = 0; c < nCh; c++) {
        CP_WAIT1();
        __syncthreads();
        if (c + 2 < nCh) {
            int sn = sc + 2; if (sn >= 3) sn -= 3;
            issue(sb + sn * SGB, (c + 2) << 5);
        }
        CP_COMMIT();

        uint32_t bufb = sb + sc * SGB;
        uint32_t sA_  = bufb;
        uint32_t sAl_ = bufb + TILEB;
        uint32_t sBh_ = bufb + ATILES * TILEB;
        uint32_t sBl_ = bufb + (ATILES + 1) * TILEB;

        #pragma unroll
        for (int kh = 0; kh < 2; kh++) {
            uint32_t ah[4][4], al[4][4], bh[2][4], bl[2][4];
            #pragma unroll
            for (int mt = 0; mt < 4; mt++) {
                ldmx4(ah[mt], sA_ + aoff[mt][kh]);
                if (!AS) ldmx4(al[mt], sAl_ + aoff[mt][kh]);
            }
            #pragma unroll
            for (int np = 0; np < 2; np++) {
                ldmx4(bh[np], sBh_ + boff[np][kh]);
                if (!BS) ldmx4(bl[np], sBl_ + boff[np][kh]);
            }
            #pragma unroll
            for (int mt = 0; mt < 4; mt++) {
                #pragma unroll
                for (int nt = 0; nt < 4; nt++) {
                    const uint32_t* bhp = &bh[nt >> 1][(nt & 1) << 1];
                    const uint32_t* blp = &bl[nt >> 1][(nt & 1) << 1];
                    mma16816(acc[mt][nt], ah[mt], bhp);
                    if (!BS) mma16816(acc[mt][nt], ah[mt], blp);
                    if (!AS) mma16816(acc[mt][nt], al[mt], bhp);
                }
            }
        }
        __syncthreads();
        if (++sc == 3) sc = 0;
    }

    // epilogue
    #pragma unroll
    for (int mt = 0; mt < 4; mt++) {
        int r0 = by * 128 + wm * 64 + mt * 16 + (lane >> 2);
        #pragma unroll
        for (int nt = 0; nt < 4; nt++) {
            int c0 = bx * 128 + wn * 32 + nt * 8 + ((lane & 3) << 1);
            if (c0 >= ncols) continue;
            float v00 = alpha * acc[mt][nt][0], v01 = alpha * acc[mt][nt][1];
            float v10 = alpha * acc[mt][nt][2], v11 = alpha * acc[mt][nt][3];
            if (outMode == 0) {
                *(float2*)(C + co + (long)r0 * ldc + c0) = make_float2(v00, v01);
                *(float2*)(C + co + (long)(r0 + 8) * ldc + c0) = make_float2(v10, v11);
            } else if (outMode == 1) {
                U16 h0, l0, h1, l1;
                split1h(v00, h0, l0); split1h(v01, h1, l1);
                *(uint32_t*)(Co  + co + (long)r0 * ldc + c0) = (uint32_t)h0 | ((uint32_t)h1 << 16);
                *(uint32_t*)(Clo + co + (long)r0 * ldc + c0) = (uint32_t)l0 | ((uint32_t)l1 << 16);
                split1h(v10, h0, l0); split1h(v11, h1, l1);
                *(uint32_t*)(Co  + co + (long)(r0 + 8) * ldc + c0) = (uint32_t)h0 | ((uint32_t)h1 << 16);
                *(uint32_t*)(Clo + co + (long)(r0 + 8) * ldc + c0) = (uint32_t)l0 | ((uint32_t)l1 << 16);
            } else {
                *(uint32_t*)(Co + co + (long)r0 * ldc + c0) =
                    (uint32_t)tohalf(v00) | ((uint32_t)tohalf(v01) << 16);
                *(uint32_t*)(Co + co + (long)(r0 + 8) * ldc + c0) =
                    (uint32_t)tohalf(v10) | ((uint32_t)tohalf(v11) << 16);
            }
        }
    }
}

// ---------------- split fp32 -> fp16 hi/lo ----------------
__global__ void split_kernel(const float* __restrict__ src,
                             U16* __restrict__ hi, U16* __restrict__ lo, long n)
{
    long i = ((long)blockIdx.x * 256 + threadIdx.x) * 4;
    if (i >= n) return;
    float4 v = *(const float4*)(src + i);
    U16 h[4], l[4];
    split1h(v.x, h[0], l[0]); split1h(v.y, h[1], l[1]);
    split1h(v.z, h[2], l[2]); split1h(v.w, h[3], l[3]);
    uint2 hv, lv;
    hv.x = (uint32_t)h[0] | ((uint32_t)h[1] << 16); hv.y = (uint32_t)h[2] | ((uint32_t)h[3] << 16);
    lv.x = (uint32_t)l[0] | ((uint32_t)l[1] << 16); lv.y = (uint32_t)l[2] | ((uint32_t)l[3] << 16);
    *(uint2*)(hi + i) = hv;
    *(uint2*)(lo + i) = lv;
}

// fp32 -> single fp16
__global__ void tosingle_kernel(const float* __restrict__ src, U16* __restrict__ o, long n)
{
    long i = ((long)blockIdx.x * 256 + threadIdx.x) * 4;
    if (i >= n) return;
    float4 v = *(const float4*)(src + i);
    uint2 ov;
    ov.x = (uint32_t)tohalf(v.x) | ((uint32_t)tohalf(v.y) << 16);
    ov.y = (uint32_t)tohalf(v.z) | ((uint32_t)tohalf(v.w) << 16);
    *(uint2*)(o + i) = ov;
}

// ---------------- RMSNorm (fp32 in, pair out) ----------------
__global__ void rmsnorm_kernel(const float* __restrict__ ql, const float* __restrict__ w,
                               U16* __restrict__ oh, U16* __restrict__ ol)
{
    const float* row = ql + (long)blockIdx.x * QLORA_;
    long ob = (long)blockIdx.x * QLORA_;
    int tid = threadIdx.x;
    float s = 0.f;
    for (int i = tid; i < QLORA_; i += 256) { float v = row[i]; s += v * v; }
    __shared__ float red[256];
    red[tid] = s; __syncthreads();
    for (int st = 128; st > 0; st >>= 1) { if (tid < st) red[tid] += red[tid + st]; __syncthreads(); }
    float scale = rsqrtf(red[0] / (float)QLORA_ + 1e-6f);
    for (int i = tid; i < QLORA_; i += 256) {
        float v = w[i] * (row[i] * scale);
        U16 h, l; split1h(v, h, l);
        oh[ob + i] = h; ol[ob + i] = l;
    }
}

// ---------------- RoPE ----------------
__device__ __forceinline__ void rope_pair(float p, int i, float x0, float x1,
                                          float& o_lo, float& o_hi)
{
    double inv = exp(-((double)(2 * i) / 64.0) * 13.815510557964274);
    double ang = (double)p * inv;
    double sd, cd; sincos(ang, &sd, &cd);
    float cc = (float)cd, ss = (float)sd;
    o_lo = x0 * cc - x1 * ss;
    o_hi = x1 * cc + x0 * ss;
}

__global__ void rope_q_kernel(const U16* __restrict__ qh, const U16* __restrict__ qlo,
                              const int* __restrict__ pos, U16* __restrict__ es)
{
    int idx = blockIdx.x * blockDim.x + threadIdx.x;
    if (idx >= BB * SS * NHH) return;
    int h = idx % NHH;
    int bs = idx / NHH;
    int b = bs / SS, s_idx = bs % SS;
    float p = (float)pos[bs];
    long xb = ((long)bs * NHH + h) * QHD + NOPE_;
    long ob = ((long)(b * NHH + h) * SS + s_idx) * QEXT + KVLORA_;
    for (int i = 0; i < 32; i++) {
        float x0 = __half2float(__ushort_as_half(qh[xb + 2 * i]))
                 + __half2float(__ushort_as_half(qlo[xb + 2 * i]));
        float x1 = __half2float(__ushort_as_half(qh[xb + 2 * i + 1]))
                 + __half2float(__ushort_as_half(qlo[xb + 2 * i + 1]));
        float lo, hi;
        rope_pair(p, i, x0, x1, lo, hi);
        es[ob + i] = tohalf(lo);
        es[ob + 32 + i] = tohalf(hi);
    }
}

__global__ void rope_k_kernel(float* __restrict__ ckv, const int* __restrict__ pos)
{
    int bs = blockIdx.x * blockDim.x + threadIdx.x;
    if (bs >= BB * SS) return;
    float p = (float)pos[bs];
    float* x = ckv + (long)bs * QEXT + KVLORA_;
    float tmp[64];
    for (int i = 0; i < 32; i++)
        rope_pair(p, i, x[2 * i], x[2 * i + 1], tmp[i], tmp[32 + i]);
    for (int j = 0; j < 64; j++) x[j] = tmp[j];
}

// ---------------- transposes ----------------
__global__ void transpose_wabs_kernel(const float* __restrict__ Wkv_up,
                                      U16* __restrict__ oh, U16* __restrict__ ol)
{
    int idx = blockIdx.x * blockDim.x + threadIdx.x;
    if (idx >= NHH * KVLORA_ * NOPE_) return;
    int n = idx % NOPE_;
    int r = idx / NOPE_;
    int c = r % KVLORA_;
    int h = r / KVLORA_;
    float v = Wkv_up[((long)h * 256 + n) * KVLORA_ + c];
    U16 a, b; split1h(v, a, b);
    oh[idx] = a; ol[idx] = b;
}

__global__ void transpose_ckv_kernel(const float* __restrict__ ckv, U16* __restrict__ os)
{
    __shared__ float t[32][33];
    int b = blockIdx.z;
    int s0 = blockIdx.x * 32, c0 = blockIdx.y * 32;
    int x = threadIdx.x, y = threadIdx.y;
    for (int i = y; i < 32; i += 8)
        t[i][x] = ckv[((long)b * SS + s0 + i) * QEXT + c0 + x];
    __syncthreads();
    for (int i = y; i < 32; i += 8) {
        long o = ((long)b * KVLORA_ + c0 + i) * SS + s0 + x;
        os[o] = tohalf(t[x][i]);
    }
}

// ---------------- causal softmax (fp32 in, single fp16 out) ----------------
__global__ void softmax_kernel(const float* __restrict__ scores, U16* __restrict__ os)
{
    long row = blockIdx.x;
    int q = (int)(row % SS);
    const float* r = scores + row * (long)SS;
    long ob = row * (long)SS;
    int tid = threadIdx.x;
    int n = q + 1;
    __shared__ float red[256];

    float mx = -1e30f;
    for (int k = tid; k < n; k += 256) mx = fmaxf(mx, r[k]);
    red[tid] = mx; __syncthreads();
    for (int st = 128; st > 0; st >>= 1) { if (tid < st) red[tid] = fmaxf(red[tid], red[tid + st]); __syncthreads(); }
    mx = red[0]; __syncthreads();

    float sum = 0.f;
    __shared__ float es[2048];
    for (int k = tid; k < n; k += 256) { float e = __expf(r[k] - mx); es[k] = e; sum += e; }
    red[tid] = sum; __syncthreads();
    for (int st = 128; st > 0; st >>= 1) { if (tid < st) red[tid] += red[tid + st]; __syncthreads(); }
    float inv = 1.f / red[0];

    for (int k = tid; k < n; k += 256) os[ob + k] = tohalf(es[k] * inv);
    for (int k = n + tid; k < SS; k += 256) os[ob + k] = 0;
}

// ---------------- host ----------------
template<int AS, int BS>
static void launch_mma(const U16* Ah, const U16* Al, const U16* Bh, const U16* Bl,
                       float* C, U16* Co, U16* Clo,
                       int M, int Npad, int K, int lda, int ldb, int ldc, int ncols,
                       long sAb, long sAh, long sBb, long sBh, long sCb, long sCh,
                       int zh, int zcount, float alpha, int cSkip, int cK, int outMode)
{
    constexpr int SMEM = 3 * ((AS ? 1 : 2) + (BS ? 1 : 2)) * TILEB;
    cudaFuncSetAttribute(mma_gemm<AS, BS>, cudaFuncAttributeMaxDynamicSharedMemorySize, SMEM);
    dim3 grid(Npad / 128, M / 128, zcount);
    mma_gemm<AS, BS><<<grid, 256, SMEM>>>(Ah, Al, Bh, Bl, C, Co, Clo,
        K, lda, ldb, ldc, ncols, sAb, sAh, sBb, sBh, sCb, sCh, zh, alpha, cSkip, cK, outMode);
}

static void launch_split(const float* s, U16* h, U16* l, long n)
{
    split_kernel<<<(unsigned)((n / 4 + 255) / 256), 256>>>(s, h, l, n);
}

extern "C" void kernel_launch(void* const* d_in, const int* in_sizes, int n_in,
                              void* d_out, int out_size)
{
    const float* hs      = (const float*)d_in[0];
    const int*   pos     = (const int*)  d_in[1];
    const float* Wq_down = (const float*)d_in[3];
    const float* q_ln_w  = (const float*)d_in[4];
    const float* Wq_up   = (const float*)d_in[5];
    const float* Wkv_down= (const float*)d_in[6];
    const float* Wkv_up  = (const float*)d_in[7];
    const float* Wo      = (const float*)d_in[8];
    float* out = (float*)d_out;

    float *ql, *ckv, *scores;
    cudaGetSymbolAddress((void**)&ql, g_ql);
    cudaGetSymbolAddress((void**)&ckv, g_ckv);
    cudaGetSymbolAddress((void**)&scores, g_scores);
    U16 *hs_h, *hs_l, *wqd_h, *wqd_l, *wqu_h, *wqu_l, *wo_h, *wo_l, *wkvd_h, *wkvd_l;
    U16 *wkvup_h, *wkvup_l, *wabsT_h, *wabsT_l, *ql_h, *ql_l, *q_h, *q_l;
    U16 *ckv_s, *ckvT_s, *qext_s, *sc_s;
    U16 *out1_h, *out1_l, *out2_h, *out2_l;
    cudaGetSymbolAddress((void**)&hs_h, g_hs_h);     cudaGetSymbolAddress((void**)&hs_l, g_hs_l);
    cudaGetSymbolAddress((void**)&wqd_h, g_wqd_h);   cudaGetSymbolAddress((void**)&wqd_l, g_wqd_l);
    cudaGetSymbolAddress((void**)&wqu_h, g_wqu_h);   cudaGetSymbolAddress((void**)&wqu_l, g_wqu_l);
    cudaGetSymbolAddress((void**)&wo_h, g_wo_h);     cudaGetSymbolAddress((void**)&wo_l, g_wo_l);
    cudaGetSymbolAddress((void**)&wkvd_h, g_wkvd_h); cudaGetSymbolAddress((void**)&wkvd_l, g_wkvd_l);
    cudaGetSymbolAddress((void**)&wkvup_h, g_wkvup_h); cudaGetSymbolAddress((void**)&wkvup_l, g_wkvup_l);
    cudaGetSymbolAddress((void**)&wabsT_h, g_wabsT_h); cudaGetSymbolAddress((void**)&wabsT_l, g_wabsT_l);
    cudaGetSymbolAddress((void**)&ql_h, g_ql_h);     cudaGetSymbolAddress((void**)&ql_l, g_ql_l);
    cudaGetSymbolAddress((void**)&q_h, g_q_h);       cudaGetSymbolAddress((void**)&q_l, g_q_l);
    cudaGetSymbolAddress((void**)&ckv_s, g_ckv_s);
    cudaGetSymbolAddress((void**)&ckvT_s, g_ckvT_s);
    cudaGetSymbolAddress((void**)&qext_s, g_qext_s);
    cudaGetSymbolAddress((void**)&sc_s, g_sc_s);
    cudaGetSymbolAddress((void**)&out1_h, g_out1_h); cudaGetSymbolAddress((void**)&out1_l, g_out1_l);
    cudaGetSymbolAddress((void**)&out2_h, g_out2_h); cudaGetSymbolAddress((void**)&out2_l, g_out2_l);

    const int M = BB * SS;
    const float scale = 1.0f / sqrtf((float)QHD);

    // input/weight splits
    launch_split(hs, hs_h, hs_l, (long)BB * SS * HDIM);
    launch_split(Wq_down, wqd_h, wqd_l, (long)QLORA_ * HDIM);
    launch_split(Wq_up, wqu_h, wqu_l, (long)NHH * QHD * QLORA_);
    launch_split(Wo, wo_h, wo_l, (long)HDIM * HDIM);
    launch_split(Wkv_down, wkvd_h, wkvd_l, (long)QEXT * HDIM);
    launch_split(Wkv_up, wkvup_h, wkvup_l, (long)NHH * 256 * KVLORA_);
    transpose_wabs_kernel<<<(NHH * KVLORA_ * NOPE_ + 255) / 256, 256>>>(Wkv_up, wabsT_h, wabsT_l);

    // 1. ql = hs @ Wq_down^T [4096,1536] fp32
    launch_mma<0,0>(hs_h, hs_l, wqd_h, wqd_l, ql, 0, 0,
                    M, QLORA_, HDIM, HDIM, HDIM, QLORA_, QLORA_,
                    0,0,0,0,0,0, 1, 1, 1.f, 0, 0, 0);
    // 2. RMSNorm -> ql pair
    rmsnorm_kernel<<<M, 256>>>(ql, q_ln_w, ql_h, ql_l);
    // 3. q = ql @ Wq_up^T [4096,3072] pair out
    launch_mma<0,0>(ql_h, ql_l, wqu_h, wqu_l, 0, q_h, q_l,
                    M, NHH * QHD, QLORA_, QLORA_, QLORA_, NHH * QHD, NHH * QHD,
                    0,0,0,0,0,0, 1, 1, 1.f, 0, 0, 1);
    // 4. ckv = hs @ Wkv_down^T [4096,576] via Npad=640, fp32 out
    launch_mma<0,0>(hs_h, hs_l, wkvd_h, wkvd_l, ckv, 0, 0,
                    M, 640, HDIM, HDIM, HDIM, QEXT, QEXT,
                    0,0,0,0,0,0, 1, 1, 1.f, 0, 0, 0);
    // 5. RoPE k (fp32 in place), single-convert + transpose
    rope_k_kernel<<<(BB * SS + 255) / 256, 256>>>(ckv, pos);
    tosingle_kernel<<<(unsigned)(((long)BB * SS * QEXT / 4 + 255) / 256), 256>>>(
        ckv, ckv_s, (long)BB * SS * QEXT);
    {
        dim3 grid(SS / 32, KVLORA_ / 32, BB);
        transpose_ckv_kernel<<<grid, dim3(32, 8)>>>(ckv, ckvT_s);
    }
    // 6. RoPE q -> qext single cols 512:576
    rope_q_kernel<<<(BB * SS * NHH + 255) / 256, 256>>>(q_h, q_l, pos, qext_s);
    // 7. qext[:,0:512] = q_nope @ q_absorb (single fp16 out)
    launch_mma<0,0>(q_h, q_l, wabsT_h, wabsT_l, 0, qext_s, 0,
                    SS, KVLORA_, NOPE_, NHH * QHD, NOPE_, QEXT, KVLORA_,
                    (long)SS * NHH * QHD, (long)QHD,
                    0, (long)KVLORA_ * NOPE_,
                    (long)NHH * SS * QEXT, (long)SS * QEXT,
                    NHH, BB * NHH, 1.f, 0, 0, 2);
    // 8. scores = scale * qext(single) @ ckv(single)^T, fp32 out, causal skip
    launch_mma<1,1>(qext_s, qext_s, ckv_s, ckv_s, scores, 0, 0,
                    SS, SS, QEXT, QEXT, QEXT, SS, SS,
                    (long)NHH * SS * QEXT, (long)SS * QEXT,
                    (long)SS * QEXT, 0,
                    (long)NHH * SS * SS, (long)SS * SS,
                    NHH, BB * NHH, scale, 1, 0, 0);
    // 9. softmax -> probs single fp16
    softmax_kernel<<<BB * NHH * SS, 256>>>(scores, sc_s);
    // 10. out1 = probs(single) @ ckvT(single), causal K-limit, pair out
    launch_mma<1,1>(sc_s, sc_s, ckvT_s, ckvT_s, 0, out1_h, out1_l,
                    SS, KVLORA_, SS, SS, SS, KVLORA_, KVLORA_,
                    (long)NHH * SS * SS, (long)SS * SS,
                    (long)KVLORA_ * SS, 0,
                    (long)NHH * SS * KVLORA_, (long)SS * KVLORA_,
                    NHH, BB * NHH, 1.f, 0, 1, 1);
    // 11. out2 = out1 @ out_absorb^T (pair out)
    launch_mma<0,0>(out1_h, out1_l, wkvup_h + (long)NOPE_ * KVLORA_, wkvup_l + (long)NOPE_ * KVLORA_,
                    0, out2_h, out2_l,
                    SS, VD_, KVLORA_, KVLORA_, KVLORA_, NHH * VD_, NHH * VD_,
                    (long)NHH * SS * KVLORA_, (long)SS * KVLORA_,
                    0, (long)256 * KVLORA_,
                    (long)SS * NHH * VD_, (long)VD_,
                    NHH, BB * NHH, 1.f, 0, 0, 1);
    // 12. final = out2 @ Wo^T [4096,2048] fp32 out
    launch_mma<0,0>(out2_h, out2_l, wo_h, wo_l, out, 0, 0,
                    M, HDIM, NHH * VD_, NHH * VD_, NHH * VD_, HDIM, HDIM,
                    0,0,0,0,0,0, 1, 1, 1.f, 0, 0, 0);
}

// round 8
// speedup vs baseline: 4.3231x; 1.2261x over previous
#include <cuda_runtime.h>
#include <cuda_fp16.h>
#include <math.h>
#include <stdint.h>

typedef unsigned short U16;

// ---------------- problem constants ----------------
#define NHH   16
#define NOPE_ 128
#define ROPED 64
#define VD_   128
#define QLORA_ 1536
#define KVLORA_ 512
#define HDIM  2048
#define BB    2
#define SS    2048
#define QEXT  576
#define QHD   (NOPE_ + ROPED)  // 192

// ---------------- scratch ----------------
__device__ float g_ql    [(long)BB*SS*QLORA_];
__device__ float g_ckv   [(long)BB*SS*QEXT];
__device__ float g_scores[(long)BB*NHH*SS*SS];

__device__ U16 g_hs_s [(long)BB*SS*HDIM];                  // single fp16
__device__ U16 g_wqd_h[(long)QLORA_*HDIM],     g_wqd_l[(long)QLORA_*HDIM];
__device__ U16 g_wqu_h[(long)NHH*QHD*QLORA_],  g_wqu_l[(long)NHH*QHD*QLORA_];
__device__ U16 g_wo_h [(long)HDIM*HDIM],       g_wo_l [(long)HDIM*HDIM];
__device__ U16 g_wkvd_h[(long)640*HDIM],       g_wkvd_l[(long)640*HDIM];   // padded 576->640
__device__ U16 g_wkvup_h[(long)NHH*256*KVLORA_], g_wkvup_l[(long)NHH*256*KVLORA_];
__device__ U16 g_wabsT_h[(long)NHH*KVLORA_*NOPE_], g_wabsT_l[(long)NHH*KVLORA_*NOPE_];
__device__ U16 g_ql_s [(long)BB*SS*QLORA_];                // single fp16 (post-rmsnorm)
__device__ U16 g_q_s  [(long)BB*SS*NHH*QHD];               // single fp16
__device__ U16 g_ckv_s[(long)BB*SS*QEXT];                  // single fp16
__device__ U16 g_ckvT_s[(long)BB*KVLORA_*SS];              // single fp16
__device__ U16 g_qext_s[(long)BB*NHH*SS*QEXT];             // single fp16
__device__ U16 g_sc_s  [(long)BB*NHH*SS*SS];               // probs single fp16
__device__ U16 g_out1_s[(long)BB*NHH*SS*KVLORA_];          // single fp16
__device__ U16 g_out2_s[(long)BB*SS*NHH*VD_];              // single fp16

// ================= helpers =================
__device__ __forceinline__ uint32_t smem_u32(const void* p) {
    uint32_t a;
    asm("{ .reg .u64 t; cvta.to.shared.u64 t, %1; cvt.u32.u64 %0, t; }" : "=r"(a) : "l"(p));
    return a;
}
__device__ __forceinline__ void cp16(uint32_t dst, const void* src) {
    asm volatile("cp.async.cg.shared.global [%0], [%1], 16;" :: "r"(dst), "l"(src));
}
#define CP_COMMIT() asm volatile("cp.async.commit_group;" ::: "memory")
#define CP_WAIT1()  asm volatile("cp.async.wait_group 1;" ::: "memory")

__device__ __forceinline__ void ldmx4(uint32_t* r, uint32_t addr) {
    asm volatile("ldmatrix.sync.aligned.m8n8.x4.shared.b16 {%0,%1,%2,%3}, [%4];"
                 : "=r"(r[0]), "=r"(r[1]), "=r"(r[2]), "=r"(r[3]) : "r"(addr));
}
__device__ __forceinline__ void mma16816(float* d, const uint32_t* a, const uint32_t* b) {
    asm volatile("mma.sync.aligned.m16n8k16.row.col.f32.f16.f16.f32 "
                 "{%0,%1,%2,%3}, {%4,%5,%6,%7}, {%8,%9}, {%0,%1,%2,%3};"
                 : "+f"(d[0]), "+f"(d[1]), "+f"(d[2]), "+f"(d[3])
                 : "r"(a[0]), "r"(a[1]), "r"(a[2]), "r"(a[3]), "r"(b[0]), "r"(b[1]));
}
__device__ __forceinline__ void split1h(float v, U16& h, U16& l) {
    __half hb = __float2half_rn(v);
    __half lb = __float2half_rn(v - __half2float(hb));
    h = __half_as_ushort(hb);
    l = __half_as_ushort(lb);
}
__device__ __forceinline__ U16 tohalf(float v) {
    return __half_as_ushort(__float2half_rn(v));
}

// ================= fp16 warp-MMA GEMM =================
// C = alpha * A @ B^T.  Row-major, elem ld.
// AS: A single fp16 (else hi/lo pair). BS: same for B.
// mma/k16: 3 (pair,pair), 2 (single,pair), 1 (single,single).
// Block 128x128, BK=32, 3-stage cp.async pipeline, 8 warps (2x4).
// outMode: 0 = fp32 C; 2 = single fp16 (Co).
#define ROWB 80
#define TILEB (128 * ROWB)     // 10240

extern __shared__ char dsmem[];

template<int AS, int BS>
__global__ void __launch_bounds__(256)
mma_gemm(const U16* __restrict__ Ah, const U16* __restrict__ Al,
         const U16* __restrict__ Bh, const U16* __restrict__ Bl,
         float* __restrict__ C, U16* __restrict__ Co,
         int K, int lda, int ldb, int ldc, int ncols,
         long sAb, long sAhh, long sBb, long sBhh, long sCb, long sChh,
         int zh, float alpha, int causalSkip, int causalK, int outMode)
{
    constexpr int ATILES = AS ? 1 : 2;
    constexpr int BTILES = BS ? 1 : 2;
    constexpr int SGB = (ATILES + BTILES) * TILEB;

    int z = blockIdx.z;
    long ao = (long)(z / zh) * sAb + (long)(z % zh) * sAhh;
    long bo = (long)(z / zh) * sBb + (long)(z % zh) * sBhh;
    long co = (long)(z / zh) * sCb + (long)(z % zh) * sChh;
    int by = blockIdx.y, bx = blockIdx.x;
    if (causalSkip && bx * 128 > by * 128 + 127) return;
    int Klim = causalK ? min(K, by * 128 + 128) : K;
    int nCh = Klim >> 5;

    int tid = threadIdx.x;
    int lane = tid & 31, wid = tid >> 5;
    int wm = wid & 1, wn = wid >> 1;

    uint32_t sb = smem_u32(dsmem);

    const U16* gAh = Ah + ao + (long)(by * 128) * lda;
    const U16* gAl = AS ? gAh : (Al + ao + (long)(by * 128) * lda);
    const U16* gBh = Bh + bo + (long)(bx * 128) * ldb;
    const U16* gBl = BS ? gBh : (Bl + bo + (long)(bx * 128) * ldb);

    uint32_t aoff[4][2], boff[2][2];
    {
        int ar = wm * 64 + (lane & 15);
        int ak = (lane >> 4) << 3;
        #pragma unroll
        for (int mt = 0; mt < 4; mt++)
            #pragma unroll
            for (int kh = 0; kh < 2; kh++)
                aoff[mt][kh] = (uint32_t)((ar + mt * 16) * ROWB + ((ak + kh * 16) << 1));
        int br = wn * 32 + (lane & 7) + ((lane & 16) ? 8 : 0);
        int bk = (lane & 8) ? 8 : 0;
        #pragma unroll
        for (int np = 0; np < 2; np++)
            #pragma unroll
            for (int kh = 0; kh < 2; kh++)
                boff[np][kh] = (uint32_t)((br + np * 16) * ROWB + ((bk + kh * 16) << 1));
    }

    float acc[4][4][4];
    #pragma unroll
    for (int mt = 0; mt < 4; mt++)
        #pragma unroll
        for (int nt = 0; nt < 4; nt++)
            #pragma unroll
            for (int r = 0; r < 4; r++) acc[mt][nt][r] = 0.f;

    auto issue = [&](uint32_t sbase, int k0) {
        #pragma unroll
        for (int half = 0; half < 2; half++) {
            int idx = (half << 8) + tid;
            int row = idx >> 2;
            int e0  = (idx & 3) << 3;
            long aof = (long)row * lda + k0 + e0;
            long bof = (long)row * ldb + k0 + e0;
            uint32_t d = sbase + (uint32_t)(row * ROWB + (e0 << 1));
            cp16(d, gAh + aof);
            if (!AS) cp16(d + TILEB, gAl + aof);
            cp16(d + ATILES * TILEB, gBh + bof);
            if (!BS) cp16(d + (ATILES + 1) * TILEB, gBl + bof);
        }
    };

    issue(sb, 0);
    CP_COMMIT();
    if (nCh > 1) issue(sb + SGB, 32);
    CP_COMMIT();

    int sc = 0;
    for (int c = 0; c < nCh; c++) {
        CP_WAIT1();
        __syncthreads();
        if (c + 2 < nCh) {
            int sn = sc + 2; if (sn >= 3) sn -= 3;
            issue(sb + sn * SGB, (c + 2) << 5);
        }
        CP_COMMIT();

        uint32_t bufb = sb + sc * SGB;
        uint32_t sA_  = bufb;
        uint32_t sAl_ = bufb + TILEB;
        uint32_t sBh_ = bufb + ATILES * TILEB;
        uint32_t sBl_ = bufb + (ATILES + 1) * TILEB;

        #pragma unroll
        for (int kh = 0; kh < 2; kh++) {
            uint32_t ah[4][4], al[4][4], bh[2][4], bl[2][4];
            #pragma unroll
            for (int mt = 0; mt < 4; mt++) {
                ldmx4(ah[mt], sA_ + aoff[mt][kh]);
                if (!AS) ldmx4(al[mt], sAl_ + aoff[mt][kh]);
            }
            #pragma unroll
            for (int np = 0; np < 2; np++) {
                ldmx4(bh[np], sBh_ + boff[np][kh]);
                if (!BS) ldmx4(bl[np], sBl_ + boff[np][kh]);
            }
            #pragma unroll
            for (int mt = 0; mt < 4; mt++) {
                #pragma unroll
                for (int nt = 0; nt < 4; nt++) {
                    const uint32_t* bhp = &bh[nt >> 1][(nt & 1) << 1];
                    const uint32_t* blp = &bl[nt >> 1][(nt & 1) << 1];
                    mma16816(acc[mt][nt], ah[mt], bhp);
                    if (!BS) mma16816(acc[mt][nt], ah[mt], blp);
                    if (!AS) mma16816(acc[mt][nt], al[mt], bhp);
                }
            }
        }
        __syncthreads();
        if (++sc == 3) sc = 0;
    }

    // epilogue
    #pragma unroll
    for (int mt = 0; mt < 4; mt++) {
        int r0 = by * 128 + wm * 64 + mt * 16 + (lane >> 2);
        #pragma unroll
        for (int nt = 0; nt < 4; nt++) {
            int c0 = bx * 128 + wn * 32 + nt * 8 + ((lane & 3) << 1);
            if (c0 >= ncols) continue;
            float v00 = alpha * acc[mt][nt][0], v01 = alpha * acc[mt][nt][1];
            float v10 = alpha * acc[mt][nt][2], v11 = alpha * acc[mt][nt][3];
            if (outMode == 0) {
                *(float2*)(C + co + (long)r0 * ldc + c0) = make_float2(v00, v01);
                *(float2*)(C + co + (long)(r0 + 8) * ldc + c0) = make_float2(v10, v11);
            } else {
                *(uint32_t*)(Co + co + (long)r0 * ldc + c0) =
                    (uint32_t)tohalf(v00) | ((uint32_t)tohalf(v01) << 16);
                *(uint32_t*)(Co + co + (long)(r0 + 8) * ldc + c0) =
                    (uint32_t)tohalf(v10) | ((uint32_t)tohalf(v11) << 16);
            }
        }
    }
}

// ---------------- split fp32 -> fp16 hi/lo ----------------
__global__ void split_kernel(const float* __restrict__ src,
                             U16* __restrict__ hi, U16* __restrict__ lo, long n)
{
    long i = ((long)blockIdx.x * 256 + threadIdx.x) * 4;
    if (i >= n) return;
    float4 v = *(const float4*)(src + i);
    U16 h[4], l[4];
    split1h(v.x, h[0], l[0]); split1h(v.y, h[1], l[1]);
    split1h(v.z, h[2], l[2]); split1h(v.w, h[3], l[3]);
    uint2 hv, lv;
    hv.x = (uint32_t)h[0] | ((uint32_t)h[1] << 16); hv.y = (uint32_t)h[2] | ((uint32_t)h[3] << 16);
    lv.x = (uint32_t)l[0] | ((uint32_t)l[1] << 16); lv.y = (uint32_t)l[2] | ((uint32_t)l[3] << 16);
    *(uint2*)(hi + i) = hv;
    *(uint2*)(lo + i) = lv;
}

// fp32 -> single fp16
__global__ void tosingle_kernel(const float* __restrict__ src, U16* __restrict__ o, long n)
{
    long i = ((long)blockIdx.x * 256 + threadIdx.x) * 4;
    if (i >= n) return;
    float4 v = *(const float4*)(src + i);
    uint2 ov;
    ov.x = (uint32_t)tohalf(v.x) | ((uint32_t)tohalf(v.y) << 16);
    ov.y = (uint32_t)tohalf(v.z) | ((uint32_t)tohalf(v.w) << 16);
    *(uint2*)(o + i) = ov;
}

// ---------------- RMSNorm (fp32 in, single fp16 out) ----------------
__global__ void rmsnorm_kernel(const float* __restrict__ ql, const float* __restrict__ w,
                               U16* __restrict__ os)
{
    const float* row = ql + (long)blockIdx.x * QLORA_;
    long ob = (long)blockIdx.x * QLORA_;
    int tid = threadIdx.x;
    float s = 0.f;
    for (int i = tid; i < QLORA_; i += 256) { float v = row[i]; s += v * v; }
    __shared__ float red[256];
    red[tid] = s; __syncthreads();
    for (int st = 128; st > 0; st >>= 1) { if (tid < st) red[tid] += red[tid + st]; __syncthreads(); }
    float scale = rsqrtf(red[0] / (float)QLORA_ + 1e-6f);
    for (int i = tid; i < QLORA_; i += 256)
        os[ob + i] = tohalf(w[i] * (row[i] * scale));
}

// ---------------- RoPE ----------------
__device__ __forceinline__ void rope_pair(float p, int i, float x0, float x1,
                                          float& o_lo, float& o_hi)
{
    double inv = exp(-((double)(2 * i) / 64.0) * 13.815510557964274);
    double ang = (double)p * inv;
    double sd, cd; sincos(ang, &sd, &cd);
    float cc = (float)cd, ss = (float)sd;
    o_lo = x0 * cc - x1 * ss;
    o_hi = x1 * cc + x0 * ss;
}

__global__ void rope_q_kernel(const U16* __restrict__ qs,
                              const int* __restrict__ pos, U16* __restrict__ es)
{
    int idx = blockIdx.x * blockDim.x + threadIdx.x;
    if (idx >= BB * SS * NHH) return;
    int h = idx % NHH;
    int bs = idx / NHH;
    int b = bs / SS, s_idx = bs % SS;
    float p = (float)pos[bs];
    long xb = ((long)bs * NHH + h) * QHD + NOPE_;
    long ob = ((long)(b * NHH + h) * SS + s_idx) * QEXT + KVLORA_;
    for (int i = 0; i < 32; i++) {
        float x0 = __half2float(__ushort_as_half(qs[xb + 2 * i]));
        float x1 = __half2float(__ushort_as_half(qs[xb + 2 * i + 1]));
        float lo, hi;
        rope_pair(p, i, x0, x1, lo, hi);
        es[ob + i] = tohalf(lo);
        es[ob + 32 + i] = tohalf(hi);
    }
}

__global__ void rope_k_kernel(float* __restrict__ ckv, const int* __restrict__ pos)
{
    int bs = blockIdx.x * blockDim.x + threadIdx.x;
    if (bs >= BB * SS) return;
    float p = (float)pos[bs];
    float* x = ckv + (long)bs * QEXT + KVLORA_;
    float tmp[64];
    for (int i = 0; i < 32; i++)
        rope_pair(p, i, x[2 * i], x[2 * i + 1], tmp[i], tmp[32 + i]);
    for (int j = 0; j < 64; j++) x[j] = tmp[j];
}

// ---------------- transposes ----------------
__global__ void transpose_wabs_kernel(const float* __restrict__ Wkv_up,
                                      U16* __restrict__ oh, U16* __restrict__ ol)
{
    int idx = blockIdx.x * blockDim.x + threadIdx.x;
    if (idx >= NHH * KVLORA_ * NOPE_) return;
    int n = idx % NOPE_;
    int r = idx / NOPE_;
    int c = r % KVLORA_;
    int h = r / KVLORA_;
    float v = Wkv_up[((long)h * 256 + n) * KVLORA_ + c];
    U16 a, b; split1h(v, a, b);
    oh[idx] = a; ol[idx] = b;
}

__global__ void transpose_ckv_kernel(const float* __restrict__ ckv, U16* __restrict__ os)
{
    __shared__ float t[32][33];
    int b = blockIdx.z;
    int s0 = blockIdx.x * 32, c0 = blockIdx.y * 32;
    int x = threadIdx.x, y = threadIdx.y;
    for (int i = y; i < 32; i += 8)
        t[i][x] = ckv[((long)b * SS + s0 + i) * QEXT + c0 + x];
    __syncthreads();
    for (int i = y; i < 32; i += 8) {
        long o = ((long)b * KVLORA_ + c0 + i) * SS + s0 + x;
        os[o] = tohalf(t[x][i]);
    }
}

// ---------------- causal softmax (fp32 in, single fp16 out) ----------------
__global__ void softmax_kernel(const float* __restrict__ scores, U16* __restrict__ os)
{
    long row = blockIdx.x;
    int q = (int)(row % SS);
    const float* r = scores + row * (long)SS;
    long ob = row * (long)SS;
    int tid = threadIdx.x;
    int n = q + 1;
    int blockEnd = ((q >> 7) + 1) << 7;   // consumers only read cols < blockEnd
    __shared__ float red[256];

    float mx = -1e30f;
    for (int k = tid; k < n; k += 256) mx = fmaxf(mx, r[k]);
    red[tid] = mx; __syncthreads();
    for (int st = 128; st > 0; st >>= 1) { if (tid < st) red[tid] = fmaxf(red[tid], red[tid + st]); __syncthreads(); }
    mx = red[0]; __syncthreads();

    float sum = 0.f;
    __shared__ float es[2048];
    for (int k = tid; k < n; k += 256) { float e = __expf(r[k] - mx); es[k] = e; sum += e; }
    red[tid] = sum; __syncthreads();
    for (int st = 128; st > 0; st >>= 1) { if (tid < st) red[tid] += red[tid + st]; __syncthreads(); }
    float inv = 1.f / red[0];

    for (int k = tid; k < n; k += 256) os[ob + k] = tohalf(es[k] * inv);
    for (int k = n + tid; k < blockEnd; k += 256) os[ob + k] = 0;
}

// ---------------- host ----------------
template<int AS, int BS>
static void launch_mma(const U16* Ah, const U16* Al, const U16* Bh, const U16* Bl,
                       float* C, U16* Co,
                       int M, int Npad, int K, int lda, int ldb, int ldc, int ncols,
                       long sAb, long sAh, long sBb, long sBh, long sCb, long sCh,
                       int zh, int zcount, float alpha, int cSkip, int cK, int outMode)
{
    constexpr int SMEM = 3 * ((AS ? 1 : 2) + (BS ? 1 : 2)) * TILEB;
    cudaFuncSetAttribute(mma_gemm<AS, BS>, cudaFuncAttributeMaxDynamicSharedMemorySize, SMEM);
    dim3 grid(Npad / 128, M / 128, zcount);
    mma_gemm<AS, BS><<<grid, 256, SMEM>>>(Ah, Al, Bh, Bl, C, Co,
        K, lda, ldb, ldc, ncols, sAb, sAh, sBb, sBh, sCb, sCh, zh, alpha, cSkip, cK, outMode);
}

static void launch_split(const float* s, U16* h, U16* l, long n)
{
    split_kernel<<<(unsigned)((n / 4 + 255) / 256), 256>>>(s, h, l, n);
}

extern "C" void kernel_launch(void* const* d_in, const int* in_sizes, int n_in,
                              void* d_out, int out_size)
{
    const float* hs      = (const float*)d_in[0];
    const int*   pos     = (const int*)  d_in[1];
    const float* Wq_down = (const float*)d_in[3];
    const float* q_ln_w  = (const float*)d_in[4];
    const float* Wq_up   = (const float*)d_in[5];
    const float* Wkv_down= (const float*)d_in[6];
    const float* Wkv_up  = (const float*)d_in[7];
    const float* Wo      = (const float*)d_in[8];
    float* out = (float*)d_out;

    float *ql, *ckv, *scores;
    cudaGetSymbolAddress((void**)&ql, g_ql);
    cudaGetSymbolAddress((void**)&ckv, g_ckv);
    cudaGetSymbolAddress((void**)&scores, g_scores);
    U16 *hs_s, *wqd_h, *wqd_l, *wqu_h, *wqu_l, *wo_h, *wo_l, *wkvd_h, *wkvd_l;
    U16 *wkvup_h, *wkvup_l, *wabsT_h, *wabsT_l, *ql_s, *q_s;
    U16 *ckv_s, *ckvT_s, *qext_s, *sc_s, *out1_s, *out2_s;
    cudaGetSymbolAddress((void**)&hs_s, g_hs_s);
    cudaGetSymbolAddress((void**)&wqd_h, g_wqd_h);   cudaGetSymbolAddress((void**)&wqd_l, g_wqd_l);
    cudaGetSymbolAddress((void**)&wqu_h, g_wqu_h);   cudaGetSymbolAddress((void**)&wqu_l, g_wqu_l);
    cudaGetSymbolAddress((void**)&wo_h, g_wo_h);     cudaGetSymbolAddress((void**)&wo_l, g_wo_l);
    cudaGetSymbolAddress((void**)&wkvd_h, g_wkvd_h); cudaGetSymbolAddress((void**)&wkvd_l, g_wkvd_l);
    cudaGetSymbolAddress((void**)&wkvup_h, g_wkvup_h); cudaGetSymbolAddress((void**)&wkvup_l, g_wkvup_l);
    cudaGetSymbolAddress((void**)&wabsT_h, g_wabsT_h); cudaGetSymbolAddress((void**)&wabsT_l, g_wabsT_l);
    cudaGetSymbolAddress((void**)&ql_s, g_ql_s);
    cudaGetSymbolAddress((void**)&q_s, g_q_s);
    cudaGetSymbolAddress((void**)&ckv_s, g_ckv_s);
    cudaGetSymbolAddress((void**)&ckvT_s, g_ckvT_s);
    cudaGetSymbolAddress((void**)&qext_s, g_qext_s);
    cudaGetSymbolAddress((void**)&sc_s, g_sc_s);
    cudaGetSymbolAddress((void**)&out1_s, g_out1_s);
    cudaGetSymbolAddress((void**)&out2_s, g_out2_s);

    const int M = BB * SS;
    const float scale = 1.0f / sqrtf((float)QHD);

    // input/weight preprocessing
    tosingle_kernel<<<(unsigned)(((long)BB * SS * HDIM / 4 + 255) / 256), 256>>>(
        hs, hs_s, (long)BB * SS * HDIM);
    launch_split(Wq_down, wqd_h, wqd_l, (long)QLORA_ * HDIM);
    launch_split(Wq_up, wqu_h, wqu_l, (long)NHH * QHD * QLORA_);
    launch_split(Wo, wo_h, wo_l, (long)HDIM * HDIM);
    launch_split(Wkv_down, wkvd_h, wkvd_l, (long)QEXT * HDIM);
    launch_split(Wkv_up, wkvup_h, wkvup_l, (long)NHH * 256 * KVLORA_);
    transpose_wabs_kernel<<<(NHH * KVLORA_ * NOPE_ + 255) / 256, 256>>>(Wkv_up, wabsT_h, wabsT_l);

    // 1. ql = hs(single) @ Wq_down(pair)^T [4096,1536] fp32
    launch_mma<1,0>(hs_s, hs_s, wqd_h, wqd_l, ql, 0,
                    M, QLORA_, HDIM, HDIM, HDIM, QLORA_, QLORA_,
                    0,0,0,0,0,0, 1, 1, 1.f, 0, 0, 0);
    // 2. RMSNorm -> ql single
    rmsnorm_kernel<<<M, 256>>>(ql, q_ln_w, ql_s);
    // 3. q = ql(single) @ Wq_up(pair)^T [4096,3072] single out
    launch_mma<1,0>(ql_s, ql_s, wqu_h, wqu_l, 0, q_s,
                    M, NHH * QHD, QLORA_, QLORA_, QLORA_, NHH * QHD, NHH * QHD,
                    0,0,0,0,0,0, 1, 1, 1.f, 0, 0, 2);
    // 4. ckv = hs(single) @ Wkv_down(pair)^T [4096,576] via Npad=640, fp32
    launch_mma<1,0>(hs_s, hs_s, wkvd_h, wkvd_l, ckv, 0,
                    M, 640, HDIM, HDIM, HDIM, QEXT, QEXT,
                    0,0,0,0,0,0, 1, 1, 1.f, 0, 0, 0);
    // 5. RoPE k (fp32 in place), single-convert + transpose
    rope_k_kernel<<<(BB * SS + 255) / 256, 256>>>(ckv, pos);
    tosingle_kernel<<<(unsigned)(((long)BB * SS * QEXT / 4 + 255) / 256), 256>>>(
        ckv, ckv_s, (long)BB * SS * QEXT);
    {
        dim3 grid(SS / 32, KVLORA_ / 32, BB);
        transpose_ckv_kernel<<<grid, dim3(32, 8)>>>(ckv, ckvT_s);
    }
    // 6. RoPE q -> qext single cols 512:576
    rope_q_kernel<<<(BB * SS * NHH + 255) / 256, 256>>>(q_s, pos, qext_s);
    // 7. qext[:,0:512] = q(single) @ q_absorb(pair), single out
    launch_mma<1,0>(q_s, q_s, wabsT_h, wabsT_l, 0, qext_s,
                    SS, KVLORA_, NOPE_, NHH * QHD, NOPE_, QEXT, KVLORA_,
                    (long)SS * NHH * QHD, (long)QHD,
                    0, (long)KVLORA_ * NOPE_,
                    (long)NHH * SS * QEXT, (long)SS * QEXT,
                    NHH, BB * NHH, 1.f, 0, 0, 2);
    // 8. scores = scale * qext(single) @ ckv(single)^T, fp32, causal skip
    launch_mma<1,1>(qext_s, qext_s, ckv_s, ckv_s, scores, 0,
                    SS, SS, QEXT, QEXT, QEXT, SS, SS,
                    (long)NHH * SS * QEXT, (long)SS * QEXT,
                    (long)SS * QEXT, 0,
                    (long)NHH * SS * SS, (long)SS * SS,
                    NHH, BB * NHH, scale, 1, 0, 0);
    // 9. softmax -> probs single fp16 (zero-fill only to causal block end)
    softmax_kernel<<<BB * NHH * SS, 256>>>(scores, sc_s);
    // 10. out1 = probs(single) @ ckvT(single), causal K-limit, single out
    launch_mma<1,1>(sc_s, sc_s, ckvT_s, ckvT_s, 0, out1_s,
                    SS, KVLORA_, SS, SS, SS, KVLORA_, KVLORA_,
                    (long)NHH * SS * SS, (long)SS * SS,
                    (long)KVLORA_ * SS, 0,
                    (long)NHH * SS * KVLORA_, (long)SS * KVLORA_,
                    NHH, BB * NHH, 1.f, 0, 1, 2);
    // 11. out2 = out1(single) @ out_absorb(pair)^T, single out
    launch_mma<1,0>(out1_s, out1_s, wkvup_h + (long)NOPE_ * KVLORA_, wkvup_l + (long)NOPE_ * KVLORA_,
                    0, out2_s,
                    SS, VD_, KVLORA_, KVLORA_, KVLORA_, NHH * VD_, NHH * VD_,
                    (long)NHH * SS * KVLORA_, (long)SS * KVLORA_,
                    0, (long)256 * KVLORA_,
                    (long)SS * NHH * VD_, (long)VD_,
                    NHH, BB * NHH, 1.f, 0, 0, 2);
    // 12. final = out2(single) @ Wo(pair)^T [4096,2048] fp32
    launch_mma<1,0>(out2_s, out2_s, wo_h, wo_l, out, 0,
                    M, HDIM, NHH * VD_, NHH * VD_, NHH * VD_, HDIM, HDIM,
                    0,0,0,0,0,0, 1, 1, 1.f, 0, 0, 0);
}

// round 9
// speedup vs baseline: 5.3808x; 1.2447x over previous
#include <cuda_runtime.h>
#include <cuda_fp16.h>
#include <math.h>
#include <stdint.h>

typedef unsigned short U16;

// ---------------- problem constants ----------------
#define NHH   16
#define NOPE_ 128
#define ROPED 64
#define VD_   128
#define QLORA_ 1536
#define KVLORA_ 512
#define HDIM  2048
#define BB    2
#define SS    2048
#define QEXT  576
#define QHD   (NOPE_ + ROPED)  // 192

// ---------------- scratch ----------------
__device__ float g_ql    [(long)BB*SS*QLORA_];
__device__ float g_ckv   [(long)BB*SS*QEXT];
__device__ float g_scores[(long)BB*NHH*SS*SS];

__device__ U16 g_hs_s [(long)BB*SS*HDIM];                  // single fp16
__device__ U16 g_wqd_s[(long)QLORA_*HDIM];                 // single fp16
__device__ U16 g_wqu_s[(long)NHH*QHD*QLORA_];              // single fp16
__device__ U16 g_wo_s [(long)HDIM*HDIM];                   // single fp16
__device__ U16 g_wkvd_s[(long)640*HDIM];                   // single fp16, padded 576->640
__device__ U16 g_wkvup_h[(long)NHH*256*KVLORA_], g_wkvup_l[(long)NHH*256*KVLORA_];
__device__ U16 g_wabsT_h[(long)NHH*KVLORA_*NOPE_], g_wabsT_l[(long)NHH*KVLORA_*NOPE_];
__device__ U16 g_ql_s [(long)BB*SS*QLORA_];                // single fp16 (post-rmsnorm)
__device__ U16 g_q_s  [(long)BB*SS*NHH*QHD];               // single fp16
__device__ U16 g_ckv_s[(long)BB*SS*QEXT];                  // single fp16
__device__ U16 g_ckvT_s[(long)BB*KVLORA_*SS];              // single fp16
__device__ U16 g_qext_s[(long)BB*NHH*SS*QEXT];             // single fp16
__device__ U16 g_sc_s  [(long)BB*NHH*SS*SS];               // probs single fp16
__device__ U16 g_out1_s[(long)BB*NHH*SS*KVLORA_];          // single fp16
__device__ U16 g_out2_s[(long)BB*SS*NHH*VD_];              // single fp16

// ================= helpers =================
__device__ __forceinline__ uint32_t smem_u32(const void* p) {
    uint32_t a;
    asm("{ .reg .u64 t; cvta.to.shared.u64 t, %1; cvt.u32.u64 %0, t; }" : "=r"(a) : "l"(p));
    return a;
}
__device__ __forceinline__ void cp16(uint32_t dst, const void* src) {
    asm volatile("cp.async.cg.shared.global [%0], [%1], 16;" :: "r"(dst), "l"(src));
}
#define CP_COMMIT() asm volatile("cp.async.commit_group;" ::: "memory")
#define CP_WAIT1()  asm volatile("cp.async.wait_group 1;" ::: "memory")

__device__ __forceinline__ void ldmx4(uint32_t* r, uint32_t addr) {
    asm volatile("ldmatrix.sync.aligned.m8n8.x4.shared.b16 {%0,%1,%2,%3}, [%4];"
                 : "=r"(r[0]), "=r"(r[1]), "=r"(r[2]), "=r"(r[3]) : "r"(addr));
}
__device__ __forceinline__ void mma16816(float* d, const uint32_t* a, const uint32_t* b) {
    asm volatile("mma.sync.aligned.m16n8k16.row.col.f32.f16.f16.f32 "
                 "{%0,%1,%2,%3}, {%4,%5,%6,%7}, {%8,%9}, {%0,%1,%2,%3};"
                 : "+f"(d[0]), "+f"(d[1]), "+f"(d[2]), "+f"(d[3])
                 : "r"(a[0]), "r"(a[1]), "r"(a[2]), "r"(a[3]), "r"(b[0]), "r"(b[1]));
}
__device__ __forceinline__ void split1h(float v, U16& h, U16& l) {
    __half hb = __float2half_rn(v);
    __half lb = __float2half_rn(v - __half2float(hb));
    h = __half_as_ushort(hb);
    l = __half_as_ushort(lb);
}
__device__ __forceinline__ U16 tohalf(float v) {
    return __half_as_ushort(__float2half_rn(v));
}

// ================= fp16 warp-MMA GEMM =================
// C = alpha * A @ B^T.  Row-major, elem ld.
// AS: A single fp16 (else hi/lo pair). BS: same for B.
// mma/k16: 3 (pair,pair), 2 (single,pair), 1 (single,single).
// Block 128x128, BK=32, 3-stage cp.async pipeline, 8 warps (2x4).
// outMode: 0 = fp32 C; 2 = single fp16 (Co).
#define ROWB 80
#define TILEB (128 * ROWB)     // 10240

extern __shared__ char dsmem[];

template<int AS, int BS>
__global__ void __launch_bounds__(256)
mma_gemm(const U16* __restrict__ Ah, const U16* __restrict__ Al,
         const U16* __restrict__ Bh, const U16* __restrict__ Bl,
         float* __restrict__ C, U16* __restrict__ Co,
         int K, int lda, int ldb, int ldc, int ncols,
         long sAb, long sAhh, long sBb, long sBhh, long sCb, long sChh,
         int zh, float alpha, int causalSkip, int causalK, int outMode)
{
    constexpr int ATILES = AS ? 1 : 2;
    constexpr int BTILES = BS ? 1 : 2;
    constexpr int SGB = (ATILES + BTILES) * TILEB;

    int z = blockIdx.z;
    long ao = (long)(z / zh) * sAb + (long)(z % zh) * sAhh;
    long bo = (long)(z / zh) * sBb + (long)(z % zh) * sBhh;
    long co = (long)(z / zh) * sCb + (long)(z % zh) * sChh;
    int by = blockIdx.y, bx = blockIdx.x;
    if (causalSkip && bx * 128 > by * 128 + 127) return;
    int Klim = causalK ? min(K, by * 128 + 128) : K;
    int nCh = Klim >> 5;

    int tid = threadIdx.x;
    int lane = tid & 31, wid = tid >> 5;
    int wm = wid & 1, wn = wid >> 1;

    uint32_t sb = smem_u32(dsmem);

    const U16* gAh = Ah + ao + (long)(by * 128) * lda;
    const U16* gAl = AS ? gAh : (Al + ao + (long)(by * 128) * lda);
    const U16* gBh = Bh + bo + (long)(bx * 128) * ldb;
    const U16* gBl = BS ? gBh : (Bl + bo + (long)(bx * 128) * ldb);

    uint32_t aoff[4][2], boff[2][2];
    {
        int ar = wm * 64 + (lane & 15);
        int ak = (lane >> 4) << 3;
        #pragma unroll
        for (int mt = 0; mt < 4; mt++)
            #pragma unroll
            for (int kh = 0; kh < 2; kh++)
                aoff[mt][kh] = (uint32_t)((ar + mt * 16) * ROWB + ((ak + kh * 16) << 1));
        int br = wn * 32 + (lane & 7) + ((lane & 16) ? 8 : 0);
        int bk = (lane & 8) ? 8 : 0;
        #pragma unroll
        for (int np = 0; np < 2; np++)
            #pragma unroll
            for (int kh = 0; kh < 2; kh++)
                boff[np][kh] = (uint32_t)((br + np * 16) * ROWB + ((bk + kh * 16) << 1));
    }

    float acc[4][4][4];
    #pragma unroll
    for (int mt = 0; mt < 4; mt++)
        #pragma unroll
        for (int nt = 0; nt < 4; nt++)
            #pragma unroll
            for (int r = 0; r < 4; r++) acc[mt][nt][r] = 0.f;

    auto issue = [&](uint32_t sbase, int k0) {
        #pragma unroll
        for (int half = 0; half < 2; half++) {
            int idx = (half << 8) + tid;
            int row = idx >> 2;
            int e0  = (idx & 3) << 3;
            long aof = (long)row * lda + k0 + e0;
            long bof = (long)row * ldb + k0 + e0;
            uint32_t d = sbase + (uint32_t)(row * ROWB + (e0 << 1));
            cp16(d, gAh + aof);
            if (!AS) cp16(d + TILEB, gAl + aof);
            cp16(d + ATILES * TILEB, gBh + bof);
            if (!BS) cp16(d + (ATILES + 1) * TILEB, gBl + bof);
        }
    };

    issue(sb, 0);
    CP_COMMIT();
    if (nCh > 1) issue(sb + SGB, 32);
    CP_COMMIT();

    int sc = 0;
    for (int c = 0; c < nCh; c++) {
        CP_WAIT1();
        __syncthreads();
        if (c + 2 < nCh) {
            int sn = sc + 2; if (sn >= 3) sn -= 3;
            issue(sb + sn * SGB, (c + 2) << 5);
        }
        CP_COMMIT();

        uint32_t bufb = sb + sc * SGB;
        uint32_t sA_  = bufb;
        uint32_t sAl_ = bufb + TILEB;
        uint32_t sBh_ = bufb + ATILES * TILEB;
        uint32_t sBl_ = bufb + (ATILES + 1) * TILEB;

        #pragma unroll
        for (int kh = 0; kh < 2; kh++) {
            uint32_t ah[4][4], al[4][4], bh[2][4], bl[2][4];
            #pragma unroll
            for (int mt = 0; mt < 4; mt++) {
                ldmx4(ah[mt], sA_ + aoff[mt][kh]);
                if (!AS) ldmx4(al[mt], sAl_ + aoff[mt][kh]);
            }
            #pragma unroll
            for (int np = 0; np < 2; np++) {
                ldmx4(bh[np], sBh_ + boff[np][kh]);
                if (!BS) ldmx4(bl[np], sBl_ + boff[np][kh]);
            }
            #pragma unroll
            for (int mt = 0; mt < 4; mt++) {
                #pragma unroll
                for (int nt = 0; nt < 4; nt++) {
                    const uint32_t* bhp = &bh[nt >> 1][(nt & 1) << 1];
                    const uint32_t* blp = &bl[nt >> 1][(nt & 1) << 1];
                    mma16816(acc[mt][nt], ah[mt], bhp);
                    if (!BS) mma16816(acc[mt][nt], ah[mt], blp);
                    if (!AS) mma16816(acc[mt][nt], al[mt], bhp);
                }
            }
        }
        __syncthreads();
        if (++sc == 3) sc = 0;
    }

    // epilogue
    #pragma unroll
    for (int mt = 0; mt < 4; mt++) {
        int r0 = by * 128 + wm * 64 + mt * 16 + (lane >> 2);
        #pragma unroll
        for (int nt = 0; nt < 4; nt++) {
            int c0 = bx * 128 + wn * 32 + nt * 8 + ((lane & 3) << 1);
            if (c0 >= ncols) continue;
            float v00 = alpha * acc[mt][nt][0], v01 = alpha * acc[mt][nt][1];
            float v10 = alpha * acc[mt][nt][2], v11 = alpha * acc[mt][nt][3];
            if (outMode == 0) {
                *(float2*)(C + co + (long)r0 * ldc + c0) = make_float2(v00, v01);
                *(float2*)(C + co + (long)(r0 + 8) * ldc + c0) = make_float2(v10, v11);
            } else {
                *(uint32_t*)(Co + co + (long)r0 * ldc + c0) =
                    (uint32_t)tohalf(v00) | ((uint32_t)tohalf(v01) << 16);
                *(uint32_t*)(Co + co + (long)(r0 + 8) * ldc + c0) =
                    (uint32_t)tohalf(v10) | ((uint32_t)tohalf(v11) << 16);
            }
        }
    }
}

// ---------------- split fp32 -> fp16 hi/lo ----------------
__global__ void split_kernel(const float* __restrict__ src,
                             U16* __restrict__ hi, U16* __restrict__ lo, long n)
{
    long i = ((long)blockIdx.x * 256 + threadIdx.x) * 4;
    if (i >= n) return;
    float4 v = *(const float4*)(src + i);
    U16 h[4], l[4];
    split1h(v.x, h[0], l[0]); split1h(v.y, h[1], l[1]);
    split1h(v.z, h[2], l[2]); split1h(v.w, h[3], l[3]);
    uint2 hv, lv;
    hv.x = (uint32_t)h[0] | ((uint32_t)h[1] << 16); hv.y = (uint32_t)h[2] | ((uint32_t)h[3] << 16);
    lv.x = (uint32_t)l[0] | ((uint32_t)l[1] << 16); lv.y = (uint32_t)l[2] | ((uint32_t)l[3] << 16);
    *(uint2*)(hi + i) = hv;
    *(uint2*)(lo + i) = lv;
}

// fp32 -> single fp16
__global__ void tosingle_kernel(const float* __restrict__ src, U16* __restrict__ o, long n)
{
    long i = ((long)blockIdx.x * 256 + threadIdx.x) * 4;
    if (i >= n) return;
    float4 v = *(const float4*)(src + i);
    uint2 ov;
    ov.x = (uint32_t)tohalf(v.x) | ((uint32_t)tohalf(v.y) << 16);
    ov.y = (uint32_t)tohalf(v.z) | ((uint32_t)tohalf(v.w) << 16);
    *(uint2*)(o + i) = ov;
}

// ---------------- RMSNorm (fp32 in, single fp16 out) ----------------
__global__ void rmsnorm_kernel(const float* __restrict__ ql, const float* __restrict__ w,
                               U16* __restrict__ os)
{
    const float* row = ql + (long)blockIdx.x * QLORA_;
    long ob = (long)blockIdx.x * QLORA_;
    int tid = threadIdx.x;
    float s = 0.f;
    for (int i = tid; i < QLORA_; i += 256) { float v = row[i]; s += v * v; }
    __shared__ float red[256];
    red[tid] = s; __syncthreads();
    for (int st = 128; st > 0; st >>= 1) { if (tid < st) red[tid] += red[tid + st]; __syncthreads(); }
    float scale = rsqrtf(red[0] / (float)QLORA_ + 1e-6f);
    for (int i = tid; i < QLORA_; i += 256)
        os[ob + i] = tohalf(w[i] * (row[i] * scale));
}

// ---------------- RoPE ----------------
__device__ __forceinline__ void rope_pair(float p, int i, float x0, float x1,
                                          float& o_lo, float& o_hi)
{
    double inv = exp(-((double)(2 * i) / 64.0) * 13.815510557964274);
    double ang = (double)p * inv;
    double sd, cd; sincos(ang, &sd, &cd);
    float cc = (float)cd, ss = (float)sd;
    o_lo = x0 * cc - x1 * ss;
    o_hi = x1 * cc + x0 * ss;
}

__global__ void rope_q_kernel(const U16* __restrict__ qs,
                              const int* __restrict__ pos, U16* __restrict__ es)
{
    int idx = blockIdx.x * blockDim.x + threadIdx.x;
    if (idx >= BB * SS * NHH) return;
    int h = idx % NHH;
    int bs = idx / NHH;
    int b = bs / SS, s_idx = bs % SS;
    float p = (float)pos[bs];
    long xb = ((long)bs * NHH + h) * QHD + NOPE_;
    long ob = ((long)(b * NHH + h) * SS + s_idx) * QEXT + KVLORA_;
    for (int i = 0; i < 32; i++) {
        float x0 = __half2float(__ushort_as_half(qs[xb + 2 * i]));
        float x1 = __half2float(__ushort_as_half(qs[xb + 2 * i + 1]));
        float lo, hi;
        rope_pair(p, i, x0, x1, lo, hi);
        es[ob + i] = tohalf(lo);
        es[ob + 32 + i] = tohalf(hi);
    }
}

__global__ void rope_k_kernel(float* __restrict__ ckv, const int* __restrict__ pos)
{
    int bs = blockIdx.x * blockDim.x + threadIdx.x;
    if (bs >= BB * SS) return;
    float p = (float)pos[bs];
    float* x = ckv + (long)bs * QEXT + KVLORA_;
    float tmp[64];
    for (int i = 0; i < 32; i++)
        rope_pair(p, i, x[2 * i], x[2 * i + 1], tmp[i], tmp[32 + i]);
    for (int j = 0; j < 64; j++) x[j] = tmp[j];
}

// ---------------- transposes ----------------
__global__ void transpose_wabs_kernel(const float* __restrict__ Wkv_up,
                                      U16* __restrict__ oh, U16* __restrict__ ol)
{
    int idx = blockIdx.x * blockDim.x + threadIdx.x;
    if (idx >= NHH * KVLORA_ * NOPE_) return;
    int n = idx % NOPE_;
    int r = idx / NOPE_;
    int c = r % KVLORA_;
    int h = r / KVLORA_;
    float v = Wkv_up[((long)h * 256 + n) * KVLORA_ + c];
    U16 a, b; split1h(v, a, b);
    oh[idx] = a; ol[idx] = b;
}

__global__ void transpose_ckv_kernel(const float* __restrict__ ckv, U16* __restrict__ os)
{
    __shared__ float t[32][33];
    int b = blockIdx.z;
    int s0 = blockIdx.x * 32, c0 = blockIdx.y * 32;
    int x = threadIdx.x, y = threadIdx.y;
    for (int i = y; i < 32; i += 8)
        t[i][x] = ckv[((long)b * SS + s0 + i) * QEXT + c0 + x];
    __syncthreads();
    for (int i = y; i < 32; i += 8) {
        long o = ((long)b * KVLORA_ + c0 + i) * SS + s0 + x;
        os[o] = tohalf(t[x][i]);
    }
}

// ---------------- causal softmax (fp32 in, single fp16 out) ----------------
__global__ void softmax_kernel(const float* __restrict__ scores, U16* __restrict__ os)
{
    long row = blockIdx.x;
    int q = (int)(row % SS);
    const float* r = scores + row * (long)SS;
    long ob = row * (long)SS;
    int tid = threadIdx.x;
    int n = q + 1;
    int blockEnd = ((q >> 7) + 1) << 7;   // consumers only read cols < blockEnd
    __shared__ float red[256];

    float mx = -1e30f;
    for (int k = tid; k < n; k += 256) mx = fmaxf(mx, r[k]);
    red[tid] = mx; __syncthreads();
    for (int st = 128; st > 0; st >>= 1) { if (tid < st) red[tid] = fmaxf(red[tid], red[tid + st]); __syncthreads(); }
    mx = red[0]; __syncthreads();

    float sum = 0.f;
    __shared__ float es[2048];
    for (int k = tid; k < n; k += 256) { float e = __expf(r[k] - mx); es[k] = e; sum += e; }
    red[tid] = sum; __syncthreads();
    for (int st = 128; st > 0; st >>= 1) { if (tid < st) red[tid] += red[tid + st]; __syncthreads(); }
    float inv = 1.f / red[0];

    for (int k = tid; k < n; k += 256) os[ob + k] = tohalf(es[k] * inv);
    for (int k = n + tid; k < blockEnd; k += 256) os[ob + k] = 0;
}

// ---------------- host ----------------
template<int AS, int BS>
static void launch_mma(const U16* Ah, const U16* Al, const U16* Bh, const U16* Bl,
                       float* C, U16* Co,
                       int M, int Npad, int K, int lda, int ldb, int ldc, int ncols,
                       long sAb, long sAh, long sBb, long sBh, long sCb, long sCh,
                       int zh, int zcount, float alpha, int cSkip, int cK, int outMode)
{
    constexpr int SMEM = 3 * ((AS ? 1 : 2) + (BS ? 1 : 2)) * TILEB;
    cudaFuncSetAttribute(mma_gemm<AS, BS>, cudaFuncAttributeMaxDynamicSharedMemorySize, SMEM);
    dim3 grid(Npad / 128, M / 128, zcount);
    mma_gemm<AS, BS><<<grid, 256, SMEM>>>(Ah, Al, Bh, Bl, C, Co,
        K, lda, ldb, ldc, ncols, sAb, sAh, sBb, sBh, sCb, sCh, zh, alpha, cSkip, cK, outMode);
}

static void launch_split(const float* s, U16* h, U16* l, long n)
{
    split_kernel<<<(unsigned)((n / 4 + 255) / 256), 256>>>(s, h, l, n);
}
static void launch_tosingle(const float* s, U16* o, long n)
{
    tosingle_kernel<<<(unsigned)((n / 4 + 255) / 256), 256>>>(s, o, n);
}

extern "C" void kernel_launch(void* const* d_in, const int* in_sizes, int n_in,
                              void* d_out, int out_size)
{
    const float* hs      = (const float*)d_in[0];
    const int*   pos     = (const int*)  d_in[1];
    const float* Wq_down = (const float*)d_in[3];
    const float* q_ln_w  = (const float*)d_in[4];
    const float* Wq_up   = (const float*)d_in[5];
    const float* Wkv_down= (const float*)d_in[6];
    const float* Wkv_up  = (const float*)d_in[7];
    const float* Wo      = (const float*)d_in[8];
    float* out = (float*)d_out;

    float *ql, *ckv, *scores;
    cudaGetSymbolAddress((void**)&ql, g_ql);
    cudaGetSymbolAddress((void**)&ckv, g_ckv);
    cudaGetSymbolAddress((void**)&scores, g_scores);
    U16 *hs_s, *wqd_s, *wqu_s, *wo_s, *wkvd_s;
    U16 *wkvup_h, *wkvup_l, *wabsT_h, *wabsT_l, *ql_s, *q_s;
    U16 *ckv_s, *ckvT_s, *qext_s, *sc_s, *out1_s, *out2_s;
    cudaGetSymbolAddress((void**)&hs_s, g_hs_s);
    cudaGetSymbolAddress((void**)&wqd_s, g_wqd_s);
    cudaGetSymbolAddress((void**)&wqu_s, g_wqu_s);
    cudaGetSymbolAddress((void**)&wo_s, g_wo_s);
    cudaGetSymbolAddress((void**)&wkvd_s, g_wkvd_s);
    cudaGetSymbolAddress((void**)&wkvup_h, g_wkvup_h); cudaGetSymbolAddress((void**)&wkvup_l, g_wkvup_l);
    cudaGetSymbolAddress((void**)&wabsT_h, g_wabsT_h); cudaGetSymbolAddress((void**)&wabsT_l, g_wabsT_l);
    cudaGetSymbolAddress((void**)&ql_s, g_ql_s);
    cudaGetSymbolAddress((void**)&q_s, g_q_s);
    cudaGetSymbolAddress((void**)&ckv_s, g_ckv_s);
    cudaGetSymbolAddress((void**)&ckvT_s, g_ckvT_s);
    cudaGetSymbolAddress((void**)&qext_s, g_qext_s);
    cudaGetSymbolAddress((void**)&sc_s, g_sc_s);
    cudaGetSymbolAddress((void**)&out1_s, g_out1_s);
    cudaGetSymbolAddress((void**)&out2_s, g_out2_s);

    const int M = BB * SS;
    const float scale = 1.0f / sqrtf((float)QHD);

    // input/weight preprocessing (big projection weights -> single fp16)
    launch_tosingle(hs, hs_s, (long)BB * SS * HDIM);
    launch_tosingle(Wq_down, wqd_s, (long)QLORA_ * HDIM);
    launch_tosingle(Wq_up, wqu_s, (long)NHH * QHD * QLORA_);
    launch_tosingle(Wo, wo_s, (long)HDIM * HDIM);
    launch_tosingle(Wkv_down, wkvd_s, (long)QEXT * HDIM);
    launch_split(Wkv_up, wkvup_h, wkvup_l, (long)NHH * 256 * KVLORA_);
    transpose_wabs_kernel<<<(NHH * KVLORA_ * NOPE_ + 255) / 256, 256>>>(Wkv_up, wabsT_h, wabsT_l);

    // 1. ql = hs(s) @ Wq_down(s)^T [4096,1536] fp32
    launch_mma<1,1>(hs_s, hs_s, wqd_s, wqd_s, ql, 0,
                    M, QLORA_, HDIM, HDIM, HDIM, QLORA_, QLORA_,
                    0,0,0,0,0,0, 1, 1, 1.f, 0, 0, 0);
    // 2. RMSNorm -> ql single
    rmsnorm_kernel<<<M, 256>>>(ql, q_ln_w, ql_s);
    // 3. q = ql(s) @ Wq_up(s)^T [4096,3072] single out
    launch_mma<1,1>(ql_s, ql_s, wqu_s, wqu_s, 0, q_s,
                    M, NHH * QHD, QLORA_, QLORA_, QLORA_, NHH * QHD, NHH * QHD,
                    0,0,0,0,0,0, 1, 1, 1.f, 0, 0, 2);
    // 4. ckv = hs(s) @ Wkv_down(s)^T [4096,576] via Npad=640, fp32
    launch_mma<1,1>(hs_s, hs_s, wkvd_s, wkvd_s, ckv, 0,
                    M, 640, HDIM, HDIM, HDIM, QEXT, QEXT,
                    0,0,0,0,0,0, 1, 1, 1.f, 0, 0, 0);
    // 5. RoPE k (fp32 in place), single-convert + transpose
    rope_k_kernel<<<(BB * SS + 255) / 256, 256>>>(ckv, pos);
    launch_tosingle(ckv, ckv_s, (long)BB * SS * QEXT);
    {
        dim3 grid(SS / 32, KVLORA_ / 32, BB);
        transpose_ckv_kernel<<<grid, dim3(32, 8)>>>(ckv, ckvT_s);
    }
    // 6. RoPE q -> qext single cols 512:576
    rope_q_kernel<<<(BB * SS * NHH + 255) / 256, 256>>>(q_s, pos, qext_s);
    // 7. qext[:,0:512] = q(s) @ q_absorb(pair), single out
    launch_mma<1,0>(q_s, q_s, wabsT_h, wabsT_l, 0, qext_s,
                    SS, KVLORA_, NOPE_, NHH * QHD, NOPE_, QEXT, KVLORA_,
                    (long)SS * NHH * QHD, (long)QHD,
                    0, (long)KVLORA_ * NOPE_,
                    (long)NHH * SS * QEXT, (long)SS * QEXT,
                    NHH, BB * NHH, 1.f, 0, 0, 2);
    // 8. scores = scale * qext(s) @ ckv(s)^T, fp32, causal skip
    launch_mma<1,1>(qext_s, qext_s, ckv_s, ckv_s, scores, 0,
                    SS, SS, QEXT, QEXT, QEXT, SS, SS,
                    (long)NHH * SS * QEXT, (long)SS * QEXT,
                    (long)SS * QEXT, 0,
                    (long)NHH * SS * SS, (long)SS * SS,
                    NHH, BB * NHH, scale, 1, 0, 0);
    // 9. softmax -> probs single fp16 (zero-fill only to causal block end)
    softmax_kernel<<<BB * NHH * SS, 256>>>(scores, sc_s);
    // 10. out1 = probs(s) @ ckvT(s), causal K-limit, single out
    launch_mma<1,1>(sc_s, sc_s, ckvT_s, ckvT_s, 0, out1_s,
                    SS, KVLORA_, SS, SS, SS, KVLORA_, KVLORA_,
                    (long)NHH * SS * SS, (long)SS * SS,
                    (long)KVLORA_ * SS, 0,
                    (long)NHH * SS * KVLORA_, (long)SS * KVLORA_,
                    NHH, BB * NHH, 1.f, 0, 1, 2);
    // 11. out2 = out1(s) @ out_absorb(pair)^T, single out
    launch_mma<1,0>(out1_s, out1_s, wkvup_h + (long)NOPE_ * KVLORA_, wkvup_l + (long)NOPE_ * KVLORA_,
                    0, out2_s,
                    SS, VD_, KVLORA_, KVLORA_, KVLORA_, NHH * VD_, NHH * VD_,
                    (long)NHH * SS * KVLORA_, (long)SS * KVLORA_,
                    0, (long)256 * KVLORA_,
                    (long)SS * NHH * VD_, (long)VD_,
                    NHH, BB * NHH, 1.f, 0, 0, 2);
    // 12. final = out2(s) @ Wo(s)^T [4096,2048] fp32
    launch_mma<1,1>(out2_s, out2_s, wo_s, wo_s, out, 0,
                    M, HDIM, NHH * VD_, NHH * VD_, NHH * VD_, HDIM, HDIM,
                    0,0,0,0,0,0, 1, 1, 1.f, 0, 0, 0);
}

// round 10
// speedup vs baseline: 5.6629x; 1.0524x over previous
#include <cuda_runtime.h>
#include <cuda_fp16.h>
#include <math.h>
#include <stdint.h>

typedef unsigned short U16;

// ---------------- problem constants ----------------
#define NHH   16
#define NOPE_ 128
#define ROPED 64
#define VD_   128
#define QLORA_ 1536
#define KVLORA_ 512
#define HDIM  2048
#define BB    2
#define SS    2048
#define QEXT  576
#define QHD   (NOPE_ + ROPED)  // 192

// ---------------- scratch ----------------
__device__ float g_ql    [(long)BB*SS*QLORA_];
__device__ float g_ckv   [(long)BB*SS*QEXT];

__device__ U16 g_hs_s [(long)BB*SS*HDIM];                  // single fp16
__device__ U16 g_wqd_s[(long)QLORA_*HDIM];                 // single fp16
__device__ U16 g_wqu_s[(long)NHH*QHD*QLORA_];              // single fp16
__device__ U16 g_wo_s [(long)HDIM*HDIM];                   // single fp16
__device__ U16 g_wkvd_s[(long)640*HDIM];                   // single fp16, padded 576->640
__device__ U16 g_wkvup_h[(long)NHH*256*KVLORA_], g_wkvup_l[(long)NHH*256*KVLORA_];
__device__ U16 g_wabsT_h[(long)NHH*KVLORA_*NOPE_], g_wabsT_l[(long)NHH*KVLORA_*NOPE_];
__device__ U16 g_ql_s [(long)BB*SS*QLORA_];                // single fp16 (post-rmsnorm)
__device__ U16 g_q_s  [(long)BB*SS*NHH*QHD];               // single fp16
__device__ U16 g_ckv_s[(long)BB*SS*QEXT];                  // single fp16
__device__ U16 g_ckvT_s[(long)BB*KVLORA_*SS];              // single fp16
__device__ U16 g_qext_s[(long)BB*NHH*SS*QEXT];             // single fp16
__device__ U16 g_sc_s  [(long)BB*NHH*SS*SS];               // raw scores then probs, fp16 in-place
__device__ U16 g_out1_s[(long)BB*NHH*SS*KVLORA_];          // single fp16
__device__ U16 g_out2_s[(long)BB*SS*NHH*VD_];              // single fp16

// ================= helpers =================
__device__ __forceinline__ uint32_t smem_u32(const void* p) {
    uint32_t a;
    asm("{ .reg .u64 t; cvta.to.shared.u64 t, %1; cvt.u32.u64 %0, t; }" : "=r"(a) : "l"(p));
    return a;
}
__device__ __forceinline__ void cp16(uint32_t dst, const void* src) {
    asm volatile("cp.async.cg.shared.global [%0], [%1], 16;" :: "r"(dst), "l"(src));
}
#define CP_COMMIT() asm volatile("cp.async.commit_group;" ::: "memory")
#define CP_WAIT1()  asm volatile("cp.async.wait_group 1;" ::: "memory")

__device__ __forceinline__ void ldmx4(uint32_t* r, uint32_t addr) {
    asm volatile("ldmatrix.sync.aligned.m8n8.x4.shared.b16 {%0,%1,%2,%3}, [%4];"
                 : "=r"(r[0]), "=r"(r[1]), "=r"(r[2]), "=r"(r[3]) : "r"(addr));
}
__device__ __forceinline__ void mma16816(float* d, const uint32_t* a, const uint32_t* b) {
    asm volatile("mma.sync.aligned.m16n8k16.row.col.f32.f16.f16.f32 "
                 "{%0,%1,%2,%3}, {%4,%5,%6,%7}, {%8,%9}, {%0,%1,%2,%3};"
                 : "+f"(d[0]), "+f"(d[1]), "+f"(d[2]), "+f"(d[3])
                 : "r"(a[0]), "r"(a[1]), "r"(a[2]), "r"(a[3]), "r"(b[0]), "r"(b[1]));
}
__device__ __forceinline__ void split1h(float v, U16& h, U16& l) {
    __half hb = __float2half_rn(v);
    __half lb = __float2half_rn(v - __half2float(hb));
    h = __half_as_ushort(hb);
    l = __half_as_ushort(lb);
}
__device__ __forceinline__ U16 tohalf(float v) {
    return __half_as_ushort(__float2half_rn(v));
}
__device__ __forceinline__ float fromhalf(U16 v) {
    return __half2float(__ushort_as_half(v));
}

// ================= fp16 warp-MMA GEMM =================
// C = alpha * A @ B^T.  Row-major, elem ld.
// AS: A single fp16 (else hi/lo pair). BS: same for B.
// Block 128x128, BK=32, 3-stage cp.async pipeline, ONE sync per chunk,
// 8 warps (2x4), 2 CTAs/SM target.  outMode: 0 = fp32 C; 2 = single fp16 (Co).
#define ROWB 80
#define TILEB (128 * ROWB)     // 10240

extern __shared__ char dsmem[];

template<int AS, int BS>
__global__ void __launch_bounds__(256, 2)
mma_gemm(const U16* __restrict__ Ah, const U16* __restrict__ Al,
         const U16* __restrict__ Bh, const U16* __restrict__ Bl,
         float* __restrict__ C, U16* __restrict__ Co,
         int K, int lda, int ldb, int ldc, int ncols,
         long sAb, long sAhh, long sBb, long sBhh, long sCb, long sChh,
         int zh, float alpha, int causalSkip, int causalK, int outMode)
{
    constexpr int ATILES = AS ? 1 : 2;
    constexpr int BTILES = BS ? 1 : 2;
    constexpr int SGB = (ATILES + BTILES) * TILEB;

    int z = blockIdx.z;
    long ao = (long)(z / zh) * sAb + (long)(z % zh) * sAhh;
    long bo = (long)(z / zh) * sBb + (long)(z % zh) * sBhh;
    long co = (long)(z / zh) * sCb + (long)(z % zh) * sChh;
    int by = blockIdx.y, bx = blockIdx.x;
    if (causalSkip && bx * 128 > by * 128 + 127) return;
    int Klim = causalK ? min(K, by * 128 + 128) : K;
    int nCh = Klim >> 5;

    int tid = threadIdx.x;
    int lane = tid & 31, wid = tid >> 5;
    int wm = wid & 1, wn = wid >> 1;

    uint32_t sb = smem_u32(dsmem);

    const U16* gAh = Ah + ao + (long)(by * 128) * lda;
    const U16* gAl = AS ? gAh : (Al + ao + (long)(by * 128) * lda);
    const U16* gBh = Bh + bo + (long)(bx * 128) * ldb;
    const U16* gBl = BS ? gBh : (Bl + bo + (long)(bx * 128) * ldb);

    uint32_t aoff[4][2], boff[2][2];
    {
        int ar = wm * 64 + (lane & 15);
        int ak = (lane >> 4) << 3;
        #pragma unroll
        for (int mt = 0; mt < 4; mt++)
            #pragma unroll
            for (int kh = 0; kh < 2; kh++)
                aoff[mt][kh] = (uint32_t)((ar + mt * 16) * ROWB + ((ak + kh * 16) << 1));
        int br = wn * 32 + (lane & 7) + ((lane & 16) ? 8 : 0);
        int bk = (lane & 8) ? 8 : 0;
        #pragma unroll
        for (int np = 0; np < 2; np++)
            #pragma unroll
            for (int kh = 0; kh < 2; kh++)
                boff[np][kh] = (uint32_t)((br + np * 16) * ROWB + ((bk + kh * 16) << 1));
    }

    float acc[4][4][4];
    #pragma unroll
    for (int mt = 0; mt < 4; mt++)
        #pragma unroll
        for (int nt = 0; nt < 4; nt++)
            #pragma unroll
            for (int r = 0; r < 4; r++) acc[mt][nt][r] = 0.f;

    auto issue = [&](uint32_t sbase, int k0) {
        #pragma unroll
        for (int half = 0; half < 2; half++) {
            int idx = (half << 8) + tid;
            int row = idx >> 2;
            int e0  = (idx & 3) << 3;
            long aof = (long)row * lda + k0 + e0;
            long bof = (long)row * ldb + k0 + e0;
            uint32_t d = sbase + (uint32_t)(row * ROWB + (e0 << 1));
            cp16(d, gAh + aof);
            if (!AS) cp16(d + TILEB, gAl + aof);
            cp16(d + ATILES * TILEB, gBh + bof);
            if (!BS) cp16(d + (ATILES + 1) * TILEB, gBl + bof);
        }
    };

    issue(sb, 0);
    CP_COMMIT();
    if (nCh > 1) issue(sb + SGB, 32);
    CP_COMMIT();

    int sc = 0;
    for (int c = 0; c < nCh; c++) {
        CP_WAIT1();
        __syncthreads();     // single barrier per chunk: data-c ready AND all warps done with chunk c-1
        if (c + 2 < nCh) {
            int sn = sc + 2; if (sn >= 3) sn -= 3;
            issue(sb + sn * SGB, (c + 2) << 5);
        }
        CP_COMMIT();

        uint32_t bufb = sb + sc * SGB;
        uint32_t sA_  = bufb;
        uint32_t sAl_ = bufb + TILEB;
        uint32_t sBh_ = bufb + ATILES * TILEB;
        uint32_t sBl_ = bufb + (ATILES + 1) * TILEB;

        #pragma unroll
        for (int kh = 0; kh < 2; kh++) {
            uint32_t ah[4][4], al[4][4], bh[2][4], bl[2][4];
            #pragma unroll
            for (int mt = 0; mt < 4; mt++) {
                ldmx4(ah[mt], sA_ + aoff[mt][kh]);
                if (!AS) ldmx4(al[mt], sAl_ + aoff[mt][kh]);
            }
            #pragma unroll
            for (int np = 0; np < 2; np++) {
                ldmx4(bh[np], sBh_ + boff[np][kh]);
                if (!BS) ldmx4(bl[np], sBl_ + boff[np][kh]);
            }
            #pragma unroll
            for (int mt = 0; mt < 4; mt++) {
                #pragma unroll
                for (int nt = 0; nt < 4; nt++) {
                    const uint32_t* bhp = &bh[nt >> 1][(nt & 1) << 1];
                    const uint32_t* blp = &bl[nt >> 1][(nt & 1) << 1];
                    mma16816(acc[mt][nt], ah[mt], bhp);
                    if (!BS) mma16816(acc[mt][nt], ah[mt], blp);
                    if (!AS) mma16816(acc[mt][nt], al[mt], bhp);
                }
            }
        }
        if (++sc == 3) sc = 0;
    }

    // epilogue
    #pragma unroll
    for (int mt = 0; mt < 4; mt++) {
        int r0 = by * 128 + wm * 64 + mt * 16 + (lane >> 2);
        #pragma unroll
        for (int nt = 0; nt < 4; nt++) {
            int c0 = bx * 128 + wn * 32 + nt * 8 + ((lane & 3) << 1);
            if (c0 >= ncols) continue;
            float v00 = alpha * acc[mt][nt][0], v01 = alpha * acc[mt][nt][1];
            float v10 = alpha * acc[mt][nt][2], v11 = alpha * acc[mt][nt][3];
            if (outMode == 0) {
                *(float2*)(C + co + (long)r0 * ldc + c0) = make_float2(v00, v01);
                *(float2*)(C + co + (long)(r0 + 8) * ldc + c0) = make_float2(v10, v11);
            } else {
                *(uint32_t*)(Co + co + (long)r0 * ldc + c0) =
                    (uint32_t)tohalf(v00) | ((uint32_t)tohalf(v01) << 16);
                *(uint32_t*)(Co + co + (long)(r0 + 8) * ldc + c0) =
                    (uint32_t)tohalf(v10) | ((uint32_t)tohalf(v11) << 16);
            }
        }
    }
}

// ---------------- split fp32 -> fp16 hi/lo ----------------
__global__ void split_kernel(const float* __restrict__ src,
                             U16* __restrict__ hi, U16* __restrict__ lo, long n)
{
    long i = ((long)blockIdx.x * 256 + threadIdx.x) * 4;
    if (i >= n) return;
    float4 v = *(const float4*)(src + i);
    U16 h[4], l[4];
    split1h(v.x, h[0], l[0]); split1h(v.y, h[1], l[1]);
    split1h(v.z, h[2], l[2]); split1h(v.w, h[3], l[3]);
    uint2 hv, lv;
    hv.x = (uint32_t)h[0] | ((uint32_t)h[1] << 16); hv.y = (uint32_t)h[2] | ((uint32_t)h[3] << 16);
    lv.x = (uint32_t)l[0] | ((uint32_t)l[1] << 16); lv.y = (uint32_t)l[2] | ((uint32_t)l[3] << 16);
    *(uint2*)(hi + i) = hv;
    *(uint2*)(lo + i) = lv;
}

// fp32 -> single fp16
__global__ void tosingle_kernel(const float* __restrict__ src, U16* __restrict__ o, long n)
{
    long i = ((long)blockIdx.x * 256 + threadIdx.x) * 4;
    if (i >= n) return;
    float4 v = *(const float4*)(src + i);
    uint2 ov;
    ov.x = (uint32_t)tohalf(v.x) | ((uint32_t)tohalf(v.y) << 16);
    ov.y = (uint32_t)tohalf(v.z) | ((uint32_t)tohalf(v.w) << 16);
    *(uint2*)(o + i) = ov;
}

// ---------------- RMSNorm (fp32 in, single fp16 out) ----------------
__global__ void rmsnorm_kernel(const float* __restrict__ ql, const float* __restrict__ w,
                               U16* __restrict__ os)
{
    const float* row = ql + (long)blockIdx.x * QLORA_;
    long ob = (long)blockIdx.x * QLORA_;
    int tid = threadIdx.x;
    float s = 0.f;
    for (int i = tid; i < QLORA_; i += 256) { float v = row[i]; s += v * v; }
    __shared__ float red[256];
    red[tid] = s; __syncthreads();
    for (int st = 128; st > 0; st >>= 1) { if (tid < st) red[tid] += red[tid + st]; __syncthreads(); }
    float scale = rsqrtf(red[0] / (float)QLORA_ + 1e-6f);
    for (int i = tid; i < QLORA_; i += 256)
        os[ob + i] = tohalf(w[i] * (row[i] * scale));
}

// ---------------- RoPE ----------------
__device__ __forceinline__ void rope_pair(float p, int i, float x0, float x1,
                                          float& o_lo, float& o_hi)
{
    double inv = exp(-((double)(2 * i) / 64.0) * 13.815510557964274);
    double ang = (double)p * inv;
    double sd, cd; sincos(ang, &sd, &cd);
    float cc = (float)cd, ss = (float)sd;
    o_lo = x0 * cc - x1 * ss;
    o_hi = x1 * cc + x0 * ss;
}

__global__ void rope_q_kernel(const U16* __restrict__ qs,
                              const int* __restrict__ pos, U16* __restrict__ es)
{
    int idx = blockIdx.x * blockDim.x + threadIdx.x;
    if (idx >= BB * SS * NHH) return;
    int h = idx % NHH;
    int bs = idx / NHH;
    int b = bs / SS, s_idx = bs % SS;
    float p = (float)pos[bs];
    long xb = ((long)bs * NHH + h) * QHD + NOPE_;
    long ob = ((long)(b * NHH + h) * SS + s_idx) * QEXT + KVLORA_;
    for (int i = 0; i < 32; i++) {
        float x0 = fromhalf(qs[xb + 2 * i]);
        float x1 = fromhalf(qs[xb + 2 * i + 1]);
        float lo, hi;
        rope_pair(p, i, x0, x1, lo, hi);
        es[ob + i] = tohalf(lo);
        es[ob + 32 + i] = tohalf(hi);
    }
}

__global__ void rope_k_kernel(float* __restrict__ ckv, const int* __restrict__ pos)
{
    int bs = blockIdx.x * blockDim.x + threadIdx.x;
    if (bs >= BB * SS) return;
    float p = (float)pos[bs];
    float* x = ckv + (long)bs * QEXT + KVLORA_;
    float tmp[64];
    for (int i = 0; i < 32; i++)
        rope_pair(p, i, x[2 * i], x[2 * i + 1], tmp[i], tmp[32 + i]);
    for (int j = 0; j < 64; j++) x[j] = tmp[j];
}

// ---------------- transposes ----------------
__global__ void transpose_wabs_kernel(const float* __restrict__ Wkv_up,
                                      U16* __restrict__ oh, U16* __restrict__ ol)
{
    int idx = blockIdx.x * blockDim.x + threadIdx.x;
    if (idx >= NHH * KVLORA_ * NOPE_) return;
    int n = idx % NOPE_;
    int r = idx / NOPE_;
    int c = r % KVLORA_;
    int h = r / KVLORA_;
    float v = Wkv_up[((long)h * 256 + n) * KVLORA_ + c];
    U16 a, b; split1h(v, a, b);
    oh[idx] = a; ol[idx] = b;
}

__global__ void transpose_ckv_kernel(const float* __restrict__ ckv, U16* __restrict__ os)
{
    __shared__ float t[32][33];
    int b = blockIdx.z;
    int s0 = blockIdx.x * 32, c0 = blockIdx.y * 32;
    int x = threadIdx.x, y = threadIdx.y;
    for (int i = y; i < 32; i += 8)
        t[i][x] = ckv[((long)b * SS + s0 + i) * QEXT + c0 + x];
    __syncthreads();
    for (int i = y; i < 32; i += 8) {
        long o = ((long)b * KVLORA_ + c0 + i) * SS + s0 + x;
        os[o] = tohalf(t[x][i]);
    }
}

// ---------------- causal softmax (fp16 in, fp16 out, in place) ----------------
__global__ void softmax_kernel(U16* __restrict__ sc)
{
    long row = blockIdx.x;
    int q = (int)(row % SS);
    long ob = row * (long)SS;
    int tid = threadIdx.x;
    int n = q + 1;
    int blockEnd = ((q >> 7) + 1) << 7;   // consumers only read cols < blockEnd
    __shared__ float red[256];
    __shared__ float es[2048];

    float mx = -1e30f;
    for (int k = tid; k < n; k += 256) {
        float v = fromhalf(sc[ob + k]);
        es[k] = v;
        mx = fmaxf(mx, v);
    }
    red[tid] = mx; __syncthreads();
    for (int st = 128; st > 0; st >>= 1) { if (tid < st) red[tid] = fmaxf(red[tid], red[tid + st]); __syncthreads(); }
    mx = red[0]; __syncthreads();

    float sum = 0.f;
    for (int k = tid; k < n; k += 256) { float e = __expf(es[k] - mx); es[k] = e; sum += e; }
    red[tid] = sum; __syncthreads();
    for (int st = 128; st > 0; st >>= 1) { if (tid < st) red[tid] += red[tid + st]; __syncthreads(); }
    float inv = 1.f / red[0];

    for (int k = tid; k < n; k += 256) sc[ob + k] = tohalf(es[k] * inv);
    for (int k = n + tid; k < blockEnd; k += 256) sc[ob + k] = 0;
}

// ---------------- host ----------------
template<int AS, int BS>
static void launch_mma(const U16* Ah, const U16* Al, const U16* Bh, const U16* Bl,
                       float* C, U16* Co,
                       int M, int Npad, int K, int lda, int ldb, int ldc, int ncols,
                       long sAb, long sAh, long sBb, long sBh, long sCb, long sCh,
                       int zh, int zcount, float alpha, int cSkip, int cK, int outMode)
{
    constexpr int SMEM = 3 * ((AS ? 1 : 2) + (BS ? 1 : 2)) * TILEB;
    cudaFuncSetAttribute(mma_gemm<AS, BS>, cudaFuncAttributeMaxDynamicSharedMemorySize, SMEM);
    dim3 grid(Npad / 128, M / 128, zcount);
    mma_gemm<AS, BS><<<grid, 256, SMEM>>>(Ah, Al, Bh, Bl, C, Co,
        K, lda, ldb, ldc, ncols, sAb, sAh, sBb, sBh, sCb, sCh, zh, alpha, cSkip, cK, outMode);
}

static void launch_split(const float* s, U16* h, U16* l, long n)
{
    split_kernel<<<(unsigned)((n / 4 + 255) / 256), 256>>>(s, h, l, n);
}
static void launch_tosingle(const float* s, U16* o, long n)
{
    tosingle_kernel<<<(unsigned)((n / 4 + 255) / 256), 256>>>(s, o, n);
}

extern "C" void kernel_launch(void* const* d_in, const int* in_sizes, int n_in,
                              void* d_out, int out_size)
{
    const float* hs      = (const float*)d_in[0];
    const int*   pos     = (const int*)  d_in[1];
    const float* Wq_down = (const float*)d_in[3];
    const float* q_ln_w  = (const float*)d_in[4];
    const float* Wq_up   = (const float*)d_in[5];
    const float* Wkv_down= (const float*)d_in[6];
    const float* Wkv_up  = (const float*)d_in[7];
    const float* Wo      = (const float*)d_in[8];
    float* out = (float*)d_out;

    float *ql, *ckv;
    cudaGetSymbolAddress((void**)&ql, g_ql);
    cudaGetSymbolAddress((void**)&ckv, g_ckv);
    U16 *hs_s, *wqd_s, *wqu_s, *wo_s, *wkvd_s;
    U16 *wkvup_h, *wkvup_l, *wabsT_h, *wabsT_l, *ql_s, *q_s;
    U16 *ckv_s, *ckvT_s, *qext_s, *sc_s, *out1_s, *out2_s;
    cudaGetSymbolAddress((void**)&hs_s, g_hs_s);
    cudaGetSymbolAddress((void**)&wqd_s, g_wqd_s);
    cudaGetSymbolAddress((void**)&wqu_s, g_wqu_s);
    cudaGetSymbolAddress((void**)&wo_s, g_wo_s);
    cudaGetSymbolAddress((void**)&wkvd_s, g_wkvd_s);
    cudaGetSymbolAddress((void**)&wkvup_h, g_wkvup_h); cudaGetSymbolAddress((void**)&wkvup_l, g_wkvup_l);
    cudaGetSymbolAddress((void**)&wabsT_h, g_wabsT_h); cudaGetSymbolAddress((void**)&wabsT_l, g_wabsT_l);
    cudaGetSymbolAddress((void**)&ql_s, g_ql_s);
    cudaGetSymbolAddress((void**)&q_s, g_q_s);
    cudaGetSymbolAddress((void**)&ckv_s, g_ckv_s);
    cudaGetSymbolAddress((void**)&ckvT_s, g_ckvT_s);
    cudaGetSymbolAddress((void**)&qext_s, g_qext_s);
    cudaGetSymbolAddress((void**)&sc_s, g_sc_s);
    cudaGetSymbolAddress((void**)&out1_s, g_out1_s);
    cudaGetSymbolAddress((void**)&out2_s, g_out2_s);

    const int M = BB * SS;
    const float scale = 1.0f / sqrtf((float)QHD);

    // input/weight preprocessing
    launch_tosingle(hs, hs_s, (long)BB * SS * HDIM);
    launch_tosingle(Wq_down, wqd_s, (long)QLORA_ * HDIM);
    launch_tosingle(Wq_up, wqu_s, (long)NHH * QHD * QLORA_);
    launch_tosingle(Wo, wo_s, (long)HDIM * HDIM);
    launch_tosingle(Wkv_down, wkvd_s, (long)QEXT * HDIM);
    launch_split(Wkv_up, wkvup_h, wkvup_l, (long)NHH * 256 * KVLORA_);
    transpose_wabs_kernel<<<(NHH * KVLORA_ * NOPE_ + 255) / 256, 256>>>(Wkv_up, wabsT_h, wabsT_l);

    // 1. ql = hs(s) @ Wq_down(s)^T [4096,1536] fp32
    launch_mma<1,1>(hs_s, hs_s, wqd_s, wqd_s, ql, 0,
                    M, QLORA_, HDIM, HDIM, HDIM, QLORA_, QLORA_,
                    0,0,0,0,0,0, 1, 1, 1.f, 0, 0, 0);
    // 2. RMSNorm -> ql single
    rmsnorm_kernel<<<M, 256>>>(ql, q_ln_w, ql_s);
    // 3. q = ql(s) @ Wq_up(s)^T [4096,3072] single out
    launch_mma<1,1>(ql_s, ql_s, wqu_s, wqu_s, 0, q_s,
                    M, NHH * QHD, QLORA_, QLORA_, QLORA_, NHH * QHD, NHH * QHD,
                    0,0,0,0,0,0, 1, 1, 1.f, 0, 0, 2);
    // 4. ckv = hs(s) @ Wkv_down(s)^T [4096,576] via Npad=640, fp32
    launch_mma<1,1>(hs_s, hs_s, wkvd_s, wkvd_s, ckv, 0,
                    M, 640, HDIM, HDIM, HDIM, QEXT, QEXT,
                    0,0,0,0,0,0, 1, 1, 1.f, 0, 0, 0);
    // 5. RoPE k (fp32 in place), single-convert + transpose
    rope_k_kernel<<<(BB * SS + 255) / 256, 256>>>(ckv, pos);
    launch_tosingle(ckv, ckv_s, (long)BB * SS * QEXT);
    {
        dim3 grid(SS / 32, KVLORA_ / 32, BB);
        transpose_ckv_kernel<<<grid, dim3(32, 8)>>>(ckv, ckvT_s);
    }
    // 6. RoPE q -> qext single cols 512:576
    rope_q_kernel<<<(BB * SS * NHH + 255) / 256, 256>>>(q_s, pos, qext_s);
    // 7. qext[:,0:512] = q(s) @ q_absorb(pair), single out
    launch_mma<1,0>(q_s, q_s, wabsT_h, wabsT_l, 0, qext_s,
                    SS, KVLORA_, NOPE_, NHH * QHD, NOPE_, QEXT, KVLORA_,
                    (long)SS * NHH * QHD, (long)QHD,
                    0, (long)KVLORA_ * NOPE_,
                    (long)NHH * SS * QEXT, (long)SS * QEXT,
                    NHH, BB * NHH, 1.f, 0, 0, 2);
    // 8. scores = scale * qext(s) @ ckv(s)^T, fp16 out, causal skip
    launch_mma<1,1>(qext_s, qext_s, ckv_s, ckv_s, 0, sc_s,
                    SS, SS, QEXT, QEXT, QEXT, SS, SS,
                    (long)NHH * SS * QEXT, (long)SS * QEXT,
                    (long)SS * QEXT, 0,
                    (long)NHH * SS * SS, (long)SS * SS,
                    NHH, BB * NHH, scale, 1, 0, 2);
    // 9. softmax in place (fp16 -> fp16 probs, zero-fill to causal block end)
    softmax_kernel<<<BB * NHH * SS, 256>>>(sc_s);
    // 10. out1 = probs(s) @ ckvT(s), causal K-limit, single out
    launch_mma<1,1>(sc_s, sc_s, ckvT_s, ckvT_s, 0, out1_s,
                    SS, KVLORA_, SS, SS, SS, KVLORA_, KVLORA_,
                    (long)NHH * SS * SS, (long)SS * SS,
                    (long)KVLORA_ * SS, 0,
                    (long)NHH * SS * KVLORA_, (long)SS * KVLORA_,
                    NHH, BB * NHH, 1.f, 0, 1, 2);
    // 11. out2 = out1(s) @ out_absorb(pair)^T, single out
    launch_mma<1,0>(out1_s, out1_s, wkvup_h + (long)NOPE_ * KVLORA_, wkvup_l + (long)NOPE_ * KVLORA_,
                    0, out2_s,
                    SS, VD_, KVLORA_, KVLORA_, KVLORA_, NHH * VD_, NHH * VD_,
                    (long)NHH * SS * KVLORA_, (long)SS * KVLORA_,
                    0, (long)256 * KVLORA_,
                    (long)SS * NHH * VD_, (long)VD_,
                    NHH, BB * NHH, 1.f, 0, 0, 2);
    // 12. final = out2(s) @ Wo(s)^T [4096,2048] fp32
    launch_mma<1,1>(out2_s, out2_s, wo_s, wo_s, out, 0,
                    M, HDIM, NHH * VD_, NHH * VD_, NHH * VD_, HDIM, HDIM,
                    0,0,0,0,0,0, 1, 1, 1.f, 0, 0, 0);
}

// round 11
// speedup vs baseline: 5.7757x; 1.0199x over previous
#include <cuda_runtime.h>
#include <cuda_fp16.h>
#include <math.h>
#include <stdint.h>

typedef unsigned short U16;

// ---------------- problem constants ----------------
#define NHH   16
#define NOPE_ 128
#define ROPED 64
#define VD_   128
#define QLORA_ 1536
#define KVLORA_ 512
#define HDIM  2048
#define BB    2
#define SS    2048
#define QEXT  576
#define QHD   (NOPE_ + ROPED)  // 192

// ---------------- scratch (all fp16) ----------------
__device__ U16 g_hs_s [(long)BB*SS*HDIM];
__device__ U16 g_wqd_s[(long)QLORA_*HDIM];
__device__ U16 g_wqu_s[(long)NHH*QHD*QLORA_];
__device__ U16 g_wo_s [(long)HDIM*HDIM];
__device__ U16 g_wkvd_s[(long)640*HDIM];                   // padded 576->640
__device__ U16 g_wkvup_s[(long)NHH*256*KVLORA_];
__device__ U16 g_wabsT_s[(long)NHH*KVLORA_*NOPE_];
__device__ U16 g_qlraw_s[(long)BB*SS*QLORA_];              // pre-rmsnorm
__device__ U16 g_ql_s [(long)BB*SS*QLORA_];                // post-rmsnorm
__device__ U16 g_q_s  [(long)BB*SS*NHH*QHD];
__device__ U16 g_ckv_s[(long)BB*SS*QEXT];                  // rope applied in place
__device__ U16 g_ckvT_s[(long)BB*KVLORA_*SS];
__device__ U16 g_qext_s[(long)BB*NHH*SS*QEXT];
__device__ U16 g_sc_s  [(long)BB*NHH*SS*SS];               // raw scores then probs, in place
__device__ U16 g_out1_s[(long)BB*NHH*SS*KVLORA_];
__device__ U16 g_out2_s[(long)BB*SS*NHH*VD_];

// ================= helpers =================
__device__ __forceinline__ uint32_t smem_u32(const void* p) {
    uint32_t a;
    asm("{ .reg .u64 t; cvta.to.shared.u64 t, %1; cvt.u32.u64 %0, t; }" : "=r"(a) : "l"(p));
    return a;
}
__device__ __forceinline__ void cp16(uint32_t dst, const void* src) {
    asm volatile("cp.async.cg.shared.global [%0], [%1], 16;" :: "r"(dst), "l"(src));
}
#define CP_COMMIT() asm volatile("cp.async.commit_group;" ::: "memory")
#define CP_WAIT1()  asm volatile("cp.async.wait_group 1;" ::: "memory")

__device__ __forceinline__ void ldmx4(uint32_t* r, uint32_t addr) {
    asm volatile("ldmatrix.sync.aligned.m8n8.x4.shared.b16 {%0,%1,%2,%3}, [%4];"
                 : "=r"(r[0]), "=r"(r[1]), "=r"(r[2]), "=r"(r[3]) : "r"(addr));
}
__device__ __forceinline__ void mma16816(float* d, const uint32_t* a, const uint32_t* b) {
    asm volatile("mma.sync.aligned.m16n8k16.row.col.f32.f16.f16.f32 "
                 "{%0,%1,%2,%3}, {%4,%5,%6,%7}, {%8,%9}, {%0,%1,%2,%3};"
                 : "+f"(d[0]), "+f"(d[1]), "+f"(d[2]), "+f"(d[3])
                 : "r"(a[0]), "r"(a[1]), "r"(a[2]), "r"(a[3]), "r"(b[0]), "r"(b[1]));
}
__device__ __forceinline__ U16 tohalf(float v) {
    return __half_as_ushort(__float2half_rn(v));
}
__device__ __forceinline__ float fromhalf(U16 v) {
    return __half2float(__ushort_as_half(v));
}

// ================= fp16 warp-MMA GEMM =================
// C = alpha * A @ B^T.  Row-major, elem ld.
// AS/BS: operand is single fp16 (1) or hi/lo pair (0).
// Block 128x128, BK=32, 3-stage cp.async pipeline, one sync per chunk,
// 8 warps (2x4).  outMode: 0 = fp32 C; 2 = single fp16 (Co).
#define ROWB 80
#define TILEB (128 * ROWB)     // 10240

extern __shared__ char dsmem[];

template<int AS, int BS>
__global__ void __launch_bounds__(256, 2)
mma_gemm(const U16* __restrict__ Ah, const U16* __restrict__ Al,
         const U16* __restrict__ Bh, const U16* __restrict__ Bl,
         float* __restrict__ C, U16* __restrict__ Co,
         int K, int lda, int ldb, int ldc, int ncols,
         long sAb, long sAhh, long sBb, long sBhh, long sCb, long sChh,
         int zh, float alpha, int causalSkip, int causalK, int outMode)
{
    constexpr int ATILES = AS ? 1 : 2;
    constexpr int BTILES = BS ? 1 : 2;
    constexpr int SGB = (ATILES + BTILES) * TILEB;

    int z = blockIdx.z;
    long ao = (long)(z / zh) * sAb + (long)(z % zh) * sAhh;
    long bo = (long)(z / zh) * sBb + (long)(z % zh) * sBhh;
    long co = (long)(z / zh) * sCb + (long)(z % zh) * sChh;
    int by = blockIdx.y, bx = blockIdx.x;
    if (causalSkip && bx * 128 > by * 128 + 127) return;
    int Klim = causalK ? min(K, by * 128 + 128) : K;
    int nCh = Klim >> 5;

    int tid = threadIdx.x;
    int lane = tid & 31, wid = tid >> 5;
    int wm = wid & 1, wn = wid >> 1;

    uint32_t sb = smem_u32(dsmem);

    const U16* gAh = Ah + ao + (long)(by * 128) * lda;
    const U16* gAl = AS ? gAh : (Al + ao + (long)(by * 128) * lda);
    const U16* gBh = Bh + bo + (long)(bx * 128) * ldb;
    const U16* gBl = BS ? gBh : (Bl + bo + (long)(bx * 128) * ldb);

    uint32_t aoff[4][2], boff[2][2];
    {
        int ar = wm * 64 + (lane & 15);
        int ak = (lane >> 4) << 3;
        #pragma unroll
        for (int mt = 0; mt < 4; mt++)
            #pragma unroll
            for (int kh = 0; kh < 2; kh++)
                aoff[mt][kh] = (uint32_t)((ar + mt * 16) * ROWB + ((ak + kh * 16) << 1));
        int br = wn * 32 + (lane & 7) + ((lane & 16) ? 8 : 0);
        int bk = (lane & 8) ? 8 : 0;
        #pragma unroll
        for (int np = 0; np < 2; np++)
            #pragma unroll
            for (int kh = 0; kh < 2; kh++)
                boff[np][kh] = (uint32_t)((br + np * 16) * ROWB + ((bk + kh * 16) << 1));
    }

    float acc[4][4][4];
    #pragma unroll
    for (int mt = 0; mt < 4; mt++)
        #pragma unroll
        for (int nt = 0; nt < 4; nt++)
            #pragma unroll
            for (int r = 0; r < 4; r++) acc[mt][nt][r] = 0.f;

    auto issue = [&](uint32_t sbase, int k0) {
        #pragma unroll
        for (int half = 0; half < 2; half++) {
            int idx = (half << 8) + tid;
            int row = idx >> 2;
            int e0  = (idx & 3) << 3;
            long aof = (long)row * lda + k0 + e0;
            long bof = (long)row * ldb + k0 + e0;
            uint32_t d = sbase + (uint32_t)(row * ROWB + (e0 << 1));
            cp16(d, gAh + aof);
            if (!AS) cp16(d + TILEB, gAl + aof);
            cp16(d + ATILES * TILEB, gBh + bof);
            if (!BS) cp16(d + (ATILES + 1) * TILEB, gBl + bof);
        }
    };

    issue(sb, 0);
    CP_COMMIT();
    if (nCh > 1) issue(sb + SGB, 32);
    CP_COMMIT();

    int sc = 0;
    for (int c = 0; c < nCh; c++) {
        CP_WAIT1();
        __syncthreads();
        if (c + 2 < nCh) {
            int sn = sc + 2; if (sn >= 3) sn -= 3;
            issue(sb + sn * SGB, (c + 2) << 5);
        }
        CP_COMMIT();

        uint32_t bufb = sb + sc * SGB;
        uint32_t sA_  = bufb;
        uint32_t sAl_ = bufb + TILEB;
        uint32_t sBh_ = bufb + ATILES * TILEB;
        uint32_t sBl_ = bufb + (ATILES + 1) * TILEB;

        #pragma unroll
        for (int kh = 0; kh < 2; kh++) {
            uint32_t ah[4][4], al[4][4], bh[2][4], bl[2][4];
            #pragma unroll
            for (int mt = 0; mt < 4; mt++) {
                ldmx4(ah[mt], sA_ + aoff[mt][kh]);
                if (!AS) ldmx4(al[mt], sAl_ + aoff[mt][kh]);
            }
            #pragma unroll
            for (int np = 0; np < 2; np++) {
                ldmx4(bh[np], sBh_ + boff[np][kh]);
                if (!BS) ldmx4(bl[np], sBl_ + boff[np][kh]);
            }
            #pragma unroll
            for (int mt = 0; mt < 4; mt++) {
                #pragma unroll
                for (int nt = 0; nt < 4; nt++) {
                    const uint32_t* bhp = &bh[nt >> 1][(nt & 1) << 1];
                    const uint32_t* blp = &bl[nt >> 1][(nt & 1) << 1];
                    mma16816(acc[mt][nt], ah[mt], bhp);
                    if (!BS) mma16816(acc[mt][nt], ah[mt], blp);
                    if (!AS) mma16816(acc[mt][nt], al[mt], bhp);
                }
            }
        }
        if (++sc == 3) sc = 0;
    }

    // epilogue
    #pragma unroll
    for (int mt = 0; mt < 4; mt++) {
        int r0 = by * 128 + wm * 64 + mt * 16 + (lane >> 2);
        #pragma unroll
        for (int nt = 0; nt < 4; nt++) {
            int c0 = bx * 128 + wn * 32 + nt * 8 + ((lane & 3) << 1);
            if (c0 >= ncols) continue;
            float v00 = alpha * acc[mt][nt][0], v01 = alpha * acc[mt][nt][1];
            float v10 = alpha * acc[mt][nt][2], v11 = alpha * acc[mt][nt][3];
            if (outMode == 0) {
                *(float2*)(C + co + (long)r0 * ldc + c0) = make_float2(v00, v01);
                *(float2*)(C + co + (long)(r0 + 8) * ldc + c0) = make_float2(v10, v11);
            } else {
                *(uint32_t*)(Co + co + (long)r0 * ldc + c0) =
                    (uint32_t)tohalf(v00) | ((uint32_t)tohalf(v01) << 16);
                *(uint32_t*)(Co + co + (long)(r0 + 8) * ldc + c0) =
                    (uint32_t)tohalf(v10) | ((uint32_t)tohalf(v11) << 16);
            }
        }
    }
}

// ---------------- fp32 -> single fp16 ----------------
__global__ void tosingle_kernel(const float* __restrict__ src, U16* __restrict__ o, long n)
{
    long i = ((long)blockIdx.x * 256 + threadIdx.x) * 4;
    if (i >= n) return;
    float4 v = *(const float4*)(src + i);
    uint2 ov;
    ov.x = (uint32_t)tohalf(v.x) | ((uint32_t)tohalf(v.y) << 16);
    ov.y = (uint32_t)tohalf(v.z) | ((uint32_t)tohalf(v.w) << 16);
    *(uint2*)(o + i) = ov;
}

// ---------------- RMSNorm (fp16 in, fp16 out, fp32 accumulation) ----------------
__global__ void rmsnorm_kernel(const U16* __restrict__ ql, const float* __restrict__ w,
                               U16* __restrict__ os)
{
    long ob = (long)blockIdx.x * QLORA_;
    int tid = threadIdx.x;
    __shared__ float vals[QLORA_];
    float s = 0.f;
    for (int i = tid; i < QLORA_; i += 256) {
        float v = fromhalf(ql[ob + i]);
        vals[i] = v;
        s += v * v;
    }
    __shared__ float red[256];
    red[tid] = s; __syncthreads();
    for (int st = 128; st > 0; st >>= 1) { if (tid < st) red[tid] += red[tid + st]; __syncthreads(); }
    float scale = rsqrtf(red[0] / (float)QLORA_ + 1e-6f);
    for (int i = tid; i < QLORA_; i += 256)
        os[ob + i] = tohalf(w[i] * (vals[i] * scale));
}

// ---------------- RoPE ----------------
__device__ __forceinline__ void rope_pair(float p, int i, float x0, float x1,
                                          float& o_lo, float& o_hi)
{
    double inv = exp(-((double)(2 * i) / 64.0) * 13.815510557964274);
    double ang = (double)p * inv;
    double sd, cd; sincos(ang, &sd, &cd);
    float cc = (float)cd, ss = (float)sd;
    o_lo = x0 * cc - x1 * ss;
    o_hi = x1 * cc + x0 * ss;
}

__global__ void rope_q_kernel(const U16* __restrict__ qs,
                              const int* __restrict__ pos, U16* __restrict__ es)
{
    int idx = blockIdx.x * blockDim.x + threadIdx.x;
    if (idx >= BB * SS * NHH) return;
    int h = idx % NHH;
    int bs = idx / NHH;
    int b = bs / SS, s_idx = bs % SS;
    float p = (float)pos[bs];
    long xb = ((long)bs * NHH + h) * QHD + NOPE_;
    long ob = ((long)(b * NHH + h) * SS + s_idx) * QEXT + KVLORA_;
    for (int i = 0; i < 32; i++) {
        float x0 = fromhalf(qs[xb + 2 * i]);
        float x1 = fromhalf(qs[xb + 2 * i + 1]);
        float lo, hi;
        rope_pair(p, i, x0, x1, lo, hi);
        es[ob + i] = tohalf(lo);
        es[ob + 32 + i] = tohalf(hi);
    }
}

__global__ void rope_k_kernel(U16* __restrict__ ckv, const int* __restrict__ pos)
{
    int bs = blockIdx.x * blockDim.x + threadIdx.x;
    if (bs >= BB * SS) return;
    float p = (float)pos[bs];
    U16* x = ckv + (long)bs * QEXT + KVLORA_;
    U16 tmp[64];
    for (int i = 0; i < 32; i++) {
        float lo, hi;
        rope_pair(p, i, fromhalf(x[2 * i]), fromhalf(x[2 * i + 1]), lo, hi);
        tmp[i] = tohalf(lo);
        tmp[32 + i] = tohalf(hi);
    }
    for (int j = 0; j < 64; j++) x[j] = tmp[j];
}

// ---------------- transposes ----------------
__global__ void transpose_wabs_kernel(const float* __restrict__ Wkv_up, U16* __restrict__ os)
{
    int idx = blockIdx.x * blockDim.x + threadIdx.x;
    if (idx >= NHH * KVLORA_ * NOPE_) return;
    int n = idx % NOPE_;
    int r = idx / NOPE_;
    int c = r % KVLORA_;
    int h = r / KVLORA_;
    os[idx] = tohalf(Wkv_up[((long)h * 256 + n) * KVLORA_ + c]);
}

__global__ void transpose_ckv_kernel(const U16* __restrict__ ckv, U16* __restrict__ os)
{
    __shared__ U16 t[32][33];
    int b = blockIdx.z;
    int s0 = blockIdx.x * 32, c0 = blockIdx.y * 32;
    int x = threadIdx.x, y = threadIdx.y;
    for (int i = y; i < 32; i += 8)
        t[i][x] = ckv[((long)b * SS + s0 + i) * QEXT + c0 + x];
    __syncthreads();
    for (int i = y; i < 32; i += 8)
        os[((long)b * KVLORA_ + c0 + i) * SS + s0 + x] = t[x][i];
}

// ---------------- causal softmax (fp16 in/out, in place) ----------------
__global__ void softmax_kernel(U16* __restrict__ sc)
{
    long row = blockIdx.x;
    int q = (int)(row % SS);
    long ob = row * (long)SS;
    int tid = threadIdx.x;
    int n = q + 1;
    int blockEnd = ((q >> 7) + 1) << 7;
    __shared__ float red[256];
    __shared__ float es[2048];

    float mx = -1e30f;
    for (int k = tid; k < n; k += 256) {
        float v = fromhalf(sc[ob + k]);
        es[k] = v;
        mx = fmaxf(mx, v);
    }
    red[tid] = mx; __syncthreads();
    for (int st = 128; st > 0; st >>= 1) { if (tid < st) red[tid] = fmaxf(red[tid], red[tid + st]); __syncthreads(); }
    mx = red[0]; __syncthreads();

    float sum = 0.f;
    for (int k = tid; k < n; k += 256) { float e = __expf(es[k] - mx); es[k] = e; sum += e; }
    red[tid] = sum; __syncthreads();
    for (int st = 128; st > 0; st >>= 1) { if (tid < st) red[tid] += red[tid + st]; __syncthreads(); }
    float inv = 1.f / red[0];

    for (int k = tid; k < n; k += 256) sc[ob + k] = tohalf(es[k] * inv);
    for (int k = n + tid; k < blockEnd; k += 256) sc[ob + k] = 0;
}

// ---------------- host ----------------
template<int AS, int BS>
static void launch_mma(const U16* Ah, const U16* Al, const U16* Bh, const U16* Bl,
                       float* C, U16* Co,
                       int M, int Npad, int K, int lda, int ldb, int ldc, int ncols,
                       long sAb, long sAh, long sBb, long sBh, long sCb, long sCh,
                       int zh, int zcount, float alpha, int cSkip, int cK, int outMode)
{
    constexpr int SMEM = 3 * ((AS ? 1 : 2) + (BS ? 1 : 2)) * TILEB;
    cudaFuncSetAttribute(mma_gemm<AS, BS>, cudaFuncAttributeMaxDynamicSharedMemorySize, SMEM);
    dim3 grid(Npad / 128, M / 128, zcount);
    mma_gemm<AS, BS><<<grid, 256, SMEM>>>(Ah, Al, Bh, Bl, C, Co,
        K, lda, ldb, ldc, ncols, sAb, sAh, sBb, sBh, sCb, sCh, zh, alpha, cSkip, cK, outMode);
}

static void launch_tosingle(const float* s, U16* o, long n)
{
    tosingle_kernel<<<(unsigned)((n / 4 + 255) / 256), 256>>>(s, o, n);
}

extern "C" void kernel_launch(void* const* d_in, const int* in_sizes, int n_in,
                              void* d_out, int out_size)
{
    const float* hs      = (const float*)d_in[0];
    const int*   pos     = (const int*)  d_in[1];
    const float* Wq_down = (const float*)d_in[3];
    const float* q_ln_w  = (const float*)d_in[4];
    const float* Wq_up   = (const float*)d_in[5];
    const float* Wkv_down= (const float*)d_in[6];
    const float* Wkv_up  = (const float*)d_in[7];
    const float* Wo      = (const float*)d_in[8];
    float* out = (float*)d_out;

    U16 *hs_s, *wqd_s, *wqu_s, *wo_s, *wkvd_s, *wkvup_s, *wabsT_s;
    U16 *qlraw_s, *ql_s, *q_s, *ckv_s, *ckvT_s, *qext_s, *sc_s, *out1_s, *out2_s;
    cudaGetSymbolAddress((void**)&hs_s, g_hs_s);
    cudaGetSymbolAddress((void**)&wqd_s, g_wqd_s);
    cudaGetSymbolAddress((void**)&wqu_s, g_wqu_s);
    cudaGetSymbolAddress((void**)&wo_s, g_wo_s);
    cudaGetSymbolAddress((void**)&wkvd_s, g_wkvd_s);
    cudaGetSymbolAddress((void**)&wkvup_s, g_wkvup_s);
    cudaGetSymbolAddress((void**)&wabsT_s, g_wabsT_s);
    cudaGetSymbolAddress((void**)&qlraw_s, g_qlraw_s);
    cudaGetSymbolAddress((void**)&ql_s, g_ql_s);
    cudaGetSymbolAddress((void**)&q_s, g_q_s);
    cudaGetSymbolAddress((void**)&ckv_s, g_ckv_s);
    cudaGetSymbolAddress((void**)&ckvT_s, g_ckvT_s);
    cudaGetSymbolAddress((void**)&qext_s, g_qext_s);
    cudaGetSymbolAddress((void**)&sc_s, g_sc_s);
    cudaGetSymbolAddress((void**)&out1_s, g_out1_s);
    cudaGetSymbolAddress((void**)&out2_s, g_out2_s);

    const int M = BB * SS;
    const float scale = 1.0f / sqrtf((float)QHD);

    // input/weight preprocessing (everything single fp16)
    launch_tosingle(hs, hs_s, (long)BB * SS * HDIM);
    launch_tosingle(Wq_down, wqd_s, (long)QLORA_ * HDIM);
    launch_tosingle(Wq_up, wqu_s, (long)NHH * QHD * QLORA_);
    launch_tosingle(Wo, wo_s, (long)HDIM * HDIM);
    launch_tosingle(Wkv_down, wkvd_s, (long)QEXT * HDIM);
    launch_tosingle(Wkv_up, wkvup_s, (long)NHH * 256 * KVLORA_);
    transpose_wabs_kernel<<<(NHH * KVLORA_ * NOPE_ + 255) / 256, 256>>>(Wkv_up, wabsT_s);

    // 1. ql = hs @ Wq_down^T [4096,1536] fp16 out
    launch_mma<1,1>(hs_s, hs_s, wqd_s, wqd_s, 0, qlraw_s,
                    M, QLORA_, HDIM, HDIM, HDIM, QLORA_, QLORA_,
                    0,0,0,0,0,0, 1, 1, 1.f, 0, 0, 2);
    // 2. RMSNorm (fp16 in, fp32 accum) -> ql fp16
    rmsnorm_kernel<<<M, 256>>>(qlraw_s, q_ln_w, ql_s);
    // 3. q = ql @ Wq_up^T [4096,3072] fp16 out
    launch_mma<1,1>(ql_s, ql_s, wqu_s, wqu_s, 0, q_s,
                    M, NHH * QHD, QLORA_, QLORA_, QLORA_, NHH * QHD, NHH * QHD,
                    0,0,0,0,0,0, 1, 1, 1.f, 0, 0, 2);
    // 4. ckv = hs @ Wkv_down^T [4096,576] via Npad=640, fp16 out
    launch_mma<1,1>(hs_s, hs_s, wkvd_s, wkvd_s, 0, ckv_s,
                    M, 640, HDIM, HDIM, HDIM, QEXT, QEXT,
                    0,0,0,0,0,0, 1, 1, 1.f, 0, 0, 2);
    // 5. RoPE k in place (fp16), then transpose
    rope_k_kernel<<<(BB * SS + 255) / 256, 256>>>(ckv_s, pos);
    {
        dim3 grid(SS / 32, KVLORA_ / 32, BB);
        transpose_ckv_kernel<<<grid, dim3(32, 8)>>>(ckv_s, ckvT_s);
    }
    // 6. RoPE q -> qext cols 512:576
    rope_q_kernel<<<(BB * SS * NHH + 255) / 256, 256>>>(q_s, pos, qext_s);
    // 7. qext[:,0:512] = q @ q_absorb (single x single)
    launch_mma<1,1>(q_s, q_s, wabsT_s, wabsT_s, 0, qext_s,
                    SS, KVLORA_, NOPE_, NHH * QHD, NOPE_, QEXT, KVLORA_,
                    (long)SS * NHH * QHD, (long)QHD,
                    0, (long)KVLORA_ * NOPE_,
                    (long)NHH * SS * QEXT, (long)SS * QEXT,
                    NHH, BB * NHH, 1.f, 0, 0, 2);
    // 8. scores = scale * qext @ ckv^T, fp16 out, causal skip
    launch_mma<1,1>(qext_s, qext_s, ckv_s, ckv_s, 0, sc_s,
                    SS, SS, QEXT, QEXT, QEXT, SS, SS,
                    (long)NHH * SS * QEXT, (long)SS * QEXT,
                    (long)SS * QEXT, 0,
                    (long)NHH * SS * SS, (long)SS * SS,
                    NHH, BB * NHH, scale, 1, 0, 2);
    // 9. softmax in place
    softmax_kernel<<<BB * NHH * SS, 256>>>(sc_s);
    // 10. out1 = probs @ ckvT, causal K-limit
    launch_mma<1,1>(sc_s, sc_s, ckvT_s, ckvT_s, 0, out1_s,
                    SS, KVLORA_, SS, SS, SS, KVLORA_, KVLORA_,
                    (long)NHH * SS * SS, (long)SS * SS,
                    (long)KVLORA_ * SS, 0,
                    (long)NHH * SS * KVLORA_, (long)SS * KVLORA_,
                    NHH, BB * NHH, 1.f, 0, 1, 2);
    // 11. out2 = out1 @ out_absorb^T (single x single)
    launch_mma<1,1>(out1_s, out1_s, wkvup_s + (long)NOPE_ * KVLORA_, wkvup_s + (long)NOPE_ * KVLORA_,
                    0, out2_s,
                    SS, VD_, KVLORA_, KVLORA_, KVLORA_, NHH * VD_, NHH * VD_,
                    (long)NHH * SS * KVLORA_, (long)SS * KVLORA_,
                    0, (long)256 * KVLORA_,
                    (long)SS * NHH * VD_, (long)VD_,
                    NHH, BB * NHH, 1.f, 0, 0, 2);
    // 12. final = out2 @ Wo^T [4096,2048] fp32 out
    launch_mma<1,1>(out2_s, out2_s, wo_s, wo_s, out, 0,
                    M, HDIM, NHH * VD_, NHH * VD_, NHH * VD_, HDIM, HDIM,
                    0,0,0,0,0,0, 1, 1, 1.f, 0, 0, 0);
}

// round 13
// speedup vs baseline: 6.1971x; 1.0730x over previous
#include <cuda_runtime.h>
#include <cuda_fp16.h>
#include <math.h>
#include <stdint.h>

typedef unsigned short U16;

// ---------------- problem constants ----------------
#define NHH   16
#define NOPE_ 128
#define ROPED 64
#define VD_   128
#define QLORA_ 1536
#define KVLORA_ 512
#define HDIM  2048
#define BB    2
#define SS    2048
#define QEXT  576
#define QHD   (NOPE_ + ROPED)  // 192

// ---------------- scratch (all fp16) ----------------
__device__ U16 g_hs_s [(long)BB*SS*HDIM];
__device__ U16 g_wqd_s[(long)QLORA_*HDIM];
__device__ U16 g_wqu_s[(long)NHH*QHD*QLORA_];
__device__ U16 g_wo_s [(long)HDIM*HDIM];
__device__ U16 g_wkvd_s[(long)640*HDIM];                   // padded 576->640
__device__ U16 g_wkvup_s[(long)NHH*256*KVLORA_];
__device__ U16 g_wabsT_s[(long)NHH*KVLORA_*NOPE_];
__device__ U16 g_qlraw_s[(long)BB*SS*QLORA_];
__device__ U16 g_ql_s [(long)BB*SS*QLORA_];
__device__ U16 g_q_s  [(long)BB*SS*NHH*QHD];
__device__ U16 g_ckv_s[(long)BB*SS*QEXT];
__device__ U16 g_ckvT_s[(long)BB*KVLORA_*SS];
__device__ U16 g_qext_s[(long)BB*NHH*SS*QEXT];
__device__ U16 g_sc_s  [(long)BB*NHH*SS*SS];
__device__ U16 g_out1_s[(long)BB*NHH*SS*KVLORA_];
__device__ U16 g_out2_s[(long)BB*SS*NHH*VD_];

// ================= helpers =================
__device__ __forceinline__ uint32_t smem_u32(const void* p) {
    uint32_t a;
    asm("{ .reg .u64 t; cvta.to.shared.u64 t, %1; cvt.u32.u64 %0, t; }" : "=r"(a) : "l"(p));
    return a;
}
__device__ __forceinline__ void cp16(uint32_t dst, const void* src) {
    asm volatile("cp.async.cg.shared.global [%0], [%1], 16;" :: "r"(dst), "l"(src));
}
#define CP_COMMIT() asm volatile("cp.async.commit_group;" ::: "memory")
#define CP_WAIT1()  asm volatile("cp.async.wait_group 1;" ::: "memory")

__device__ __forceinline__ void ldmx4(uint32_t* r, uint32_t addr) {
    asm volatile("ldmatrix.sync.aligned.m8n8.x4.shared.b16 {%0,%1,%2,%3}, [%4];"
                 : "=r"(r[0]), "=r"(r[1]), "=r"(r[2]), "=r"(r[3]) : "r"(addr));
}
__device__ __forceinline__ void mma16816(float* d, const uint32_t* a, const uint32_t* b) {
    asm volatile("mma.sync.aligned.m16n8k16.row.col.f32.f16.f16.f32 "
                 "{%0,%1,%2,%3}, {%4,%5,%6,%7}, {%8,%9}, {%0,%1,%2,%3};"
                 : "+f"(d[0]), "+f"(d[1]), "+f"(d[2]), "+f"(d[3])
                 : "r"(a[0]), "r"(a[1]), "r"(a[2]), "r"(a[3]), "r"(b[0]), "r"(b[1]));
}
__device__ __forceinline__ U16 tohalf(float v) {
    return __half_as_ushort(__float2half_rn(v));
}
__device__ __forceinline__ float fromhalf(U16 v) {
    return __half2float(__ushort_as_half(v));
}

// ================= fp16 warp-MMA GEMM (single x single) =================
// C = alpha * A @ B^T.  Row-major fp16, elem ld.
// Block 128x128, BK=64, 3-stage cp.async pipeline, ONE sync per chunk,
// 8 warps (2x4), 2 CTAs/SM.  outMode: 0 = fp32 C; 2 = fp16 (Co).
#define ROWB 144                 // 64 halves (128 B) + 16 B pad
#define TILEB (128 * ROWB)       // 18432
#define SGB   (2 * TILEB)        // 36864 (A + B tile)
#define MSMEM (3 * SGB)          // 110592

extern __shared__ char dsmem[];

__global__ void __launch_bounds__(256, 2)
mma_gemm(const U16* __restrict__ A, const U16* __restrict__ B,
         float* __restrict__ C, U16* __restrict__ Co,
         int K, int lda, int ldb, int ldc, int ncols,
         long sAb, long sAhh, long sBb, long sBhh, long sCb, long sChh,
         int zh, float alpha, int causalSkip, int causalK, int outMode)
{
    int z = blockIdx.z;
    long ao = (long)(z / zh) * sAb + (long)(z % zh) * sAhh;
    long bo = (long)(z / zh) * sBb + (long)(z % zh) * sBhh;
    long co = (long)(z / zh) * sCb + (long)(z % zh) * sChh;
    int by = blockIdx.y, bx = blockIdx.x;
    if (causalSkip && bx * 128 > by * 128 + 127) return;
    int Klim = causalK ? min(K, by * 128 + 128) : K;
    int nCh = Klim >> 6;                       // 64-K chunks

    int tid = threadIdx.x;
    int lane = tid & 31, wid = tid >> 5;
    int wm = wid & 1, wn = wid >> 1;

    uint32_t sb = smem_u32(dsmem);

    const U16* gA = A + ao + (long)(by * 128) * lda;
    const U16* gB = B + bo + (long)(bx * 128) * ldb;

    uint32_t aoff[4], boff[2];
    {
        int ar = wm * 64 + (lane & 15);
        int ak = (lane >> 4) << 3;
        #pragma unroll
        for (int mt = 0; mt < 4; mt++)
            aoff[mt] = (uint32_t)((ar + mt * 16) * ROWB + (ak << 1));
        int br = wn * 32 + (lane & 7) + ((lane & 16) ? 8 : 0);
        int bk = (lane & 8) ? 8 : 0;
        #pragma unroll
        for (int np = 0; np < 2; np++)
            boff[np] = (uint32_t)((br + np * 16) * ROWB + (bk << 1));
    }

    float acc[4][4][4];
    #pragma unroll
    for (int mt = 0; mt < 4; mt++)
        #pragma unroll
        for (int nt = 0; nt < 4; nt++)
            #pragma unroll
            for (int r = 0; r < 4; r++) acc[mt][nt][r] = 0.f;

    auto issue = [&](uint32_t sbase, int k0) {
        #pragma unroll
        for (int q = 0; q < 4; q++) {
            int idx = (q << 8) + tid;          // 0..1023
            int row = idx >> 3;
            int e0  = (idx & 7) << 3;
            uint32_t d = sbase + (uint32_t)(row * ROWB + (e0 << 1));
            cp16(d,         gA + (long)row * lda + k0 + e0);
            cp16(d + TILEB, gB + (long)row * ldb + k0 + e0);
        }
    };

    issue(sb, 0);
    CP_COMMIT();
    if (nCh > 1) issue(sb + SGB, 64);
    CP_COMMIT();

    int sc = 0;
    for (int c = 0; c < nCh; c++) {
        CP_WAIT1();
        __syncthreads();
        if (c + 2 < nCh) {
            int sn = sc + 2; if (sn >= 3) sn -= 3;
            issue(sb + sn * SGB, (c + 2) << 6);
        }
        CP_COMMIT();

        uint32_t sA_ = sb + sc * SGB;
        uint32_t sB_ = sA_ + TILEB;

        #pragma unroll
        for (int kh = 0; kh < 4; kh++) {
            uint32_t koffs = (uint32_t)(kh * 32);
            uint32_t ah[4][4], bh[2][4];
            #pragma unroll
            for (int mt = 0; mt < 4; mt++)
                ldmx4(ah[mt], sA_ + aoff[mt] + koffs);
            #pragma unroll
            for (int np = 0; np < 2; np++)
                ldmx4(bh[np], sB_ + boff[np] + koffs);
            #pragma unroll
            for (int mt = 0; mt < 4; mt++)
                #pragma unroll
                for (int nt = 0; nt < 4; nt++)
                    mma16816(acc[mt][nt], ah[mt], &bh[nt >> 1][(nt & 1) << 1]);
        }
        if (++sc == 3) sc = 0;
    }

    // epilogue
    #pragma unroll
    for (int mt = 0; mt < 4; mt++) {
        int r0 = by * 128 + wm * 64 + mt * 16 + (lane >> 2);
        #pragma unroll
        for (int nt = 0; nt < 4; nt++) {
            int c0 = bx * 128 + wn * 32 + nt * 8 + ((lane & 3) << 1);
            if (c0 >= ncols) continue;
            float v00 = alpha * acc[mt][nt][0], v01 = alpha * acc[mt][nt][1];
            float v10 = alpha * acc[mt][nt][2], v11 = alpha * acc[mt][nt][3];
            if (outMode == 0) {
                *(float2*)(C + co + (long)r0 * ldc + c0) = make_float2(v00, v01);
                *(float2*)(C + co + (long)(r0 + 8) * ldc + c0) = make_float2(v10, v11);
            } else {
                *(uint32_t*)(Co + co + (long)r0 * ldc + c0) =
                    (uint32_t)tohalf(v00) | ((uint32_t)tohalf(v01) << 16);
                *(uint32_t*)(Co + co + (long)(r0 + 8) * ldc + c0) =
                    (uint32_t)tohalf(v10) | ((uint32_t)tohalf(v11) << 16);
            }
        }
    }
}

// ---------------- fused multi-tensor fp32 -> fp16 convert ----------------
// Segment table passed BY VALUE (graph-capture safe; no memcpyToSymbol).
#define NSEG 6
struct SegTab {
    const float* src[NSEG];
    U16* dst[NSEG];
    long end[NSEG];    // cumulative float4 counts
};

__global__ void convert_all_kernel(SegTab t, long total4)
{
    long i4 = (long)blockIdx.x * 256 + threadIdx.x;
    if (i4 >= total4) return;
    int s = 0;
    #pragma unroll
    for (int k = 0; k < NSEG - 1; k++) s += (i4 >= t.end[k]);
    long base4 = s ? t.end[s - 1] : 0;
    long off = (i4 - base4) * 4;
    float4 v = *(const float4*)(t.src[s] + off);
    uint2 ov;
    ov.x = (uint32_t)tohalf(v.x) | ((uint32_t)tohalf(v.y) << 16);
    ov.y = (uint32_t)tohalf(v.z) | ((uint32_t)tohalf(v.w) << 16);
    *(uint2*)(t.dst[s] + off) = ov;
}

// ---------------- RMSNorm (fp16 in, fp16 out, fp32 accumulation) ----------------
__global__ void rmsnorm_kernel(const U16* __restrict__ ql, const float* __restrict__ w,
                               U16* __restrict__ os)
{
    long ob = (long)blockIdx.x * QLORA_;
    int tid = threadIdx.x;
    __shared__ float vals[QLORA_];
    float s = 0.f;
    for (int i = tid; i < QLORA_; i += 256) {
        float v = fromhalf(ql[ob + i]);
        vals[i] = v;
        s += v * v;
    }
    __shared__ float red[256];
    red[tid] = s; __syncthreads();
    for (int st = 128; st > 0; st >>= 1) { if (tid < st) red[tid] += red[tid + st]; __syncthreads(); }
    float scale = rsqrtf(red[0] / (float)QLORA_ + 1e-6f);
    for (int i = tid; i < QLORA_; i += 256)
        os[ob + i] = tohalf(w[i] * (vals[i] * scale));
}

// ---------------- RoPE ----------------
__device__ __forceinline__ void rope_pair(float p, int i, float x0, float x1,
                                          float& o_lo, float& o_hi)
{
    double inv = exp(-((double)(2 * i) / 64.0) * 13.815510557964274);
    double ang = (double)p * inv;
    double sd, cd; sincos(ang, &sd, &cd);
    float cc = (float)cd, ss = (float)sd;
    o_lo = x0 * cc - x1 * ss;
    o_hi = x1 * cc + x0 * ss;
}

__global__ void rope_q_kernel(const U16* __restrict__ qs,
                              const int* __restrict__ pos, U16* __restrict__ es)
{
    int idx = blockIdx.x * blockDim.x + threadIdx.x;
    if (idx >= BB * SS * NHH) return;
    int h = idx % NHH;
    int bs = idx / NHH;
    int b = bs / SS, s_idx = bs % SS;
    float p = (float)pos[bs];
    long xb = ((long)bs * NHH + h) * QHD + NOPE_;
    long ob = ((long)(b * NHH + h) * SS + s_idx) * QEXT + KVLORA_;
    for (int i = 0; i < 32; i++) {
        float lo, hi;
        rope_pair(p, i, fromhalf(qs[xb + 2 * i]), fromhalf(qs[xb + 2 * i + 1]), lo, hi);
        es[ob + i] = tohalf(lo);
        es[ob + 32 + i] = tohalf(hi);
    }
}

__global__ void rope_k_kernel(U16* __restrict__ ckv, const int* __restrict__ pos)
{
    int bs = blockIdx.x * blockDim.x + threadIdx.x;
    if (bs >= BB * SS) return;
    float p = (float)pos[bs];
    U16* x = ckv + (long)bs * QEXT + KVLORA_;
    U16 tmp[64];
    for (int i = 0; i < 32; i++) {
        float lo, hi;
        rope_pair(p, i, fromhalf(x[2 * i]), fromhalf(x[2 * i + 1]), lo, hi);
        tmp[i] = tohalf(lo);
        tmp[32 + i] = tohalf(hi);
    }
    for (int j = 0; j < 64; j++) x[j] = tmp[j];
}

// ---------------- transposes ----------------
__global__ void transpose_wabs_kernel(const float* __restrict__ Wkv_up, U16* __restrict__ os)
{
    int idx = blockIdx.x * blockDim.x + threadIdx.x;
    if (idx >= NHH * KVLORA_ * NOPE_) return;
    int n = idx % NOPE_;
    int r = idx / NOPE_;
    int c = r % KVLORA_;
    int h = r / KVLORA_;
    os[idx] = tohalf(Wkv_up[((long)h * 256 + n) * KVLORA_ + c]);
}

__global__ void transpose_ckv_kernel(const U16* __restrict__ ckv, U16* __restrict__ os)
{
    __shared__ U16 t[32][33];
    int b = blockIdx.z;
    int s0 = blockIdx.x * 32, c0 = blockIdx.y * 32;
    int x = threadIdx.x, y = threadIdx.y;
    for (int i = y; i < 32; i += 8)
        t[i][x] = ckv[((long)b * SS + s0 + i) * QEXT + c0 + x];
    __syncthreads();
    for (int i = y; i < 32; i += 8)
        os[((long)b * KVLORA_ + c0 + i) * SS + s0 + x] = t[x][i];
}

// ---------------- causal softmax (fp16 in/out, in place, warp-shuffle) ----------------
__global__ void softmax_kernel(U16* __restrict__ sc)
{
    long row = blockIdx.x;
    int q = (int)(row % SS);
    long ob = row * (long)SS;
    int tid = threadIdx.x;
    int lane = tid & 31, wid = tid >> 5;
    int n = q + 1;
    int blockEnd = ((q >> 7) + 1) << 7;
    __shared__ float wred[8];
    __shared__ float es[2048];

    float mx = -1e30f;
    for (int k = tid; k < n; k += 256) {
        float v = fromhalf(sc[ob + k]);
        es[k] = v;
        mx = fmaxf(mx, v);
    }
    #pragma unroll
    for (int o = 16; o > 0; o >>= 1) mx = fmaxf(mx, __shfl_xor_sync(0xffffffffu, mx, o));
    if (lane == 0) wred[wid] = mx;
    __syncthreads();
    mx = wred[lane & 7];
    #pragma unroll
    for (int o = 4; o > 0; o >>= 1) mx = fmaxf(mx, __shfl_xor_sync(0xffffffffu, mx, o));
    mx = __shfl_sync(0xffffffffu, mx, 0);

    float sum = 0.f;
    for (int k = tid; k < n; k += 256) { float e = __expf(es[k] - mx); es[k] = e; sum += e; }
    #pragma unroll
    for (int o = 16; o > 0; o >>= 1) sum += __shfl_xor_sync(0xffffffffu, sum, o);
    __syncthreads();
    if (lane == 0) wred[wid] = sum;
    __syncthreads();
    sum = wred[lane & 7];
    #pragma unroll
    for (int o = 4; o > 0; o >>= 1) sum += __shfl_xor_sync(0xffffffffu, sum, o);
    sum = __shfl_sync(0xffffffffu, sum, 0);
    float inv = 1.f / sum;

    for (int k = tid; k < n; k += 256) sc[ob + k] = tohalf(es[k] * inv);
    for (int k = n + tid; k < blockEnd; k += 256) sc[ob + k] = 0;
}

// ---------------- host ----------------
static void launch_mma(const U16* A, const U16* B, float* C, U16* Co,
                       int M, int Npad, int K, int lda, int ldb, int ldc, int ncols,
                       long sAb, long sAh, long sBb, long sBh, long sCb, long sCh,
                       int zh, int zcount, float alpha, int cSkip, int cK, int outMode)
{
    cudaFuncSetAttribute(mma_gemm, cudaFuncAttributeMaxDynamicSharedMemorySize, MSMEM);
    dim3 grid(Npad / 128, M / 128, zcount);
    mma_gemm<<<grid, 256, MSMEM>>>(A, B, C, Co,
        K, lda, ldb, ldc, ncols, sAb, sAh, sBb, sBh, sCb, sCh, zh, alpha, cSkip, cK, outMode);
}

extern "C" void kernel_launch(void* const* d_in, const int* in_sizes, int n_in,
                              void* d_out, int out_size)
{
    const float* hs      = (const float*)d_in[0];
    const int*   pos     = (const int*)  d_in[1];
    const float* Wq_down = (const float*)d_in[3];
    const float* q_ln_w  = (const float*)d_in[4];
    const float* Wq_up   = (const float*)d_in[5];
    const float* Wkv_down= (const float*)d_in[6];
    const float* Wkv_up  = (const float*)d_in[7];
    const float* Wo      = (const float*)d_in[8];
    float* out = (float*)d_out;

    U16 *hs_s, *wqd_s, *wqu_s, *wo_s, *wkvd_s, *wkvup_s, *wabsT_s;
    U16 *qlraw_s, *ql_s, *q_s, *ckv_s, *ckvT_s, *qext_s, *sc_s, *out1_s, *out2_s;
    cudaGetSymbolAddress((void**)&hs_s, g_hs_s);
    cudaGetSymbolAddress((void**)&wqd_s, g_wqd_s);
    cudaGetSymbolAddress((void**)&wqu_s, g_wqu_s);
    cudaGetSymbolAddress((void**)&wo_s, g_wo_s);
    cudaGetSymbolAddress((void**)&wkvd_s, g_wkvd_s);
    cudaGetSymbolAddress((void**)&wkvup_s, g_wkvup_s);
    cudaGetSymbolAddress((void**)&wabsT_s, g_wabsT_s);
    cudaGetSymbolAddress((void**)&qlraw_s, g_qlraw_s);
    cudaGetSymbolAddress((void**)&ql_s, g_ql_s);
    cudaGetSymbolAddress((void**)&q_s, g_q_s);
    cudaGetSymbolAddress((void**)&ckv_s, g_ckv_s);
    cudaGetSymbolAddress((void**)&ckvT_s, g_ckvT_s);
    cudaGetSymbolAddress((void**)&qext_s, g_qext_s);
    cudaGetSymbolAddress((void**)&sc_s, g_sc_s);
    cudaGetSymbolAddress((void**)&out1_s, g_out1_s);
    cudaGetSymbolAddress((void**)&out2_s, g_out2_s);

    const int M = BB * SS;
    const float scale = 1.0f / sqrtf((float)QHD);

    // fused preprocessing converts (6 tensors, one kernel, table by value)
    {
        SegTab t;
        const long sz[NSEG] = {
            (long)BB * SS * HDIM, (long)QLORA_ * HDIM, (long)NHH * QHD * QLORA_,
            (long)HDIM * HDIM, (long)QEXT * HDIM, (long)NHH * 256 * KVLORA_ };
        const float* srcs[NSEG] = { hs, Wq_down, Wq_up, Wo, Wkv_down, Wkv_up };
        U16* dsts[NSEG] = { hs_s, wqd_s, wqu_s, wo_s, wkvd_s, wkvup_s };
        long acc = 0;
        for (int i = 0; i < NSEG; i++) {
            t.src[i] = srcs[i];
            t.dst[i] = dsts[i];
            acc += sz[i] / 4;
            t.end[i] = acc;
        }
        convert_all_kernel<<<(unsigned)((acc + 255) / 256), 256>>>(t, acc);
    }
    transpose_wabs_kernel<<<(NHH * KVLORA_ * NOPE_ + 255) / 256, 256>>>(Wkv_up, wabsT_s);

    // 1. ql = hs @ Wq_down^T [4096,1536] fp16 out
    launch_mma(hs_s, wqd_s, 0, qlraw_s,
               M, QLORA_, HDIM, HDIM, HDIM, QLORA_, QLORA_,
               0,0,0,0,0,0, 1, 1, 1.f, 0, 0, 2);
    // 2. RMSNorm
    rmsnorm_kernel<<<M, 256>>>(qlraw_s, q_ln_w, ql_s);
    // 3. q = ql @ Wq_up^T [4096,3072] fp16 out
    launch_mma(ql_s, wqu_s, 0, q_s,
               M, NHH * QHD, QLORA_, QLORA_, QLORA_, NHH * QHD, NHH * QHD,
               0,0,0,0,0,0, 1, 1, 1.f, 0, 0, 2);
    // 4. ckv = hs @ Wkv_down^T [4096,576] via Npad=640, fp16 out
    launch_mma(hs_s, wkvd_s, 0, ckv_s,
               M, 640, HDIM, HDIM, HDIM, QEXT, QEXT,
               0,0,0,0,0,0, 1, 1, 1.f, 0, 0, 2);
    // 5. RoPE k in place, then transpose
    rope_k_kernel<<<(BB * SS + 255) / 256, 256>>>(ckv_s, pos);
    {
        dim3 grid(SS / 32, KVLORA_ / 32, BB);
        transpose_ckv_kernel<<<grid, dim3(32, 8)>>>(ckv_s, ckvT_s);
    }
    // 6. RoPE q -> qext cols 512:576
    rope_q_kernel<<<(BB * SS * NHH + 255) / 256, 256>>>(q_s, pos, qext_s);
    // 7. qext[:,0:512] = q @ q_absorb
    launch_mma(q_s, wabsT_s, 0, qext_s,
               SS, KVLORA_, NOPE_, NHH * QHD, NOPE_, QEXT, KVLORA_,
               (long)SS * NHH * QHD, (long)QHD,
               0, (long)KVLORA_ * NOPE_,
               (long)NHH * SS * QEXT, (long)SS * QEXT,
               NHH, BB * NHH, 1.f, 0, 0, 2);
    // 8. scores = scale * qext @ ckv^T, fp16 out, causal skip
    launch_mma(qext_s, ckv_s, 0, sc_s,
               SS, SS, QEXT, QEXT, QEXT, SS, SS,
               (long)NHH * SS * QEXT, (long)SS * QEXT,
               (long)SS * QEXT, 0,
               (long)NHH * SS * SS, (long)SS * SS,
               NHH, BB * NHH, scale, 1, 0, 2);
    // 9. softmax in place
    softmax_kernel<<<BB * NHH * SS, 256>>>(sc_s);
    // 10. out1 = probs @ ckvT, causal K-limit
    launch_mma(sc_s, ckvT_s, 0, out1_s,
               SS, KVLORA_, SS, SS, SS, KVLORA_, KVLORA_,
               (long)NHH * SS * SS, (long)SS * SS,
               (long)KVLORA_ * SS, 0,
               (long)NHH * SS * KVLORA_, (long)SS * KVLORA_,
               NHH, BB * NHH, 1.f, 0, 1, 2);
    // 11. out2 = out1 @ out_absorb^T
    launch_mma(out1_s, wkvup_s + (long)NOPE_ * KVLORA_, 0, out2_s,
               SS, VD_, KVLORA_, KVLORA_, KVLORA_, NHH * VD_, NHH * VD_,
               (long)NHH * SS * KVLORA_, (long)SS * KVLORA_,
               0, (long)256 * KVLORA_,
               (long)SS * NHH * VD_, (long)VD_,
               NHH, BB * NHH, 1.f, 0, 0, 2);
    // 12. final = out2 @ Wo^T [4096,2048] fp32 out
    launch_mma(out2_s, wo_s, out, 0,
               M, HDIM, NHH * VD_, NHH * VD_, NHH * VD_, HDIM, HDIM,
               0,0,0,0,0,0, 1, 1, 1.f, 0, 0, 0);
}

// round 14
// speedup vs baseline: 7.6938x; 1.2415x over previous
#include <cuda_runtime.h>
#include <cuda_fp16.h>
#include <math.h>
#include <stdint.h>

typedef unsigned short U16;

// ---------------- problem constants ----------------
#define NHH   16
#define NOPE_ 128
#define ROPED 64
#define VD_   128
#define QLORA_ 1536
#define KVLORA_ 512
#define HDIM  2048
#define BB    2
#define SS    2048
#define QEXT  576
#define QHD   (NOPE_ + ROPED)  // 192
#define NCOMB 2176             // 1536 (ql) + 640 (ckv padded)
#define NVALID 2112            // 1536 + 576

// ---------------- scratch (all fp16) ----------------
__device__ U16 g_hs_s [(long)BB*SS*HDIM];
__device__ U16 g_wcomb_s[(long)NCOMB*HDIM];                // Wq_down rows 0..1535, Wkv_down rows 1536..2111, pad zero
__device__ U16 g_wqu_s[(long)NHH*QHD*QLORA_];
__device__ U16 g_wo_s [(long)HDIM*HDIM];
__device__ U16 g_wkvup_s[(long)NHH*256*KVLORA_];
__device__ U16 g_wabsT_s[(long)NHH*KVLORA_*NOPE_];
__device__ U16 g_qlckv_s[(long)BB*SS*NCOMB];               // cols 0..1535 raw ql, 1536..2111 ckv
__device__ U16 g_ql_s [(long)BB*SS*QLORA_];                // post-rmsnorm
__device__ U16 g_q_s  [(long)BB*SS*NHH*QHD];
__device__ U16 g_ckvT_s[(long)BB*KVLORA_*SS];
__device__ U16 g_qext_s[(long)BB*NHH*SS*QEXT];
__device__ U16 g_sc_s  [(long)BB*NHH*SS*SS];
__device__ U16 g_out1_s[(long)BB*NHH*SS*KVLORA_];
__device__ U16 g_out2_s[(long)BB*SS*NHH*VD_];

// ================= helpers =================
__device__ __forceinline__ uint32_t smem_u32(const void* p) {
    uint32_t a;
    asm("{ .reg .u64 t; cvta.to.shared.u64 t, %1; cvt.u32.u64 %0, t; }" : "=r"(a) : "l"(p));
    return a;
}
__device__ __forceinline__ void cp16(uint32_t dst, const void* src) {
    asm volatile("cp.async.cg.shared.global [%0], [%1], 16;" :: "r"(dst), "l"(src));
}
#define CP_COMMIT() asm volatile("cp.async.commit_group;" ::: "memory")
#define CP_WAIT1()  asm volatile("cp.async.wait_group 1;" ::: "memory")

__device__ __forceinline__ void ldmx4(uint32_t* r, uint32_t addr) {
    asm volatile("ldmatrix.sync.aligned.m8n8.x4.shared.b16 {%0,%1,%2,%3}, [%4];"
                 : "=r"(r[0]), "=r"(r[1]), "=r"(r[2]), "=r"(r[3]) : "r"(addr));
}
__device__ __forceinline__ void mma16816(float* d, const uint32_t* a, const uint32_t* b) {
    asm volatile("mma.sync.aligned.m16n8k16.row.col.f32.f16.f16.f32 "
                 "{%0,%1,%2,%3}, {%4,%5,%6,%7}, {%8,%9}, {%0,%1,%2,%3};"
                 : "+f"(d[0]), "+f"(d[1]), "+f"(d[2]), "+f"(d[3])
                 : "r"(a[0]), "r"(a[1]), "r"(a[2]), "r"(a[3]), "r"(b[0]), "r"(b[1]));
}
__device__ __forceinline__ U16 tohalf(float v) {
    return __half_as_ushort(__float2half_rn(v));
}
__device__ __forceinline__ float fromhalf(U16 v) {
    return __half2float(__ushort_as_half(v));
}

// ================= fp16 warp-MMA GEMM (single x single) =================
// C = alpha * A @ B^T.  Row-major fp16, elem ld.
// Block 128x128, BK=64, 3-stage cp.async pipeline, one sync per chunk,
// 8 warps (2x4), 2 CTAs/SM.  outMode: 0 = fp32 C; 2 = fp16 (Co).
#define ROWB 144                 // 64 halves (128 B) + 16 B pad
#define TILEB (128 * ROWB)       // 18432
#define SGB   (2 * TILEB)        // 36864
#define MSMEM (3 * SGB)          // 110592

extern __shared__ char dsmem[];

__global__ void __launch_bounds__(256, 2)
mma_gemm(const U16* __restrict__ A, const U16* __restrict__ B,
         float* __restrict__ C, U16* __restrict__ Co,
         int K, int lda, int ldb, int ldc, int ncols,
         long sAb, long sAhh, long sBb, long sBhh, long sCb, long sChh,
         int zh, float alpha, int causalSkip, int causalK, int outMode)
{
    int z = blockIdx.z;
    long ao = (long)(z / zh) * sAb + (long)(z % zh) * sAhh;
    long bo = (long)(z / zh) * sBb + (long)(z % zh) * sBhh;
    long co = (long)(z / zh) * sCb + (long)(z % zh) * sChh;
    int by = blockIdx.y, bx = blockIdx.x;
    if (causalSkip && bx * 128 > by * 128 + 127) return;
    int Klim = causalK ? min(K, by * 128 + 128) : K;
    int nCh = Klim >> 6;

    int tid = threadIdx.x;
    int lane = tid & 31, wid = tid >> 5;
    int wm = wid & 1, wn = wid >> 1;

    uint32_t sb = smem_u32(dsmem);

    const U16* gA = A + ao + (long)(by * 128) * lda;
    const U16* gB = B + bo + (long)(bx * 128) * ldb;

    uint32_t aoff[4], boff[2];
    {
        int ar = wm * 64 + (lane & 15);
        int ak = (lane >> 4) << 3;
        #pragma unroll
        for (int mt = 0; mt < 4; mt++)
            aoff[mt] = (uint32_t)((ar + mt * 16) * ROWB + (ak << 1));
        int br = wn * 32 + (lane & 7) + ((lane & 16) ? 8 : 0);
        int bk = (lane & 8) ? 8 : 0;
        #pragma unroll
        for (int np = 0; np < 2; np++)
            boff[np] = (uint32_t)((br + np * 16) * ROWB + (bk << 1));
    }

    float acc[4][4][4];
    #pragma unroll
    for (int mt = 0; mt < 4; mt++)
        #pragma unroll
        for (int nt = 0; nt < 4; nt++)
            #pragma unroll
            for (int r = 0; r < 4; r++) acc[mt][nt][r] = 0.f;

    auto issue = [&](uint32_t sbase, int k0) {
        #pragma unroll
        for (int q = 0; q < 4; q++) {
            int idx = (q << 8) + tid;
            int row = idx >> 3;
            int e0  = (idx & 7) << 3;
            uint32_t d = sbase + (uint32_t)(row * ROWB + (e0 << 1));
            cp16(d,         gA + (long)row * lda + k0 + e0);
            cp16(d + TILEB, gB + (long)row * ldb + k0 + e0);
        }
    };

    issue(sb, 0);
    CP_COMMIT();
    if (nCh > 1) issue(sb + SGB, 64);
    CP_COMMIT();

    int sc = 0;
    for (int c = 0; c < nCh; c++) {
        CP_WAIT1();
        __syncthreads();
        if (c + 2 < nCh) {
            int sn = sc + 2; if (sn >= 3) sn -= 3;
            issue(sb + sn * SGB, (c + 2) << 6);
        }
        CP_COMMIT();

        uint32_t sA_ = sb + sc * SGB;
        uint32_t sB_ = sA_ + TILEB;

        #pragma unroll
        for (int kh = 0; kh < 4; kh++) {
            uint32_t koffs = (uint32_t)(kh * 32);
            uint32_t ah[4][4], bh[2][4];
            #pragma unroll
            for (int mt = 0; mt < 4; mt++)
                ldmx4(ah[mt], sA_ + aoff[mt] + koffs);
            #pragma unroll
            for (int np = 0; np < 2; np++)
                ldmx4(bh[np], sB_ + boff[np] + koffs);
            #pragma unroll
            for (int mt = 0; mt < 4; mt++)
                #pragma unroll
                for (int nt = 0; nt < 4; nt++)
                    mma16816(acc[mt][nt], ah[mt], &bh[nt >> 1][(nt & 1) << 1]);
        }
        if (++sc == 3) sc = 0;
    }

    // epilogue
    #pragma unroll
    for (int mt = 0; mt < 4; mt++) {
        int r0 = by * 128 + wm * 64 + mt * 16 + (lane >> 2);
        #pragma unroll
        for (int nt = 0; nt < 4; nt++) {
            int c0 = bx * 128 + wn * 32 + nt * 8 + ((lane & 3) << 1);
            if (c0 >= ncols) continue;
            float v00 = alpha * acc[mt][nt][0], v01 = alpha * acc[mt][nt][1];
            float v10 = alpha * acc[mt][nt][2], v11 = alpha * acc[mt][nt][3];
            if (outMode == 0) {
                *(float2*)(C + co + (long)r0 * ldc + c0) = make_float2(v00, v01);
                *(float2*)(C + co + (long)(r0 + 8) * ldc + c0) = make_float2(v10, v11);
            } else {
                *(uint32_t*)(Co + co + (long)r0 * ldc + c0) =
                    (uint32_t)tohalf(v00) | ((uint32_t)tohalf(v01) << 16);
                *(uint32_t*)(Co + co + (long)(r0 + 8) * ldc + c0) =
                    (uint32_t)tohalf(v10) | ((uint32_t)tohalf(v11) << 16);
            }
        }
    }
}

// ---------------- fused multi-tensor fp32 -> fp16 convert (table by value) ----------------
#define NSEG 6
struct SegTab {
    const float* src[NSEG];
    U16* dst[NSEG];
    long end[NSEG];
};

__global__ void convert_all_kernel(SegTab t, long total4)
{
    long i4 = (long)blockIdx.x * 256 + threadIdx.x;
    if (i4 >= total4) return;
    int s = 0;
    #pragma unroll
    for (int k = 0; k < NSEG - 1; k++) s += (i4 >= t.end[k]);
    long base4 = s ? t.end[s - 1] : 0;
    long off = (i4 - base4) * 4;
    float4 v = *(const float4*)(t.src[s] + off);
    uint2 ov;
    ov.x = (uint32_t)tohalf(v.x) | ((uint32_t)tohalf(v.y) << 16);
    ov.y = (uint32_t)tohalf(v.z) | ((uint32_t)tohalf(v.w) << 16);
    *(uint2*)(t.dst[s] + off) = ov;
}

// ---------------- RMSNorm (fp16 in from combined buffer, fp16 out) ----------------
__global__ void rmsnorm_kernel(const U16* __restrict__ qlckv, const float* __restrict__ w,
                               U16* __restrict__ os)
{
    long ib = (long)blockIdx.x * NCOMB;
    long ob = (long)blockIdx.x * QLORA_;
    int tid = threadIdx.x;
    __shared__ float vals[QLORA_];
    float s = 0.f;
    for (int i = tid; i < QLORA_; i += 256) {
        float v = fromhalf(qlckv[ib + i]);
        vals[i] = v;
        s += v * v;
    }
    __shared__ float red[256];
    red[tid] = s; __syncthreads();
    for (int st = 128; st > 0; st >>= 1) { if (tid < st) red[tid] += red[tid + st]; __syncthreads(); }
    float scale = rsqrtf(red[0] / (float)QLORA_ + 1e-6f);
    for (int i = tid; i < QLORA_; i += 256)
        os[ob + i] = tohalf(w[i] * (vals[i] * scale));
}

// ---------------- RoPE (fp32 sincos on fp32-rounded angle; double inv_freq table) ----------------
__device__ __forceinline__ void build_invfreq(float* inv)
{
    if (threadIdx.x < 32)
        inv[threadIdx.x] = (float)exp(-((double)(2 * threadIdx.x) / 64.0) * 13.815510557964274);
    __syncthreads();
}

__global__ void rope_q_kernel(const U16* __restrict__ qs,
                              const int* __restrict__ pos, U16* __restrict__ es)
{
    __shared__ float invf[32];
    build_invfreq(invf);
    int idx = blockIdx.x * blockDim.x + threadIdx.x;
    if (idx >= BB * SS * NHH) return;
    int h = idx % NHH;
    int bs = idx / NHH;
    int b = bs / SS, s_idx = bs % SS;
    float p = (float)pos[bs];
    long xb = ((long)bs * NHH + h) * QHD + NOPE_;
    long ob = ((long)(b * NHH + h) * SS + s_idx) * QEXT + KVLORA_;
    #pragma unroll 8
    for (int i = 0; i < 32; i++) {
        float ang = p * invf[i];
        float sn, cs;
        sincosf(ang, &sn, &cs);
        float x0 = fromhalf(qs[xb + 2 * i]);
        float x1 = fromhalf(qs[xb + 2 * i + 1]);
        es[ob + i]      = tohalf(x0 * cs - x1 * sn);
        es[ob + 32 + i] = tohalf(x1 * cs + x0 * sn);
    }
}

// rope_k operates on combined buffer: row ld = NCOMB, rope region at col 2048 (1536+512)
__global__ void rope_k_kernel(U16* __restrict__ qlckv, const int* __restrict__ pos)
{
    __shared__ float invf[32];
    build_invfreq(invf);
    int bs = blockIdx.x * blockDim.x + threadIdx.x;
    if (bs >= BB * SS) return;
    float p = (float)pos[bs];
    U16* x = qlckv + (long)bs * NCOMB + QLORA_ + KVLORA_;
    U16 tmp[64];
    #pragma unroll 8
    for (int i = 0; i < 32; i++) {
        float ang = p * invf[i];
        float sn, cs;
        sincosf(ang, &sn, &cs);
        float x0 = fromhalf(x[2 * i]);
        float x1 = fromhalf(x[2 * i + 1]);
        tmp[i]      = tohalf(x0 * cs - x1 * sn);
        tmp[32 + i] = tohalf(x1 * cs + x0 * sn);
    }
    for (int j = 0; j < 64; j++) x[j] = tmp[j];
}

// ---------------- transposes ----------------
__global__ void transpose_wabs_kernel(const float* __restrict__ Wkv_up, U16* __restrict__ os)
{
    int idx = blockIdx.x * blockDim.x + threadIdx.x;
    if (idx >= NHH * KVLORA_ * NOPE_) return;
    int n = idx % NOPE_;
    int r = idx / NOPE_;
    int c = r % KVLORA_;
    int h = r / KVLORA_;
    os[idx] = tohalf(Wkv_up[((long)h * 256 + n) * KVLORA_ + c]);
}

// reads ckv columns (0..511) out of combined buffer (offset 1536, ld NCOMB)
__global__ void transpose_ckv_kernel(const U16* __restrict__ qlckv, U16* __restrict__ os)
{
    __shared__ U16 t[32][33];
    int b = blockIdx.z;
    int s0 = blockIdx.x * 32, c0 = blockIdx.y * 32;
    int x = threadIdx.x, y = threadIdx.y;
    for (int i = y; i < 32; i += 8)
        t[i][x] = qlckv[((long)b * SS + s0 + i) * NCOMB + QLORA_ + c0 + x];
    __syncthreads();
    for (int i = y; i < 32; i += 8)
        os[((long)b * KVLORA_ + c0 + i) * SS + s0 + x] = t[x][i];
}

// ---------------- causal softmax (fp16 in/out, in place, warp-shuffle) ----------------
__global__ void softmax_kernel(U16* __restrict__ sc)
{
    long row = blockIdx.x;
    int q = (int)(row % SS);
    long ob = row * (long)SS;
    int tid = threadIdx.x;
    int lane = tid & 31, wid = tid >> 5;
    int n = q + 1;
    int blockEnd = ((q >> 7) + 1) << 7;
    __shared__ float wred[8];
    __shared__ float es[2048];

    float mx = -1e30f;
    for (int k = tid; k < n; k += 256) {
        float v = fromhalf(sc[ob + k]);
        es[k] = v;
        mx = fmaxf(mx, v);
    }
    #pragma unroll
    for (int o = 16; o > 0; o >>= 1) mx = fmaxf(mx, __shfl_xor_sync(0xffffffffu, mx, o));
    if (lane == 0) wred[wid] = mx;
    __syncthreads();
    mx = wred[lane & 7];
    #pragma unroll
    for (int o = 4; o > 0; o >>= 1) mx = fmaxf(mx, __shfl_xor_sync(0xffffffffu, mx, o));
    mx = __shfl_sync(0xffffffffu, mx, 0);

    float sum = 0.f;
    for (int k = tid; k < n; k += 256) { float e = __expf(es[k] - mx); es[k] = e; sum += e; }
    #pragma unroll
    for (int o = 16; o > 0; o >>= 1) sum += __shfl_xor_sync(0xffffffffu, sum, o);
    __syncthreads();
    if (lane == 0) wred[wid] = sum;
    __syncthreads();
    sum = wred[lane & 7];
    #pragma unroll
    for (int o = 4; o > 0; o >>= 1) sum += __shfl_xor_sync(0xffffffffu, sum, o);
    sum = __shfl_sync(0xffffffffu, sum, 0);
    float inv = 1.f / sum;

    for (int k = tid; k < n; k += 256) sc[ob + k] = tohalf(es[k] * inv);
    for (int k = n + tid; k < blockEnd; k += 256) sc[ob + k] = 0;
}

// ---------------- host ----------------
static void launch_mma(const U16* A, const U16* B, float* C, U16* Co,
                       int M, int Npad, int K, int lda, int ldb, int ldc, int ncols,
                       long sAb, long sAh, long sBb, long sBh, long sCb, long sCh,
                       int zh, int zcount, float alpha, int cSkip, int cK, int outMode)
{
    cudaFuncSetAttribute(mma_gemm, cudaFuncAttributeMaxDynamicSharedMemorySize, MSMEM);
    dim3 grid(Npad / 128, M / 128, zcount);
    mma_gemm<<<grid, 256, MSMEM>>>(A, B, C, Co,
        K, lda, ldb, ldc, ncols, sAb, sAh, sBb, sBh, sCb, sCh, zh, alpha, cSkip, cK, outMode);
}

extern "C" void kernel_launch(void* const* d_in, const int* in_sizes, int n_in,
                              void* d_out, int out_size)
{
    const float* hs      = (const float*)d_in[0];
    const int*   pos     = (const int*)  d_in[1];
    const float* Wq_down = (const float*)d_in[3];
    const float* q_ln_w  = (const float*)d_in[4];
    const float* Wq_up   = (const float*)d_in[5];
    const float* Wkv_down= (const float*)d_in[6];
    const float* Wkv_up  = (const float*)d_in[7];
    const float* Wo      = (const float*)d_in[8];
    float* out = (float*)d_out;

    U16 *hs_s, *wcomb_s, *wqu_s, *wo_s, *wkvup_s, *wabsT_s;
    U16 *qlckv_s, *ql_s, *q_s, *ckvT_s, *qext_s, *sc_s, *out1_s, *out2_s;
    cudaGetSymbolAddress((void**)&hs_s, g_hs_s);
    cudaGetSymbolAddress((void**)&wcomb_s, g_wcomb_s);
    cudaGetSymbolAddress((void**)&wqu_s, g_wqu_s);
    cudaGetSymbolAddress((void**)&wo_s, g_wo_s);
    cudaGetSymbolAddress((void**)&wkvup_s, g_wkvup_s);
    cudaGetSymbolAddress((void**)&wabsT_s, g_wabsT_s);
    cudaGetSymbolAddress((void**)&qlckv_s, g_qlckv_s);
    cudaGetSymbolAddress((void**)&ql_s, g_ql_s);
    cudaGetSymbolAddress((void**)&q_s, g_q_s);
    cudaGetSymbolAddress((void**)&ckvT_s, g_ckvT_s);
    cudaGetSymbolAddress((void**)&qext_s, g_qext_s);
    cudaGetSymbolAddress((void**)&sc_s, g_sc_s);
    cudaGetSymbolAddress((void**)&out1_s, g_out1_s);
    cudaGetSymbolAddress((void**)&out2_s, g_out2_s);

    const int M = BB * SS;
    const float scale = 1.0f / sqrtf((float)QHD);

    // fused preprocessing: Wq_down -> wcomb rows 0..1535, Wkv_down -> wcomb rows 1536..2111
    {
        SegTab t;
        const long sz[NSEG] = {
            (long)BB * SS * HDIM, (long)QLORA_ * HDIM, (long)QEXT * HDIM,
            (long)NHH * QHD * QLORA_, (long)HDIM * HDIM, (long)NHH * 256 * KVLORA_ };
        const float* srcs[NSEG] = { hs, Wq_down, Wkv_down, Wq_up, Wo, Wkv_up };
        U16* dsts[NSEG] = { hs_s, wcomb_s, wcomb_s + (long)QLORA_ * HDIM, wqu_s, wo_s, wkvup_s };
        long acc = 0;
        for (int i = 0; i < NSEG; i++) {
            t.src[i] = srcs[i];
            t.dst[i] = dsts[i];
            acc += sz[i] / 4;
            t.end[i] = acc;
        }
        convert_all_kernel<<<(unsigned)((acc + 255) / 256), 256>>>(t, acc);
    }
    transpose_wabs_kernel<<<(NHH * KVLORA_ * NOPE_ + 255) / 256, 256>>>(Wkv_up, wabsT_s);

    // 1. [ql | ckv] = hs @ [Wq_down | Wkv_down]^T   [4096, 2176], fp16 out
    launch_mma(hs_s, wcomb_s, 0, qlckv_s,
               M, NCOMB, HDIM, HDIM, HDIM, NCOMB, NVALID,
               0,0,0,0,0,0, 1, 1, 1.f, 0, 0, 2);
    // 2. RMSNorm on ql part
    rmsnorm_kernel<<<M, 256>>>(qlckv_s, q_ln_w, ql_s);
    // 3. q = ql @ Wq_up^T [4096,3072] fp16 out
    launch_mma(ql_s, wqu_s, 0, q_s,
               M, NHH * QHD, QLORA_, QLORA_, QLORA_, NHH * QHD, NHH * QHD,
               0,0,0,0,0,0, 1, 1, 1.f, 0, 0, 2);
    // 4. RoPE k in place (combined buffer), then transpose ckv
    rope_k_kernel<<<(BB * SS + 255) / 256, 256>>>(qlckv_s, pos);
    {
        dim3 grid(SS / 32, KVLORA_ / 32, BB);
        transpose_ckv_kernel<<<grid, dim3(32, 8)>>>(qlckv_s, ckvT_s);
    }
    // 5. RoPE q -> qext cols 512:576
    rope_q_kernel<<<(BB * SS * NHH + 255) / 256, 256>>>(q_s, pos, qext_s);
    // 6. qext[:,0:512] = q @ q_absorb
    launch_mma(q_s, wabsT_s, 0, qext_s,
               SS, KVLORA_, NOPE_, NHH * QHD, NOPE_, QEXT, KVLORA_,
               (long)SS * NHH * QHD, (long)QHD,
               0, (long)KVLORA_ * NOPE_,
               (long)NHH * SS * QEXT, (long)SS * QEXT,
               NHH, BB * NHH, 1.f, 0, 0, 2);
    // 7. scores = scale * qext @ ckv^T (B = combined buffer, offset 1536, ld 2176)
    launch_mma(qext_s, qlckv_s + QLORA_, 0, sc_s,
               SS, SS, QEXT, QEXT, NCOMB, SS, SS,
               (long)NHH * SS * QEXT, (long)SS * QEXT,
               (long)SS * NCOMB, 0,
               (long)NHH * SS * SS, (long)SS * SS,
               NHH, BB * NHH, scale, 1, 0, 2);
    // 8. softmax in place
    softmax_kernel<<<BB * NHH * SS, 256>>>(sc_s);
    // 9. out1 = probs @ ckvT, causal K-limit
    launch_mma(sc_s, ckvT_s, 0, out1_s,
               SS, KVLORA_, SS, SS, SS, KVLORA_, KVLORA_,
               (long)NHH * SS * SS, (long)SS * SS,
               (long)KVLORA_ * SS, 0,
               (long)NHH * SS * KVLORA_, (long)SS * KVLORA_,
               NHH, BB * NHH, 1.f, 0, 1, 2);
    // 10. out2 = out1 @ out_absorb^T
    launch_mma(out1_s, wkvup_s + (long)NOPE_ * KVLORA_, 0, out2_s,
               SS, VD_, KVLORA_, KVLORA_, KVLORA_, NHH * VD_, NHH * VD_,
               (long)NHH * SS * KVLORA_, (long)SS * KVLORA_,
               0, (long)256 * KVLORA_,
               (long)SS * NHH * VD_, (long)VD_,
               NHH, BB * NHH, 1.f, 0, 0, 2);
    // 11. final = out2 @ Wo^T [4096,2048] fp32 out
    launch_mma(out2_s, wo_s, out, 0,
               M, HDIM, NHH * VD_, NHH * VD_, NHH * VD_, HDIM, HDIM,
               0,0,0,0,0,0, 1, 1, 1.f, 0, 0, 0);
}

// round 15
// speedup vs baseline: 7.9524x; 1.0336x over previous
#include <cuda_runtime.h>
#include <cuda_fp16.h>
#include <math.h>
#include <stdint.h>

typedef unsigned short U16;

// ---------------- problem constants ----------------
#define NHH   16
#define NOPE_ 128
#define ROPED 64
#define VD_   128
#define QLORA_ 1536
#define KVLORA_ 512
#define HDIM  2048
#define BB    2
#define SS    2048
#define QEXT  576
#define QHD   (NOPE_ + ROPED)  // 192
#define NCOMB 2176             // 1536 (ql) + 640 (ckv padded)
#define NVALID 2112            // 1536 + 576

// ---------------- scratch (all fp16) ----------------
__device__ U16 g_hs_s [(long)BB*SS*HDIM];
__device__ U16 g_wcomb_s[(long)NCOMB*HDIM];
__device__ U16 g_wqu_s[(long)NHH*QHD*QLORA_];
__device__ U16 g_wo_s [(long)HDIM*HDIM];
__device__ U16 g_wkvup_s[(long)NHH*256*KVLORA_];
__device__ U16 g_wabsT_s[(long)NHH*KVLORA_*NOPE_];
__device__ U16 g_qlckv_s[(long)BB*SS*NCOMB];
__device__ U16 g_ql_s [(long)BB*SS*QLORA_];
__device__ U16 g_q_s  [(long)BB*SS*NHH*QHD];
__device__ U16 g_ckvT_s[(long)BB*KVLORA_*SS];
__device__ U16 g_qext_s[(long)BB*NHH*SS*QEXT];
__device__ U16 g_sc_s  [(long)BB*NHH*SS*SS];
__device__ U16 g_out1_s[(long)BB*NHH*SS*KVLORA_];
__device__ U16 g_out2_s[(long)BB*SS*NHH*VD_];

// ================= helpers =================
__device__ __forceinline__ uint32_t smem_u32(const void* p) {
    uint32_t a;
    asm("{ .reg .u64 t; cvta.to.shared.u64 t, %1; cvt.u32.u64 %0, t; }" : "=r"(a) : "l"(p));
    return a;
}
__device__ __forceinline__ void cp16(uint32_t dst, const void* src) {
    asm volatile("cp.async.cg.shared.global [%0], [%1], 16;" :: "r"(dst), "l"(src));
}
#define CP_COMMIT() asm volatile("cp.async.commit_group;" ::: "memory")
#define CP_WAIT1()  asm volatile("cp.async.wait_group 1;" ::: "memory")

__device__ __forceinline__ void ldmx4(uint32_t* r, uint32_t addr) {
    asm volatile("ldmatrix.sync.aligned.m8n8.x4.shared.b16 {%0,%1,%2,%3}, [%4];"
                 : "=r"(r[0]), "=r"(r[1]), "=r"(r[2]), "=r"(r[3]) : "r"(addr));
}
__device__ __forceinline__ void mma16816(float* d, const uint32_t* a, const uint32_t* b) {
    asm volatile("mma.sync.aligned.m16n8k16.row.col.f32.f16.f16.f32 "
                 "{%0,%1,%2,%3}, {%4,%5,%6,%7}, {%8,%9}, {%0,%1,%2,%3};"
                 : "+f"(d[0]), "+f"(d[1]), "+f"(d[2]), "+f"(d[3])
                 : "r"(a[0]), "r"(a[1]), "r"(a[2]), "r"(a[3]), "r"(b[0]), "r"(b[1]));
}
__device__ __forceinline__ U16 tohalf(float v) {
    return __half_as_ushort(__float2half_rn(v));
}
__device__ __forceinline__ float fromhalf(U16 v) {
    return __half2float(__ushort_as_half(v));
}

// ================= fp16 warp-MMA GEMM (single x single) =================
#define ROWB 144
#define TILEB (128 * ROWB)
#define SGB   (2 * TILEB)
#define MSMEM (3 * SGB)

extern __shared__ char dsmem[];

__global__ void __launch_bounds__(256, 2)
mma_gemm(const U16* __restrict__ A, const U16* __restrict__ B,
         float* __restrict__ C, U16* __restrict__ Co,
         int K, int lda, int ldb, int ldc, int ncols,
         long sAb, long sAhh, long sBb, long sBhh, long sCb, long sChh,
         int zh, float alpha, int causalSkip, int causalK, int outMode)
{
    int z = blockIdx.z;
    long ao = (long)(z / zh) * sAb + (long)(z % zh) * sAhh;
    long bo = (long)(z / zh) * sBb + (long)(z % zh) * sBhh;
    long co = (long)(z / zh) * sCb + (long)(z % zh) * sChh;
    int by = blockIdx.y, bx = blockIdx.x;
    if (causalSkip && bx * 128 > by * 128 + 127) return;
    int Klim = causalK ? min(K, by * 128 + 128) : K;
    int nCh = Klim >> 6;

    int tid = threadIdx.x;
    int lane = tid & 31, wid = tid >> 5;
    int wm = wid & 1, wn = wid >> 1;

    uint32_t sb = smem_u32(dsmem);

    const U16* gA = A + ao + (long)(by * 128) * lda;
    const U16* gB = B + bo + (long)(bx * 128) * ldb;

    uint32_t aoff[4], boff[2];
    {
        int ar = wm * 64 + (lane & 15);
        int ak = (lane >> 4) << 3;
        #pragma unroll
        for (int mt = 0; mt < 4; mt++)
            aoff[mt] = (uint32_t)((ar + mt * 16) * ROWB + (ak << 1));
        int br = wn * 32 + (lane & 7) + ((lane & 16) ? 8 : 0);
        int bk = (lane & 8) ? 8 : 0;
        #pragma unroll
        for (int np = 0; np < 2; np++)
            boff[np] = (uint32_t)((br + np * 16) * ROWB + (bk << 1));
    }

    float acc[4][4][4];
    #pragma unroll
    for (int mt = 0; mt < 4; mt++)
        #pragma unroll
        for (int nt = 0; nt < 4; nt++)
            #pragma unroll
            for (int r = 0; r < 4; r++) acc[mt][nt][r] = 0.f;

    auto issue = [&](uint32_t sbase, int k0) {
        #pragma unroll
        for (int q = 0; q < 4; q++) {
            int idx = (q << 8) + tid;
            int row = idx >> 3;
            int e0  = (idx & 7) << 3;
            uint32_t d = sbase + (uint32_t)(row * ROWB + (e0 << 1));
            cp16(d,         gA + (long)row * lda + k0 + e0);
            cp16(d + TILEB, gB + (long)row * ldb + k0 + e0);
        }
    };

    issue(sb, 0);
    CP_COMMIT();
    if (nCh > 1) issue(sb + SGB, 64);
    CP_COMMIT();

    int sc = 0;
    for (int c = 0; c < nCh; c++) {
        CP_WAIT1();
        __syncthreads();
        if (c + 2 < nCh) {
            int sn = sc + 2; if (sn >= 3) sn -= 3;
            issue(sb + sn * SGB, (c + 2) << 6);
        }
        CP_COMMIT();

        uint32_t sA_ = sb + sc * SGB;
        uint32_t sB_ = sA_ + TILEB;

        #pragma unroll
        for (int kh = 0; kh < 4; kh++) {
            uint32_t koffs = (uint32_t)(kh * 32);
            uint32_t ah[4][4], bh[2][4];
            #pragma unroll
            for (int mt = 0; mt < 4; mt++)
                ldmx4(ah[mt], sA_ + aoff[mt] + koffs);
            #pragma unroll
            for (int np = 0; np < 2; np++)
                ldmx4(bh[np], sB_ + boff[np] + koffs);
            #pragma unroll
            for (int mt = 0; mt < 4; mt++)
                #pragma unroll
                for (int nt = 0; nt < 4; nt++)
                    mma16816(acc[mt][nt], ah[mt], &bh[nt >> 1][(nt & 1) << 1]);
        }
        if (++sc == 3) sc = 0;
    }

    #pragma unroll
    for (int mt = 0; mt < 4; mt++) {
        int r0 = by * 128 + wm * 64 + mt * 16 + (lane >> 2);
        #pragma unroll
        for (int nt = 0; nt < 4; nt++) {
            int c0 = bx * 128 + wn * 32 + nt * 8 + ((lane & 3) << 1);
            if (c0 >= ncols) continue;
            float v00 = alpha * acc[mt][nt][0], v01 = alpha * acc[mt][nt][1];
            float v10 = alpha * acc[mt][nt][2], v11 = alpha * acc[mt][nt][3];
            if (outMode == 0) {
                *(float2*)(C + co + (long)r0 * ldc + c0) = make_float2(v00, v01);
                *(float2*)(C + co + (long)(r0 + 8) * ldc + c0) = make_float2(v10, v11);
            } else {
                *(uint32_t*)(Co + co + (long)r0 * ldc + c0) =
                    (uint32_t)tohalf(v00) | ((uint32_t)tohalf(v01) << 16);
                *(uint32_t*)(Co + co + (long)(r0 + 8) * ldc + c0) =
                    (uint32_t)tohalf(v10) | ((uint32_t)tohalf(v11) << 16);
            }
        }
    }
}

// ---------------- fused multi-tensor fp32 -> fp16 convert (table by value) ----------------
#define NSEG 6
struct SegTab {
    const float* src[NSEG];
    U16* dst[NSEG];
    long end[NSEG];
};

__global__ void convert_all_kernel(SegTab t, long total4)
{
    long i4 = (long)blockIdx.x * 256 + threadIdx.x;
    if (i4 >= total4) return;
    int s = 0;
    #pragma unroll
    for (int k = 0; k < NSEG - 1; k++) s += (i4 >= t.end[k]);
    long base4 = s ? t.end[s - 1] : 0;
    long off = (i4 - base4) * 4;
    float4 v = *(const float4*)(t.src[s] + off);
    uint2 ov;
    ov.x = (uint32_t)tohalf(v.x) | ((uint32_t)tohalf(v.y) << 16);
    ov.y = (uint32_t)tohalf(v.z) | ((uint32_t)tohalf(v.w) << 16);
    *(uint2*)(t.dst[s] + off) = ov;
}

// ---------------- RMSNorm (vectorized: 3 x uint32 per thread) ----------------
__global__ void rmsnorm_kernel(const U16* __restrict__ qlckv, const float* __restrict__ w,
                               U16* __restrict__ os)
{
    long ib = (long)blockIdx.x * NCOMB;
    long ob = (long)blockIdx.x * QLORA_;
    int tid = threadIdx.x;
    int lane = tid & 31, wid = tid >> 5;
    float v[6];
    #pragma unroll
    for (int j = 0; j < 3; j++) {
        uint32_t p = *(const uint32_t*)(qlckv + ib + j * 512 + tid * 2);
        v[2 * j]     = fromhalf((U16)(p & 0xffff));
        v[2 * j + 1] = fromhalf((U16)(p >> 16));
    }
    float s = v[0]*v[0] + v[1]*v[1] + v[2]*v[2] + v[3]*v[3] + v[4]*v[4] + v[5]*v[5];
    #pragma unroll
    for (int o = 16; o > 0; o >>= 1) s += __shfl_xor_sync(0xffffffffu, s, o);
    __shared__ float wred[8];
    if (lane == 0) wred[wid] = s;
    __syncthreads();
    s = wred[lane & 7];
    #pragma unroll
    for (int o = 4; o > 0; o >>= 1) s += __shfl_xor_sync(0xffffffffu, s, o);
    s = __shfl_sync(0xffffffffu, s, 0);
    float scale = rsqrtf(s / (float)QLORA_ + 1e-6f);
    #pragma unroll
    for (int j = 0; j < 3; j++) {
        int c = j * 512 + tid * 2;
        U16 h0 = tohalf(w[c] * (v[2 * j] * scale));
        U16 h1 = tohalf(w[c + 1] * (v[2 * j + 1] * scale));
        *(uint32_t*)(os + ob + c) = (uint32_t)h0 | ((uint32_t)h1 << 16);
    }
}

// ---------------- RoPE (fp32 sincos; double-exact inv_freq table) ----------------
__device__ __forceinline__ void build_invfreq(float* inv)
{
    if (threadIdx.x < 32)
        inv[threadIdx.x] = (float)exp(-((double)(2 * threadIdx.x) / 64.0) * 13.815510557964274);
    __syncthreads();
}

__global__ void rope_q_kernel(const U16* __restrict__ qs,
                              const int* __restrict__ pos, U16* __restrict__ es)
{
    __shared__ float invf[32];
    build_invfreq(invf);
    int idx = blockIdx.x * blockDim.x + threadIdx.x;
    if (idx >= BB * SS * NHH) return;
    int h = idx % NHH;
    int bs = idx / NHH;
    int b = bs / SS, s_idx = bs % SS;
    float p = (float)pos[bs];
    long xb = ((long)bs * NHH + h) * QHD + NOPE_;
    long ob = ((long)(b * NHH + h) * SS + s_idx) * QEXT + KVLORA_;
    #pragma unroll 8
    for (int i = 0; i < 32; i++) {
        float ang = p * invf[i];
        float sn, cs;
        sincosf(ang, &sn, &cs);
        float x0 = fromhalf(qs[xb + 2 * i]);
        float x1 = fromhalf(qs[xb + 2 * i + 1]);
        es[ob + i]      = tohalf(x0 * cs - x1 * sn);
        es[ob + 32 + i] = tohalf(x1 * cs + x0 * sn);
    }
}

__global__ void rope_k_kernel(U16* __restrict__ qlckv, const int* __restrict__ pos)
{
    __shared__ float invf[32];
    build_invfreq(invf);
    int bs = blockIdx.x * blockDim.x + threadIdx.x;
    if (bs >= BB * SS) return;
    float p = (float)pos[bs];
    U16* x = qlckv + (long)bs * NCOMB + QLORA_ + KVLORA_;
    U16 tmp[64];
    #pragma unroll 8
    for (int i = 0; i < 32; i++) {
        float ang = p * invf[i];
        float sn, cs;
        sincosf(ang, &sn, &cs);
        float x0 = fromhalf(x[2 * i]);
        float x1 = fromhalf(x[2 * i + 1]);
        tmp[i]      = tohalf(x0 * cs - x1 * sn);
        tmp[32 + i] = tohalf(x1 * cs + x0 * sn);
    }
    for (int j = 0; j < 64; j++) x[j] = tmp[j];
}

// ---------------- transposes ----------------
__global__ void transpose_wabs_kernel(const float* __restrict__ Wkv_up, U16* __restrict__ os)
{
    int idx = blockIdx.x * blockDim.x + threadIdx.x;
    if (idx >= NHH * KVLORA_ * NOPE_) return;
    int n = idx % NOPE_;
    int r = idx / NOPE_;
    int c = r % KVLORA_;
    int h = r / KVLORA_;
    os[idx] = tohalf(Wkv_up[((long)h * 256 + n) * KVLORA_ + c]);
}

__global__ void transpose_ckv_kernel(const U16* __restrict__ qlckv, U16* __restrict__ os)
{
    __shared__ U16 t[32][33];
    int b = blockIdx.z;
    int s0 = blockIdx.x * 32, c0 = blockIdx.y * 32;
    int x = threadIdx.x, y = threadIdx.y;
    for (int i = y; i < 32; i += 8)
        t[i][x] = qlckv[((long)b * SS + s0 + i) * NCOMB + QLORA_ + c0 + x];
    __syncthreads();
    for (int i = y; i < 32; i += 8)
        os[((long)b * KVLORA_ + c0 + i) * SS + s0 + x] = t[x][i];
}

// ---------------- causal softmax: row in registers (uint4 = 8 halves/thread) ----------------
__global__ void softmax_kernel(U16* __restrict__ sc)
{
    long row = blockIdx.x;
    int q = (int)(row % SS);
    long ob = row * (long)SS;
    int tid = threadIdx.x;
    int lane = tid & 31, wid = tid >> 5;
    int c0 = tid << 3;                       // this thread's 8 columns
    int blockEnd = ((q >> 7) + 1) << 7;
    __shared__ float wred[8];

    float v[8];
    bool active = (c0 < blockEnd);
    if (active) {
        uint4 pk = *(const uint4*)(sc + ob + c0);
        uint32_t w4[4] = {pk.x, pk.y, pk.z, pk.w};
        #pragma unroll
        for (int j = 0; j < 4; j++) {
            v[2 * j]     = fromhalf((U16)(w4[j] & 0xffff));
            v[2 * j + 1] = fromhalf((U16)(w4[j] >> 16));
        }
    }
    // masked max
    float mx = -1e30f;
    #pragma unroll
    for (int j = 0; j < 8; j++)
        if (active && c0 + j <= q) mx = fmaxf(mx, v[j]);
    #pragma unroll
    for (int o = 16; o > 0; o >>= 1) mx = fmaxf(mx, __shfl_xor_sync(0xffffffffu, mx, o));
    if (lane == 0) wred[wid] = mx;
    __syncthreads();
    mx = wred[lane & 7];
    #pragma unroll
    for (int o = 4; o > 0; o >>= 1) mx = fmaxf(mx, __shfl_xor_sync(0xffffffffu, mx, o));
    mx = __shfl_sync(0xffffffffu, mx, 0);

    // exp + masked sum
    float sum = 0.f;
    #pragma unroll
    for (int j = 0; j < 8; j++) {
        float e = (active && c0 + j <= q) ? __expf(v[j] - mx) : 0.f;
        v[j] = e;
        sum += e;
    }
    #pragma unroll
    for (int o = 16; o > 0; o >>= 1) sum += __shfl_xor_sync(0xffffffffu, sum, o);
    __syncthreads();
    if (lane == 0) wred[wid] = sum;
    __syncthreads();
    sum = wred[lane & 7];
    #pragma unroll
    for (int o = 4; o > 0; o >>= 1) sum += __shfl_xor_sync(0xffffffffu, sum, o);
    sum = __shfl_sync(0xffffffffu, sum, 0);
    float inv = 1.f / sum;

    if (active) {
        uint4 o4;
        uint32_t* w4 = (uint32_t*)&o4;
        #pragma unroll
        for (int j = 0; j < 4; j++)
            w4[j] = (uint32_t)tohalf(v[2 * j] * inv) |
                    ((uint32_t)tohalf(v[2 * j + 1] * inv) << 16);
        *(uint4*)(sc + ob + c0) = o4;
    }
}

// ---------------- host ----------------
static void launch_mma(const U16* A, const U16* B, float* C, U16* Co,
                       int M, int Npad, int K, int lda, int ldb, int ldc, int ncols,
                       long sAb, long sAh, long sBb, long sBh, long sCb, long sCh,
                       int zh, int zcount, float alpha, int cSkip, int cK, int outMode)
{
    cudaFuncSetAttribute(mma_gemm, cudaFuncAttributeMaxDynamicSharedMemorySize, MSMEM);
    dim3 grid(Npad / 128, M / 128, zcount);
    mma_gemm<<<grid, 256, MSMEM>>>(A, B, C, Co,
        K, lda, ldb, ldc, ncols, sAb, sAh, sBb, sBh, sCb, sCh, zh, alpha, cSkip, cK, outMode);
}

extern "C" void kernel_launch(void* const* d_in, const int* in_sizes, int n_in,
                              void* d_out, int out_size)
{
    const float* hs      = (const float*)d_in[0];
    const int*   pos     = (const int*)  d_in[1];
    const float* Wq_down = (const float*)d_in[3];
    const float* q_ln_w  = (const float*)d_in[4];
    const float* Wq_up   = (const float*)d_in[5];
    const float* Wkv_down= (const float*)d_in[6];
    const float* Wkv_up  = (const float*)d_in[7];
    const float* Wo      = (const float*)d_in[8];
    float* out = (float*)d_out;

    U16 *hs_s, *wcomb_s, *wqu_s, *wo_s, *wkvup_s, *wabsT_s;
    U16 *qlckv_s, *ql_s, *q_s, *ckvT_s, *qext_s, *sc_s, *out1_s, *out2_s;
    cudaGetSymbolAddress((void**)&hs_s, g_hs_s);
    cudaGetSymbolAddress((void**)&wcomb_s, g_wcomb_s);
    cudaGetSymbolAddress((void**)&wqu_s, g_wqu_s);
    cudaGetSymbolAddress((void**)&wo_s, g_wo_s);
    cudaGetSymbolAddress((void**)&wkvup_s, g_wkvup_s);
    cudaGetSymbolAddress((void**)&wabsT_s, g_wabsT_s);
    cudaGetSymbolAddress((void**)&qlckv_s, g_qlckv_s);
    cudaGetSymbolAddress((void**)&ql_s, g_ql_s);
    cudaGetSymbolAddress((void**)&q_s, g_q_s);
    cudaGetSymbolAddress((void**)&ckvT_s, g_ckvT_s);
    cudaGetSymbolAddress((void**)&qext_s, g_qext_s);
    cudaGetSymbolAddress((void**)&sc_s, g_sc_s);
    cudaGetSymbolAddress((void**)&out1_s, g_out1_s);
    cudaGetSymbolAddress((void**)&out2_s, g_out2_s);

    const int M = BB * SS;
    const float scale = 1.0f / sqrtf((float)QHD);

    // fused preprocessing converts
    {
        SegTab t;
        const long sz[NSEG] = {
            (long)BB * SS * HDIM, (long)QLORA_ * HDIM, (long)QEXT * HDIM,
            (long)NHH * QHD * QLORA_, (long)HDIM * HDIM, (long)NHH * 256 * KVLORA_ };
        const float* srcs[NSEG] = { hs, Wq_down, Wkv_down, Wq_up, Wo, Wkv_up };
        U16* dsts[NSEG] = { hs_s, wcomb_s, wcomb_s + (long)QLORA_ * HDIM, wqu_s, wo_s, wkvup_s };
        long acc = 0;
        for (int i = 0; i < NSEG; i++) {
            t.src[i] = srcs[i];
            t.dst[i] = dsts[i];
            acc += sz[i] / 4;
            t.end[i] = acc;
        }
        convert_all_kernel<<<(unsigned)((acc + 255) / 256), 256>>>(t, acc);
    }
    transpose_wabs_kernel<<<(NHH * KVLORA_ * NOPE_ + 255) / 256, 256>>>(Wkv_up, wabsT_s);

    // 1. [ql | ckv] = hs @ [Wq_down | Wkv_down]^T   [4096, 2176], fp16 out
    launch_mma(hs_s, wcomb_s, 0, qlckv_s,
               M, NCOMB, HDIM, HDIM, HDIM, NCOMB, NVALID,
               0,0,0,0,0,0, 1, 1, 1.f, 0, 0, 2);
    // 2. RMSNorm on ql part
    rmsnorm_kernel<<<M, 256>>>(qlckv_s, q_ln_w, ql_s);
    // 3. q = ql @ Wq_up^T [4096,3072] fp16 out
    launch_mma(ql_s, wqu_s, 0, q_s,
               M, NHH * QHD, QLORA_, QLORA_, QLORA_, NHH * QHD, NHH * QHD,
               0,0,0,0,0,0, 1, 1, 1.f, 0, 0, 2);
    // 4. RoPE k in place, then transpose ckv
    rope_k_kernel<<<(BB * SS + 255) / 256, 256>>>(qlckv_s, pos);
    {
        dim3 grid(SS / 32, KVLORA_ / 32, BB);
        transpose_ckv_kernel<<<grid, dim3(32, 8)>>>(qlckv_s, ckvT_s);
    }
    // 5. RoPE q -> qext cols 512:576
    rope_q_kernel<<<(BB * SS * NHH + 255) / 256, 256>>>(q_s, pos, qext_s);
    // 6. qext[:,0:512] = q @ q_absorb
    launch_mma(q_s, wabsT_s, 0, qext_s,
               SS, KVLORA_, NOPE_, NHH * QHD, NOPE_, QEXT, KVLORA_,
               (long)SS * NHH * QHD, (long)QHD,
               0, (long)KVLORA_ * NOPE_,
               (long)NHH * SS * QEXT, (long)SS * QEXT,
               NHH, BB * NHH, 1.f, 0, 0, 2);
    // 7. scores = scale * qext @ ckv^T (B in combined buffer, ld 2176)
    launch_mma(qext_s, qlckv_s + QLORA_, 0, sc_s,
               SS, SS, QEXT, QEXT, NCOMB, SS, SS,
               (long)NHH * SS * QEXT, (long)SS * QEXT,
               (long)SS * NCOMB, 0,
               (long)NHH * SS * SS, (long)SS * SS,
               NHH, BB * NHH, scale, 1, 0, 2);
    // 8. softmax in place (register-resident rows)
    softmax_kernel<<<BB * NHH * SS, 256>>>(sc_s);
    // 9. out1 = probs @ ckvT, causal K-limit
    launch_mma(sc_s, ckvT_s, 0, out1_s,
               SS, KVLORA_, SS, SS, SS, KVLORA_, KVLORA_,
               (long)NHH * SS * SS, (long)SS * SS,
               (long)KVLORA_ * SS, 0,
               (long)NHH * SS * KVLORA_, (long)SS * KVLORA_,
               NHH, BB * NHH, 1.f, 0, 1, 2);
    // 10. out2 = out1 @ out_absorb^T
    launch_mma(out1_s, wkvup_s + (long)NOPE_ * KVLORA_, 0, out2_s,
               SS, VD_, KVLORA_, KVLORA_, KVLORA_, NHH * VD_, NHH * VD_,
               (long)NHH * SS * KVLORA_, (long)SS * KVLORA_,
               0, (long)256 * KVLORA_,
               (long)SS * NHH * VD_, (long)VD_,
               NHH, BB * NHH, 1.f, 0, 0, 2);
    // 11. final = out2 @ Wo^T [4096,2048] fp32 out
    launch_mma(out2_s, wo_s, out, 0,
               M, HDIM, NHH * VD_, NHH * VD_, NHH * VD_, HDIM, HDIM,
               0,0,0,0,0,0, 1, 1, 1.f, 0, 0, 0);
}

// round 16
// speedup vs baseline: 7.9670x; 1.0018x over previous
#include <cuda_runtime.h>
#include <cuda_fp16.h>
#include <math.h>
#include <stdint.h>

typedef unsigned short U16;

// ---------------- problem constants ----------------
#define NHH   16
#define NOPE_ 128
#define ROPED 64
#define VD_   128
#define QLORA_ 1536
#define KVLORA_ 512
#define HDIM  2048
#define BB    2
#define SS    2048
#define QEXT  576
#define QHD   (NOPE_ + ROPED)  // 192
#define NCOMB 2176             // 1536 (ql) + 640 (ckv padded)
#define NVALID 2112            // 1536 + 576

// ---------------- scratch ----------------
__device__ U16 g_hs_s [(long)BB*SS*HDIM];
__device__ U16 g_wcomb_s[(long)NCOMB*HDIM];
__device__ U16 g_wqu_s[(long)NHH*QHD*QLORA_];              // pre-multiplied by q_ln_w
__device__ U16 g_wo_s [(long)HDIM*HDIM];
__device__ U16 g_wkvup_s[(long)NHH*256*KVLORA_];
__device__ U16 g_wabsT_s[(long)NHH*KVLORA_*NOPE_];
__device__ U16 g_qlckv_s[(long)BB*SS*NCOMB];
__device__ float g_rs[(long)BB*SS];                        // rmsnorm row scales
__device__ U16 g_q_s  [(long)BB*SS*NHH*QHD];
__device__ U16 g_ckvT_s[(long)BB*KVLORA_*SS];
__device__ U16 g_qext_s[(long)BB*NHH*SS*QEXT];
__device__ U16 g_sc_s  [(long)BB*NHH*SS*SS];
__device__ U16 g_out1_s[(long)BB*NHH*SS*KVLORA_];
__device__ U16 g_out2_s[(long)BB*SS*NHH*VD_];

// ================= helpers =================
__device__ __forceinline__ uint32_t smem_u32(const void* p) {
    uint32_t a;
    asm("{ .reg .u64 t; cvta.to.shared.u64 t, %1; cvt.u32.u64 %0, t; }" : "=r"(a) : "l"(p));
    return a;
}
__device__ __forceinline__ void cp16(uint32_t dst, const void* src) {
    asm volatile("cp.async.cg.shared.global [%0], [%1], 16;" :: "r"(dst), "l"(src));
}
#define CP_COMMIT() asm volatile("cp.async.commit_group;" ::: "memory")
#define CP_WAIT1()  asm volatile("cp.async.wait_group 1;" ::: "memory")

__device__ __forceinline__ void ldmx4(uint32_t* r, uint32_t addr) {
    asm volatile("ldmatrix.sync.aligned.m8n8.x4.shared.b16 {%0,%1,%2,%3}, [%4];"
                 : "=r"(r[0]), "=r"(r[1]), "=r"(r[2]), "=r"(r[3]) : "r"(addr));
}
__device__ __forceinline__ void mma16816(float* d, const uint32_t* a, const uint32_t* b) {
    asm volatile("mma.sync.aligned.m16n8k16.row.col.f32.f16.f16.f32 "
                 "{%0,%1,%2,%3}, {%4,%5,%6,%7}, {%8,%9}, {%0,%1,%2,%3};"
                 : "+f"(d[0]), "+f"(d[1]), "+f"(d[2]), "+f"(d[3])
                 : "r"(a[0]), "r"(a[1]), "r"(a[2]), "r"(a[3]), "r"(b[0]), "r"(b[1]));
}
__device__ __forceinline__ U16 tohalf(float v) {
    return __half_as_ushort(__float2half_rn(v));
}
__device__ __forceinline__ float fromhalf(U16 v) {
    return __half2float(__ushort_as_half(v));
}

// ================= fp16 warp-MMA GEMM (single x single) =================
#define ROWB 144
#define TILEB (128 * ROWB)
#define SGB   (2 * TILEB)
#define MSMEM (3 * SGB)

extern __shared__ char dsmem[];

__global__ void __launch_bounds__(256, 2)
mma_gemm(const U16* __restrict__ A, const U16* __restrict__ B,
         float* __restrict__ C, U16* __restrict__ Co,
         const float* __restrict__ rowScale,
         int K, int lda, int ldb, int ldc, int ncols,
         long sAb, long sAhh, long sBb, long sBhh, long sCb, long sChh,
         int zh, float alpha, int causalSkip, int causalK, int outMode)
{
    int z = blockIdx.z;
    long ao = (long)(z / zh) * sAb + (long)(z % zh) * sAhh;
    long bo = (long)(z / zh) * sBb + (long)(z % zh) * sBhh;
    long co = (long)(z / zh) * sCb + (long)(z % zh) * sChh;
    int by = blockIdx.y, bx = blockIdx.x;
    if (causalSkip && bx * 128 > by * 128 + 127) return;
    int Klim = causalK ? min(K, by * 128 + 128) : K;
    int nCh = Klim >> 6;

    int tid = threadIdx.x;
    int lane = tid & 31, wid = tid >> 5;
    int wm = wid & 1, wn = wid >> 1;

    uint32_t sb = smem_u32(dsmem);

    const U16* gA = A + ao + (long)(by * 128) * lda;
    const U16* gB = B + bo + (long)(bx * 128) * ldb;

    uint32_t aoff[4], boff[2];
    {
        int ar = wm * 64 + (lane & 15);
        int ak = (lane >> 4) << 3;
        #pragma unroll
        for (int mt = 0; mt < 4; mt++)
            aoff[mt] = (uint32_t)((ar + mt * 16) * ROWB + (ak << 1));
        int br = wn * 32 + (lane & 7) + ((lane & 16) ? 8 : 0);
        int bk = (lane & 8) ? 8 : 0;
        #pragma unroll
        for (int np = 0; np < 2; np++)
            boff[np] = (uint32_t)((br + np * 16) * ROWB + (bk << 1));
    }

    float acc[4][4][4];
    #pragma unroll
    for (int mt = 0; mt < 4; mt++)
        #pragma unroll
        for (int nt = 0; nt < 4; nt++)
            #pragma unroll
            for (int r = 0; r < 4; r++) acc[mt][nt][r] = 0.f;

    auto issue = [&](uint32_t sbase, int k0) {
        #pragma unroll
        for (int q = 0; q < 4; q++) {
            int idx = (q << 8) + tid;
            int row = idx >> 3;
            int e0  = (idx & 7) << 3;
            uint32_t d = sbase + (uint32_t)(row * ROWB + (e0 << 1));
            cp16(d,         gA + (long)row * lda + k0 + e0);
            cp16(d + TILEB, gB + (long)row * ldb + k0 + e0);
        }
    };

    issue(sb, 0);
    CP_COMMIT();
    if (nCh > 1) issue(sb + SGB, 64);
    CP_COMMIT();

    int sc = 0;
    for (int c = 0; c < nCh; c++) {
        CP_WAIT1();
        __syncthreads();
        if (c + 2 < nCh) {
            int sn = sc + 2; if (sn >= 3) sn -= 3;
            issue(sb + sn * SGB, (c + 2) << 6);
        }
        CP_COMMIT();

        uint32_t sA_ = sb + sc * SGB;
        uint32_t sB_ = sA_ + TILEB;

        #pragma unroll
        for (int kh = 0; kh < 4; kh++) {
            uint32_t koffs = (uint32_t)(kh * 32);
            uint32_t ah[4][4], bh[2][4];
            #pragma unroll
            for (int mt = 0; mt < 4; mt++)
                ldmx4(ah[mt], sA_ + aoff[mt] + koffs);
            #pragma unroll
            for (int np = 0; np < 2; np++)
                ldmx4(bh[np], sB_ + boff[np] + koffs);
            #pragma unroll
            for (int mt = 0; mt < 4; mt++)
                #pragma unroll
                for (int nt = 0; nt < 4; nt++)
                    mma16816(acc[mt][nt], ah[mt], &bh[nt >> 1][(nt & 1) << 1]);
        }
        if (++sc == 3) sc = 0;
    }

    #pragma unroll
    for (int mt = 0; mt < 4; mt++) {
        int r0 = by * 128 + wm * 64 + mt * 16 + (lane >> 2);
        float s0 = alpha, s1 = alpha;
        if (rowScale) {
            s0 *= rowScale[r0];
            s1 *= rowScale[r0 + 8];
        }
        #pragma unroll
        for (int nt = 0; nt < 4; nt++) {
            int c0 = bx * 128 + wn * 32 + nt * 8 + ((lane & 3) << 1);
            if (c0 >= ncols) continue;
            float v00 = s0 * acc[mt][nt][0], v01 = s0 * acc[mt][nt][1];
            float v10 = s1 * acc[mt][nt][2], v11 = s1 * acc[mt][nt][3];
            if (outMode == 0) {
                *(float2*)(C + co + (long)r0 * ldc + c0) = make_float2(v00, v01);
                *(float2*)(C + co + (long)(r0 + 8) * ldc + c0) = make_float2(v10, v11);
            } else {
                *(uint32_t*)(Co + co + (long)r0 * ldc + c0) =
                    (uint32_t)tohalf(v00) | ((uint32_t)tohalf(v01) << 16);
                *(uint32_t*)(Co + co + (long)(r0 + 8) * ldc + c0) =
                    (uint32_t)tohalf(v10) | ((uint32_t)tohalf(v11) << 16);
            }
        }
    }
}

// ---------------- fused multi-tensor fp32 -> fp16 convert (table by value) ----------------
// Segment wseg (Wq_up) gets columns multiplied by q_ln_w (rmsnorm weight fold).
#define NSEG 6
struct SegTab {
    const float* src[NSEG];
    U16* dst[NSEG];
    long end[NSEG];
};

__global__ void convert_all_kernel(SegTab t, const float* __restrict__ w, int wseg, long total4)
{
    long i4 = (long)blockIdx.x * 256 + threadIdx.x;
    if (i4 >= total4) return;
    int s = 0;
    #pragma unroll
    for (int k = 0; k < NSEG - 1; k++) s += (i4 >= t.end[k]);
    long base4 = s ? t.end[s - 1] : 0;
    long off = (i4 - base4) * 4;
    float4 v = *(const float4*)(t.src[s] + off);
    if (s == wseg) {
        int k = (int)(off % QLORA_);
        v.x *= w[k]; v.y *= w[k + 1]; v.z *= w[k + 2]; v.w *= w[k + 3];
    }
    uint2 ov;
    ov.x = (uint32_t)tohalf(v.x) | ((uint32_t)tohalf(v.y) << 16);
    ov.y = (uint32_t)tohalf(v.z) | ((uint32_t)tohalf(v.w) << 16);
    *(uint2*)(t.dst[s] + off) = ov;
}

// ---------------- RMSNorm row scales only (128 threads/row, 6 u32 each) ----------------
__global__ void rowscale_kernel(const U16* __restrict__ qlckv, float* __restrict__ rs)
{
    long ib = (long)blockIdx.x * NCOMB;
    int tid = threadIdx.x;
    int lane = tid & 31, wid = tid >> 5;
    float s = 0.f;
    #pragma unroll
    for (int j = 0; j < 6; j++) {
        uint32_t p = *(const uint32_t*)(qlckv + ib + j * 256 + tid * 2);
        float a = fromhalf((U16)(p & 0xffff));
        float b = fromhalf((U16)(p >> 16));
        s += a * a + b * b;
    }
    #pragma unroll
    for (int o = 16; o > 0; o >>= 1) s += __shfl_xor_sync(0xffffffffu, s, o);
    __shared__ float wr[4];
    if (lane == 0) wr[wid] = s;
    __syncthreads();
    if (tid == 0) {
        float tot = wr[0] + wr[1] + wr[2] + wr[3];
        rs[blockIdx.x] = rsqrtf(tot / (float)QLORA_ + 1e-6f);
    }
}

// ---------------- RoPE (fp32 sincos; double-exact inv_freq table) ----------------
__device__ __forceinline__ void build_invfreq(float* inv)
{
    if (threadIdx.x < 32)
        inv[threadIdx.x] = (float)exp(-((double)(2 * threadIdx.x) / 64.0) * 13.815510557964274);
    __syncthreads();
}

__global__ void rope_q_kernel(const U16* __restrict__ qs,
                              const int* __restrict__ pos, U16* __restrict__ es)
{
    __shared__ float invf[32];
    build_invfreq(invf);
    int idx = blockIdx.x * blockDim.x + threadIdx.x;
    if (idx >= BB * SS * NHH) return;
    int h = idx % NHH;
    int bs = idx / NHH;
    int b = bs / SS, s_idx = bs % SS;
    float p = (float)pos[bs];
    long xb = ((long)bs * NHH + h) * QHD + NOPE_;
    long ob = ((long)(b * NHH + h) * SS + s_idx) * QEXT + KVLORA_;
    #pragma unroll 8
    for (int i = 0; i < 32; i++) {
        float ang = p * invf[i];
        float sn, cs;
        sincosf(ang, &sn, &cs);
        float x0 = fromhalf(qs[xb + 2 * i]);
        float x1 = fromhalf(qs[xb + 2 * i + 1]);
        es[ob + i]      = tohalf(x0 * cs - x1 * sn);
        es[ob + 32 + i] = tohalf(x1 * cs + x0 * sn);
    }
}

__global__ void rope_k_kernel(U16* __restrict__ qlckv, const int* __restrict__ pos)
{
    __shared__ float invf[32];
    build_invfreq(invf);
    int bs = blockIdx.x * blockDim.x + threadIdx.x;
    if (bs >= BB * SS) return;
    float p = (float)pos[bs];
    U16* x = qlckv + (long)bs * NCOMB + QLORA_ + KVLORA_;
    U16 tmp[64];
    #pragma unroll 8
    for (int i = 0; i < 32; i++) {
        float ang = p * invf[i];
        float sn, cs;
        sincosf(ang, &sn, &cs);
        float x0 = fromhalf(x[2 * i]);
        float x1 = fromhalf(x[2 * i + 1]);
        tmp[i]      = tohalf(x0 * cs - x1 * sn);
        tmp[32 + i] = tohalf(x1 * cs + x0 * sn);
    }
    for (int j = 0; j < 64; j++) x[j] = tmp[j];
}

// ---------------- transposes ----------------
__global__ void transpose_wabs_kernel(const float* __restrict__ Wkv_up, U16* __restrict__ os)
{
    int idx = blockIdx.x * blockDim.x + threadIdx.x;
    if (idx >= NHH * KVLORA_ * NOPE_) return;
    int n = idx % NOPE_;
    int r = idx / NOPE_;
    int c = r % KVLORA_;
    int h = r / KVLORA_;
    os[idx] = tohalf(Wkv_up[((long)h * 256 + n) * KVLORA_ + c]);
}

__global__ void transpose_ckv_kernel(const U16* __restrict__ qlckv, U16* __restrict__ os)
{
    __shared__ U16 t[32][33];
    int b = blockIdx.z;
    int s0 = blockIdx.x * 32, c0 = blockIdx.y * 32;
    int x = threadIdx.x, y = threadIdx.y;
    for (int i = y; i < 32; i += 8)
        t[i][x] = qlckv[((long)b * SS + s0 + i) * NCOMB + QLORA_ + c0 + x];
    __syncthreads();
    for (int i = y; i < 32; i += 8)
        os[((long)b * KVLORA_ + c0 + i) * SS + s0 + x] = t[x][i];
}

// ---------------- causal softmax: row in registers (uint4 = 8 halves/thread) ----------------
__global__ void softmax_kernel(U16* __restrict__ sc)
{
    long row = blockIdx.x;
    int q = (int)(row % SS);
    long ob = row * (long)SS;
    int tid = threadIdx.x;
    int lane = tid & 31, wid = tid >> 5;
    int c0 = tid << 3;
    int blockEnd = ((q >> 7) + 1) << 7;
    __shared__ float wred[8];

    float v[8];
    bool active = (c0 < blockEnd);
    if (active) {
        uint4 pk = *(const uint4*)(sc + ob + c0);
        uint32_t w4[4] = {pk.x, pk.y, pk.z, pk.w};
        #pragma unroll
        for (int j = 0; j < 4; j++) {
            v[2 * j]     = fromhalf((U16)(w4[j] & 0xffff));
            v[2 * j + 1] = fromhalf((U16)(w4[j] >> 16));
        }
    }
    float mx = -1e30f;
    #pragma unroll
    for (int j = 0; j < 8; j++)
        if (active && c0 + j <= q) mx = fmaxf(mx, v[j]);
    #pragma unroll
    for (int o = 16; o > 0; o >>= 1) mx = fmaxf(mx, __shfl_xor_sync(0xffffffffu, mx, o));
    if (lane == 0) wred[wid] = mx;
    __syncthreads();
    mx = wred[lane & 7];
    #pragma unroll
    for (int o = 4; o > 0; o >>= 1) mx = fmaxf(mx, __shfl_xor_sync(0xffffffffu, mx, o));
    mx = __shfl_sync(0xffffffffu, mx, 0);

    float sum = 0.f;
    #pragma unroll
    for (int j = 0; j < 8; j++) {
        float e = (active && c0 + j <= q) ? __expf(v[j] - mx) : 0.f;
        v[j] = e;
        sum += e;
    }
    #pragma unroll
    for (int o = 16; o > 0; o >>= 1) sum += __shfl_xor_sync(0xffffffffu, sum, o);
    __syncthreads();
    if (lane == 0) wred[wid] = sum;
    __syncthreads();
    sum = wred[lane & 7];
    #pragma unroll
    for (int o = 4; o > 0; o >>= 1) sum += __shfl_xor_sync(0xffffffffu, sum, o);
    sum = __shfl_sync(0xffffffffu, sum, 0);
    float inv = 1.f / sum;

    if (active) {
        uint4 o4;
        uint32_t* w4 = (uint32_t*)&o4;
        #pragma unroll
        for (int j = 0; j < 4; j++)
            w4[j] = (uint32_t)tohalf(v[2 * j] * inv) |
                    ((uint32_t)tohalf(v[2 * j + 1] * inv) << 16);
        *(uint4*)(sc + ob + c0) = o4;
    }
}

// ---------------- host ----------------
static void launch_mma(const U16* A, const U16* B, float* C, U16* Co, const float* rs,
                       int M, int Npad, int K, int lda, int ldb, int ldc, int ncols,
                       long sAb, long sAh, long sBb, long sBh, long sCb, long sCh,
                       int zh, int zcount, float alpha, int cSkip, int cK, int outMode)
{
    cudaFuncSetAttribute(mma_gemm, cudaFuncAttributeMaxDynamicSharedMemorySize, MSMEM);
    dim3 grid(Npad / 128, M / 128, zcount);
    mma_gemm<<<grid, 256, MSMEM>>>(A, B, C, Co, rs,
        K, lda, ldb, ldc, ncols, sAb, sAh, sBb, sBh, sCb, sCh, zh, alpha, cSkip, cK, outMode);
}

extern "C" void kernel_launch(void* const* d_in, const int* in_sizes, int n_in,
                              void* d_out, int out_size)
{
    const float* hs      = (const float*)d_in[0];
    const int*   pos     = (const int*)  d_in[1];
    const float* Wq_down = (const float*)d_in[3];
    const float* q_ln_w  = (const float*)d_in[4];
    const float* Wq_up   = (const float*)d_in[5];
    const float* Wkv_down= (const float*)d_in[6];
    const float* Wkv_up  = (const float*)d_in[7];
    const float* Wo      = (const float*)d_in[8];
    float* out = (float*)d_out;

    U16 *hs_s, *wcomb_s, *wqu_s, *wo_s, *wkvup_s, *wabsT_s;
    U16 *qlckv_s, *q_s, *ckvT_s, *qext_s, *sc_s, *out1_s, *out2_s;
    float* rs;
    cudaGetSymbolAddress((void**)&hs_s, g_hs_s);
    cudaGetSymbolAddress((void**)&wcomb_s, g_wcomb_s);
    cudaGetSymbolAddress((void**)&wqu_s, g_wqu_s);
    cudaGetSymbolAddress((void**)&wo_s, g_wo_s);
    cudaGetSymbolAddress((void**)&wkvup_s, g_wkvup_s);
    cudaGetSymbolAddress((void**)&wabsT_s, g_wabsT_s);
    cudaGetSymbolAddress((void**)&qlckv_s, g_qlckv_s);
    cudaGetSymbolAddress((void**)&rs, g_rs);
    cudaGetSymbolAddress((void**)&q_s, g_q_s);
    cudaGetSymbolAddress((void**)&ckvT_s, g_ckvT_s);
    cudaGetSymbolAddress((void**)&qext_s, g_qext_s);
    cudaGetSymbolAddress((void**)&sc_s, g_sc_s);
    cudaGetSymbolAddress((void**)&out1_s, g_out1_s);
    cudaGetSymbolAddress((void**)&out2_s, g_out2_s);

    const int M = BB * SS;
    const float scale = 1.0f / sqrtf((float)QHD);

    // fused preprocessing converts (Wq_up gets q_ln_w folded in: segment 3)
    {
        SegTab t;
        const long sz[NSEG] = {
            (long)BB * SS * HDIM, (long)QLORA_ * HDIM, (long)QEXT * HDIM,
            (long)NHH * QHD * QLORA_, (long)HDIM * HDIM, (long)NHH * 256 * KVLORA_ };
        const float* srcs[NSEG] = { hs, Wq_down, Wkv_down, Wq_up, Wo, Wkv_up };
        U16* dsts[NSEG] = { hs_s, wcomb_s, wcomb_s + (long)QLORA_ * HDIM, wqu_s, wo_s, wkvup_s };
        long acc = 0;
        for (int i = 0; i < NSEG; i++) {
            t.src[i] = srcs[i];
            t.dst[i] = dsts[i];
            acc += sz[i] / 4;
            t.end[i] = acc;
        }
        convert_all_kernel<<<(unsigned)((acc + 255) / 256), 256>>>(t, q_ln_w, 3, acc);
    }
    transpose_wabs_kernel<<<(NHH * KVLORA_ * NOPE_ + 255) / 256, 256>>>(Wkv_up, wabsT_s);

    // 1. [ql | ckv] = hs @ [Wq_down | Wkv_down]^T   [4096, 2176], fp16 out
    launch_mma(hs_s, wcomb_s, 0, qlckv_s, 0,
               M, NCOMB, HDIM, HDIM, HDIM, NCOMB, NVALID,
               0,0,0,0,0,0, 1, 1, 1.f, 0, 0, 2);
    // 2. rmsnorm row scales only
    rowscale_kernel<<<M, 128>>>(qlckv_s, rs);
    // 3. q = rs * (qlraw @ (Wq_up*w)^T)  [4096,3072] fp16 out, A straight from combined buffer
    launch_mma(qlckv_s, wqu_s, 0, q_s, rs,
               M, NHH * QHD, QLORA_, NCOMB, QLORA_, NHH * QHD, NHH * QHD,
               0,0,0,0,0,0, 1, 1, 1.f, 0, 0, 2);
    // 4. RoPE k in place, then transpose ckv
    rope_k_kernel<<<(BB * SS + 255) / 256, 256>>>(qlckv_s, pos);
    {
        dim3 grid(SS / 32, KVLORA_ / 32, BB);
        transpose_ckv_kernel<<<grid, dim3(32, 8)>>>(qlckv_s, ckvT_s);
    }
    // 5. RoPE q -> qext cols 512:576
    rope_q_kernel<<<(BB * SS * NHH + 255) / 256, 256>>>(q_s, pos, qext_s);
    // 6. qext[:,0:512] = q @ q_absorb
    launch_mma(q_s, wabsT_s, 0, qext_s, 0,
               SS, KVLORA_, NOPE_, NHH * QHD, NOPE_, QEXT, KVLORA_,
               (long)SS * NHH * QHD, (long)QHD,
               0, (long)KVLORA_ * NOPE_,
               (long)NHH * SS * QEXT, (long)SS * QEXT,
               NHH, BB * NHH, 1.f, 0, 0, 2);
    // 7. scores = scale * qext @ ckv^T (B in combined buffer, ld 2176)
    launch_mma(qext_s, qlckv_s + QLORA_, 0, sc_s, 0,
               SS, SS, QEXT, QEXT, NCOMB, SS, SS,
               (long)NHH * SS * QEXT, (long)SS * QEXT,
               (long)SS * NCOMB, 0,
               (long)NHH * SS * SS, (long)SS * SS,
               NHH, BB * NHH, scale, 1, 0, 2);
    // 8. softmax in place
    softmax_kernel<<<BB * NHH * SS, 256>>>(sc_s);
    // 9. out1 = probs @ ckvT, causal K-limit
    launch_mma(sc_s, ckvT_s, 0, out1_s, 0,
               SS, KVLORA_, SS, SS, SS, KVLORA_, KVLORA_,
               (long)NHH * SS * SS, (long)SS * SS,
               (long)KVLORA_ * SS, 0,
               (long)NHH * SS * KVLORA_, (long)SS * KVLORA_,
               NHH, BB * NHH, 1.f, 0, 1, 2);
    // 10. out2 = out1 @ out_absorb^T
    launch_mma(out1_s, wkvup_s + (long)NOPE_ * KVLORA_, 0, out2_s, 0,
               SS, VD_, KVLORA_, KVLORA_, KVLORA_, NHH * VD_, NHH * VD_,
               (long)NHH * SS * KVLORA_, (long)SS * KVLORA_,
               0, (long)256 * KVLORA_,
               (long)SS * NHH * VD_, (long)VD_,
               NHH, BB * NHH, 1.f, 0, 0, 2);
    // 11. final = out2 @ Wo^T [4096,2048] fp32 out
    launch_mma(out2_s, wo_s, out, 0, 0,
               M, HDIM, NHH * VD_, NHH * VD_, NHH * VD_, HDIM, HDIM,
               0,0,0,0,0,0, 1, 1, 1.f, 0, 0, 0);
}